// round 4
// baseline (speedup 1.0000x reference)
#include <cuda_runtime.h>
#include <cstdint>

#define GAIN   1.6778523489932886f   /* 1/0.596 */
#define INV058 1.3130643285972254f   /* 1/sqrt(0.7^2+0.3^2) */
#define EPSN   1e-4f

typedef unsigned long long ull;

/* ---------------- static device scratch (no allocations allowed) -------- */
__device__ __align__(16) float g_wpool[15230976];
__device__ __align__(16) float g_pm[4];
__device__ __align__(16) float g_xn[33554432];
__device__ __align__(16) float g_bufA[67108864];
__device__ __align__(16) float g_bufB[67108864];
__device__ __align__(16) float g_h[33554432];
__device__ __align__(16) float g_pool[8388608];
__device__ __align__(16) float g_x[16777216];

/* weight pool offsets (floats), all 16B aligned */
#define O_C0W1 0
#define O_C0WD 8192
#define O_C0W2 10112
#define O_C0DN 18304
#define O_C1W1 26496
#define O_C1WD 59264
#define O_C1W2 63104
#define O_C1DN 95872
#define O_C2W1 128640
#define O_C2WD 259712
#define O_C2W2 267392
#define O_C2DN 398464
#define O_HG   529536
#define O_DW   4723840
#define O_GRU  4736128
#define O_OUT  13124736

__device__ __forceinline__ float sigmoidf_fast(float x) {
    return __fdividef(1.f, 1.f + __expf(-x));
}
__device__ __forceinline__ float mp_siluf(float x) {
    return x * sigmoidf_fast(x) * GAIN;
}

/* packed fp32x2 helpers */
__device__ __forceinline__ ull ffma2(ull a, ull b, ull c) {
    ull d;
    asm("fma.rn.f32x2 %0, %1, %2, %3;" : "=l"(d) : "l"(a), "l"(b), "l"(c));
    return d;
}
__device__ __forceinline__ ull dup2(float v) {
    ull r;
    asm("mov.b64 %0, {%1, %1};" : "=l"(r) : "f"(v));
    return r;
}
__device__ __forceinline__ float2 unpack2(ull v) {
    float2 f;
    asm("mov.b64 {%0, %1}, %2;" : "=f"(f.x), "=f"(f.y) : "l"(v));
    return f;
}

/* ---------------- fused weight normalization (segmented) ----------------- */
struct NormSeg { const float* src; float* dst; int rowlen; int row_end; };
struct NormDescs { NormSeg s[16]; };

__global__ void norm_rows_multi(NormDescs d) {
    int blk = blockIdx.x;
    int seg = 0, row_start = 0;
#pragma unroll
    for (int i = 0; i < 16; i++) {
        if (blk >= d.s[i].row_end) { seg = i + 1; row_start = d.s[i].row_end; }
    }
    int r = blk - row_start;
    int rowlen = d.s[seg].rowlen;
    const float* s = d.s[seg].src + (long long)r * rowlen;
    float* dst = d.s[seg].dst + (long long)r * rowlen;
    float acc = 0.f;
    for (int i = threadIdx.x; i < rowlen; i += blockDim.x) { float v = s[i]; acc = fmaf(v, v, acc); }
#pragma unroll
    for (int off = 16; off; off >>= 1) acc += __shfl_down_sync(0xffffffffu, acc, off);
    __shared__ float sm[8];
    int warp = threadIdx.x >> 5, lane = threadIdx.x & 31;
    if (lane == 0) sm[warp] = acc;
    __syncthreads();
    if (threadIdx.x == 0) {
        float t = 0.f;
        int nw = blockDim.x >> 5;
        for (int i = 0; i < nw; i++) t += sm[i];
        sm[0] = rsqrtf(t + 1e-8f);
    }
    __syncthreads();
    float iv = sm[0];
    for (int i = threadIdx.x; i < rowlen; i += blockDim.x) dst[i] = s[i] * iv;
}

/* ---------------- proj closed-form pixel norm --------------------------- */
__global__ void proj_moments(const float* __restrict__ pw, const float* __restrict__ pb,
                             float* __restrict__ pm) {
    if (threadIdx.x == 0) {
        float a = 0.f, b2 = 0.f, c2 = 0.f;
        for (int i = 0; i < 64; i++) {
            float w = pw[i], bb = pb[i];
            a = fmaf(w, w, a); b2 = fmaf(w, bb, b2); c2 = fmaf(bb, bb, c2);
        }
        pm[0] = a * (1.f / 64.f); pm[1] = b2 * (1.f / 64.f); pm[2] = c2 * (1.f / 64.f);
    }
}

__global__ void proj_pixelnorm(const float* __restrict__ audio, const float* __restrict__ pw,
                               const float* __restrict__ pb, const float* __restrict__ pm,
                               float* __restrict__ xn) {
    long long p = (long long)blockIdx.x * blockDim.x + threadIdx.x;
    if (p >= 524288LL) return;
    float A = audio[p];
    float ms = fmaf(A * A, pm[0], fmaf(2.f * A, pm[1], pm[2]));
    float iv = rsqrtf(ms + EPSN);
    long long b = p >> 18;
    long long rem = p & 262143LL;
    float* o = xn + b * 64LL * 262144LL + rem;
#pragma unroll
    for (int c = 0; c < 64; c++)
        o[(long long)c * 262144LL] = fmaf(A, pw[c], pb[c]) * iv;
}

/* ---------------- generic pixel norm (thread per position) -------------- */
__global__ void pixelnorm(const float* __restrict__ x, float* __restrict__ xn,
                          int C, long long P, long long BP) {
    long long p = (long long)blockIdx.x * blockDim.x + threadIdx.x;
    if (p >= BP) return;
    long long b = p / P, pp = p % P;
    const float* xi = x + b * (long long)C * P + pp;
    float s = 0.f;
#pragma unroll 8
    for (int c = 0; c < C; c++) { float v = xi[(long long)c * P]; s = fmaf(v, v, s); }
    float iv = rsqrtf(s / (float)C + EPSN);
    float* o = xn + b * (long long)C * P + pp;
#pragma unroll 8
    for (int c = 0; c < C; c++) o[(long long)c * P] = xi[(long long)c * P] * iv;
}

/* ---------------- tiled fp32x2 GEMM: Y[M,P] = W[M,K] @ X[K,P] ----------- */
/* M%64==0, K%16==0, P%64==0. grid = (P/64, M/64, B), 256 threads.         */
/* W tile stored duplicated as (w,w) pairs so A operands load as f32x2;    */
/* X tile's adjacent columns already form valid f32x2 pairs.               */
template <bool SILU_LOAD, bool MPADD>
__global__ void __launch_bounds__(256) gemm64(const float* __restrict__ W,
                                              const float* __restrict__ X,
                                              float* __restrict__ Y,
                                              const float* __restrict__ R,
                                              int M, int K, long long P) {
    __shared__ __align__(16) ull  WsD[16][66];   /* [kk][m] = (w,w) */
    __shared__ __align__(16) float Xs[16][68];
    const int tid = threadIdx.x;
    const long long p0 = (long long)blockIdx.x * 64;
    const int m0 = blockIdx.y * 64;
    const int b = blockIdx.z;
    const float* Xb = X + (long long)b * K * P;
    float* Yb = Y + (long long)b * M * P;
    const float* Rb = MPADD ? (R + (long long)b * M * P) : (const float*)0;

    const int wm = tid >> 2;
    const int wk = (tid & 3) << 2;
    const int xk = tid >> 4;
    const int xp = (tid & 15) << 2;
    const int row0 = (tid >> 4) << 2;
    const int col0 = (tid & 15) << 2;

    ull acc[4][2];
#pragma unroll
    for (int i = 0; i < 4; i++) { acc[i][0] = 0ull; acc[i][1] = 0ull; }

    for (int k0 = 0; k0 < K; k0 += 16) {
        float4 w4 = *(const float4*)(W + (long long)(m0 + wm) * K + (k0 + wk));
        WsD[wk + 0][wm] = dup2(w4.x);
        WsD[wk + 1][wm] = dup2(w4.y);
        WsD[wk + 2][wm] = dup2(w4.z);
        WsD[wk + 3][wm] = dup2(w4.w);
        float4 x4 = *(const float4*)(Xb + (long long)(k0 + xk) * P + (p0 + xp));
        if (SILU_LOAD) {
            x4.x = mp_siluf(x4.x); x4.y = mp_siluf(x4.y);
            x4.z = mp_siluf(x4.z); x4.w = mp_siluf(x4.w);
        }
        *(float4*)(&Xs[xk][xp]) = x4;
        __syncthreads();
#pragma unroll
        for (int kk = 0; kk < 16; kk++) {
            const ulonglong2 a0 = *(const ulonglong2*)(&WsD[kk][row0]);
            const ulonglong2 a1 = *(const ulonglong2*)(&WsD[kk][row0 + 2]);
            const ulonglong2 bp = *(const ulonglong2*)(&Xs[kk][col0]);
            acc[0][0] = ffma2(a0.x, bp.x, acc[0][0]);
            acc[0][1] = ffma2(a0.x, bp.y, acc[0][1]);
            acc[1][0] = ffma2(a0.y, bp.x, acc[1][0]);
            acc[1][1] = ffma2(a0.y, bp.y, acc[1][1]);
            acc[2][0] = ffma2(a1.x, bp.x, acc[2][0]);
            acc[2][1] = ffma2(a1.x, bp.y, acc[2][1]);
            acc[3][0] = ffma2(a1.y, bp.x, acc[3][0]);
            acc[3][1] = ffma2(a1.y, bp.y, acc[3][1]);
        }
        __syncthreads();
    }
#pragma unroll
    for (int i = 0; i < 4; i++) {
        long long base = (long long)(m0 + row0 + i) * P + p0 + col0;
        float2 lo = unpack2(acc[i][0]);
        float2 hi = unpack2(acc[i][1]);
        float4 o = make_float4(lo.x, lo.y, hi.x, hi.y);
        if (MPADD) {
            float4 r4 = *(const float4*)(Rb + base);
            o.x = fmaf(0.7f, r4.x, 0.3f * o.x) * INV058;
            o.y = fmaf(0.7f, r4.y, 0.3f * o.y) * INV058;
            o.z = fmaf(0.7f, r4.z, 0.3f * o.z) * INV058;
            o.w = fmaf(0.7f, r4.w, 0.3f * o.w) * INV058;
        }
        *(float4*)(Yb + base) = o;
    }
}

/* ---------------- depthwise 5x3 conv2d (pad 2,1), silu at output -------- */
__global__ void dwconv2d_silu(const float* __restrict__ in, const float* __restrict__ w,
                              float* __restrict__ out, int C, int F, long long total) {
    long long t = (long long)blockIdx.x * blockDim.x + threadIdx.x;
    if (t >= total) return;
    int l0 = (int)(t & 511) << 2;
    long long r = t >> 9;
    int f = (int)(r % F); r /= F;
    int c = (int)(r % C);
    int b = (int)(r / C);
    const float* base = in + ((long long)(b * C + c)) * F * 2048LL;
    const float* wc = w + c * 15;
    float a0 = 0.f, a1 = 0.f, a2 = 0.f, a3 = 0.f;
#pragma unroll
    for (int df = 0; df < 5; df++) {
        int ff = f + df - 2;
        if (ff < 0 || ff >= F) continue;
        const float* row = base + (long long)ff * 2048;
        float v[6];
#pragma unroll
        for (int j = 0; j < 6; j++) {
            int ll = l0 + j - 1;
            v[j] = (ll >= 0 && ll < 2048) ? row[ll] : 0.f;
        }
#pragma unroll
        for (int dl = 0; dl < 3; dl++) {
            float wv = wc[df * 3 + dl];
            a0 = fmaf(wv, v[dl + 0], a0);
            a1 = fmaf(wv, v[dl + 1], a1);
            a2 = fmaf(wv, v[dl + 2], a2);
            a3 = fmaf(wv, v[dl + 3], a3);
        }
    }
    float* o = out + (((long long)(b * C + c)) * F + f) * 2048LL + l0;
    o[0] = mp_siluf(a0); o[1] = mp_siluf(a1);
    o[2] = mp_siluf(a2); o[3] = mp_siluf(a3);
}

/* ---------------- freq average pool ------------------------------------ */
__global__ void avgpool_f(const float* __restrict__ in, float* __restrict__ out,
                          int C, int F, int Fo, int s, long long total) {
    long long t = (long long)blockIdx.x * blockDim.x + threadIdx.x;
    if (t >= total) return;
    int l = (int)(t & 2047);
    long long r = t >> 11;
    int fo = (int)(r % Fo); r /= Fo;
    int c = (int)(r % C);
    int b = (int)(r / C);
    const float* p = in + (((long long)(b * C + c)) * F + fo * s) * 2048LL + l;
    float sum = 0.f;
    for (int j = 0; j < s; j++) sum += p[(long long)j * 2048];
    out[t] = sum * (1.f / (float)s);
}

/* ---------------- seq: silu -> depthwise k3 -> silu --------------------- */
__global__ void dwconv1d_silu(const float* __restrict__ hg, const float* __restrict__ w,
                              float* __restrict__ out) {
    long long t = (long long)blockIdx.x * blockDim.x + threadIdx.x;
    if (t >= 1048576LL) return;
    int l0 = (int)(t & 511) << 2;
    int c = (int)((t >> 9) & 1023);
    int b = (int)(t >> 19);
    const float* row = hg + ((long long)b * 2048 + c) * 2048LL;
    const float* wc = w + c * 3;
    float v[6];
#pragma unroll
    for (int j = 0; j < 6; j++) {
        int ll = l0 + j - 1;
        v[j] = (ll >= 0 && ll < 2048) ? mp_siluf(row[ll]) : 0.f;
    }
    float a0 = 0.f, a1 = 0.f, a2 = 0.f, a3 = 0.f;
#pragma unroll
    for (int dl = 0; dl < 3; dl++) {
        float wv = wc[dl];
        a0 = fmaf(wv, v[dl + 0], a0);
        a1 = fmaf(wv, v[dl + 1], a1);
        a2 = fmaf(wv, v[dl + 2], a2);
        a3 = fmaf(wv, v[dl + 3], a3);
    }
    float* o = out + ((long long)b * 1024 + c) * 2048LL + l0;
    o[0] = mp_siluf(a0); o[1] = mp_siluf(a1);
    o[2] = mp_siluf(a2); o[3] = mp_siluf(a3);
}

/* ---------------- minGRU warp scan fused with output gate --------------- */
__global__ void gru_scan(const float* __restrict__ u, const float* __restrict__ hg,
                         float* __restrict__ out) {
    int w = (int)((blockIdx.x * blockDim.x + threadIdx.x) >> 5);
    int lane = threadIdx.x & 31;
    if (w >= 2048) return;
    int bt = w >> 10, c = w & 1023;
    const float* zrow = u + ((long long)bt * 2048 + c) * 2048LL;
    const float* crow = zrow + 1024LL * 2048LL;
    const float* grow = hg + ((long long)bt * 2048 + 1024 + c) * 2048LL;
    float* orow = out + ((long long)bt * 1024 + c) * 2048LL;
    float carry = 0.f;
    for (int l0 = 0; l0 < 2048; l0 += 32) {
        float z = sigmoidf_fast(zrow[l0 + lane]);
        float a = 1.f - z;
        float bb = z * crow[l0 + lane];
#pragma unroll
        for (int off = 1; off < 32; off <<= 1) {
            float ap = __shfl_up_sync(0xffffffffu, a, off);
            float bp = __shfl_up_sync(0xffffffffu, bb, off);
            if (lane >= off) { bb = fmaf(a, bp, bb); a *= ap; }
        }
        float ov = fmaf(a, carry, bb);
        carry = __shfl_sync(0xffffffffu, ov, 31);
        orow[l0 + lane] = ov * mp_siluf(grow[l0 + lane]);
    }
}

/* ---------------- final activation -------------------------------------- */
__global__ void silu_out(const float* __restrict__ in, float* __restrict__ out, long long n) {
    long long i = (long long)blockIdx.x * blockDim.x + threadIdx.x;
    if (i < n) out[i] = mp_siluf(in[i]);
}

/* ======================================================================== */
extern "C" void kernel_launch(void* const* d_in, const int* in_sizes, int n_in,
                              void* d_out, int out_size) {
    const float* audio = (const float*)d_in[0];
    const float* pw    = (const float*)d_in[1];
    const float* pb    = (const float*)d_in[2];
    const float* c0w1  = (const float*)d_in[3];
    const float* c0wd  = (const float*)d_in[4];
    const float* c0w2  = (const float*)d_in[5];
    const float* c0dn  = (const float*)d_in[6];
    const float* c1w1  = (const float*)d_in[7];
    const float* c1wd  = (const float*)d_in[8];
    const float* c1w2  = (const float*)d_in[9];
    const float* c1dn  = (const float*)d_in[10];
    const float* c2w1  = (const float*)d_in[11];
    const float* c2wd  = (const float*)d_in[12];
    const float* c2w2  = (const float*)d_in[13];
    const float* c2dn  = (const float*)d_in[14];
    const float* hgw   = (const float*)d_in[15];
    const float* dww   = (const float*)d_in[16];
    const float* gruw  = (const float*)d_in[17];
    const float* outw  = (const float*)d_in[18];

    float *wp, *pm, *xn, *bufA, *bufB, *hb, *pool, *xb;
    cudaGetSymbolAddress((void**)&wp,   g_wpool);
    cudaGetSymbolAddress((void**)&pm,   g_pm);
    cudaGetSymbolAddress((void**)&xn,   g_xn);
    cudaGetSymbolAddress((void**)&bufA, g_bufA);
    cudaGetSymbolAddress((void**)&bufB, g_bufB);
    cudaGetSymbolAddress((void**)&hb,   g_h);
    cudaGetSymbolAddress((void**)&pool, g_pool);
    cudaGetSymbolAddress((void**)&xb,   g_x);

    /* fused weight normalization: one launch for all 16 weight tensors */
    NormDescs nd;
    int acc = 0;
    const float* srcs[16] = {c0w1, c0wd, c0w2, c0dn, c1w1, c1wd, c1w2, c1dn,
                             c2w1, c2wd, c2w2, c2dn, hgw, dww, gruw, outw};
    float* dsts[16] = {wp + O_C0W1, wp + O_C0WD, wp + O_C0W2, wp + O_C0DN,
                       wp + O_C1W1, wp + O_C1WD, wp + O_C1W2, wp + O_C1DN,
                       wp + O_C2W1, wp + O_C2WD, wp + O_C2W2, wp + O_C2DN,
                       wp + O_HG, wp + O_DW, wp + O_GRU, wp + O_OUT};
    int rows[16]   = {128, 128, 64, 128, 256, 256, 128, 256, 512, 512, 256, 512,
                      8192, 4096, 8192, 2048};
    int rowlen[16] = {64, 15, 128, 64, 128, 15, 256, 128, 256, 15, 512, 256,
                      512, 3, 1024, 1024};
    for (int i = 0; i < 16; i++) {
        acc += rows[i];
        nd.s[i].src = srcs[i]; nd.s[i].dst = dsts[i];
        nd.s[i].rowlen = rowlen[i]; nd.s[i].row_end = acc;
    }
    norm_rows_multi<<<acc, 128>>>(nd);

    /* block 0  (C 64->128->64->pool4->128, F=128, P=262144) */
    proj_moments<<<1, 32>>>(pw, pb, pm);
    proj_pixelnorm<<<2048, 256>>>(audio, pw, pb, pm, xn);
    gemm64<true, false><<<dim3(4096, 2, 2), 256>>>(wp + O_C0W1, xn, bufA, (const float*)0, 128, 64, 262144LL);
    dwconv2d_silu<<<65536, 256>>>(bufA, wp + O_C0WD, bufB, 128, 128, 16777216LL);
    gemm64<false, true><<<dim3(4096, 1, 2), 256>>>(wp + O_C0W2, bufB, hb, xn, 64, 128, 262144LL);
    avgpool_f<<<32768, 256>>>(hb, pool, 64, 128, 32, 4, 8388608LL);
    gemm64<false, false><<<dim3(1024, 2, 2), 256>>>(wp + O_C0DN, pool, xb, (const float*)0, 128, 64, 65536LL);

    /* block 1  (C 128->256->128->pool4->256, F=32, P=65536) */
    pixelnorm<<<512, 256>>>(xb, xn, 128, 65536LL, 131072LL);
    gemm64<true, false><<<dim3(1024, 4, 2), 256>>>(wp + O_C1W1, xn, bufA, (const float*)0, 256, 128, 65536LL);
    dwconv2d_silu<<<32768, 256>>>(bufA, wp + O_C1WD, bufB, 256, 32, 8388608LL);
    gemm64<false, true><<<dim3(1024, 2, 2), 256>>>(wp + O_C1W2, bufB, hb, xn, 128, 256, 65536LL);
    avgpool_f<<<16384, 256>>>(hb, pool, 128, 32, 8, 4, 4194304LL);
    gemm64<false, false><<<dim3(256, 4, 2), 256>>>(wp + O_C1DN, pool, xb, (const float*)0, 256, 128, 16384LL);

    /* block 2  (C 256->512->256->pool8->512, F=8, P=16384) */
    pixelnorm<<<128, 256>>>(xb, xn, 256, 16384LL, 32768LL);
    gemm64<true, false><<<dim3(256, 8, 2), 256>>>(wp + O_C2W1, xn, bufA, (const float*)0, 512, 256, 16384LL);
    dwconv2d_silu<<<16384, 256>>>(bufA, wp + O_C2WD, bufB, 512, 8, 4194304LL);
    gemm64<false, true><<<dim3(256, 4, 2), 256>>>(wp + O_C2W2, bufB, hb, xn, 256, 512, 16384LL);
    avgpool_f<<<4096, 256>>>(hb, pool, 256, 8, 1, 8, 1048576LL);
    gemm64<false, false><<<dim3(32, 8, 2), 256>>>(wp + O_C2DN, pool, xb, (const float*)0, 512, 256, 2048LL);

    /* seq blocks ×4  (C=512, L=2048) */
    for (int i = 0; i < 4; i++) {
        pixelnorm<<<16, 256>>>(xb, xn, 512, 2048LL, 4096LL);
        gemm64<false, false><<<dim3(32, 32, 2), 256>>>(wp + O_HG + i * 1048576, xn, bufA, (const float*)0, 2048, 512, 2048LL);
        dwconv1d_silu<<<4096, 256>>>(bufA, wp + O_DW + i * 3072, bufB);
        gemm64<false, false><<<dim3(32, 32, 2), 256>>>(wp + O_GRU + i * 2097152, bufB, hb, (const float*)0, 2048, 1024, 2048LL);
        gru_scan<<<256, 256>>>(hb, bufA, pool);
        gemm64<false, true><<<dim3(32, 8, 2), 256>>>(wp + O_OUT + i * 524288, pool, xb, xn, 512, 1024, 2048LL);
    }

    silu_out<<<8192, 256>>>(xb, (float*)d_out, 2097152LL);
}

// round 7
// speedup vs baseline: 1.4205x; 1.4205x over previous
#include <cuda_runtime.h>
#include <cstdint>

#define GAIN   1.6778523489932886f   /* 1/0.596 */
#define INV058 1.3130643285972254f   /* 1/sqrt(0.7^2+0.3^2) */
#define EPSN   1e-4f

typedef unsigned long long ull;

/* ---------------- static device scratch (no allocations allowed) -------- */
__device__ __align__(16) float g_wpool[15230976];
__device__ __align__(16) float g_pm[4];
__device__ __align__(16) float g_xn[33554432];
__device__ __align__(16) float g_bufA[67108864];
__device__ __align__(16) float g_bufB[67108864];
__device__ __align__(16) float g_h[33554432];
__device__ __align__(16) float g_pool[8388608];
__device__ __align__(16) float g_x[16777216];

/* weight pool offsets (floats), all 16B aligned */
#define O_C0W1 0
#define O_C0WD 8192
#define O_C0W2 10112
#define O_C0DN 18304
#define O_C1W1 26496
#define O_C1WD 59264
#define O_C1W2 63104
#define O_C1DN 95872
#define O_C2W1 128640
#define O_C2WD 259712
#define O_C2W2 267392
#define O_C2DN 398464
#define O_HG   529536
#define O_DW   4723840
#define O_GRU  4736128
#define O_OUT  13124736

__device__ __forceinline__ float sigmoidf_fast(float x) {
    return __fdividef(1.f, 1.f + __expf(-x));
}
__device__ __forceinline__ float mp_siluf(float x) {
    return x * sigmoidf_fast(x) * GAIN;
}

/* packed fp32x2 helpers */
__device__ __forceinline__ ull ffma2(ull a, ull b, ull c) {
    ull d;
    asm("fma.rn.f32x2 %0, %1, %2, %3;" : "=l"(d) : "l"(a), "l"(b), "l"(c));
    return d;
}
__device__ __forceinline__ ull dup2(float v) {
    ull r;
    asm("mov.b64 %0, {%1, %1};" : "=l"(r) : "f"(v));
    return r;
}
__device__ __forceinline__ float2 unpack2(ull v) {
    float2 f;
    asm("mov.b64 {%0, %1}, %2;" : "=f"(f.x), "=f"(f.y) : "l"(v));
    return f;
}

/* ---------------- fused weight normalization (segmented) ----------------- */
struct NormSeg { const float* src; float* dst; int rowlen; int row_end; };
struct NormDescs { NormSeg s[16]; };

__global__ void norm_rows_multi(NormDescs d) {
    int blk = blockIdx.x;
    int seg = 0, row_start = 0;
#pragma unroll
    for (int i = 0; i < 16; i++) {
        if (blk >= d.s[i].row_end) { seg = i + 1; row_start = d.s[i].row_end; }
    }
    int r = blk - row_start;
    int rowlen = d.s[seg].rowlen;
    const float* s = d.s[seg].src + (long long)r * rowlen;
    float* dst = d.s[seg].dst + (long long)r * rowlen;
    float acc = 0.f;
    for (int i = threadIdx.x; i < rowlen; i += blockDim.x) { float v = s[i]; acc = fmaf(v, v, acc); }
#pragma unroll
    for (int off = 16; off; off >>= 1) acc += __shfl_down_sync(0xffffffffu, acc, off);
    __shared__ float sm[8];
    int warp = threadIdx.x >> 5, lane = threadIdx.x & 31;
    if (lane == 0) sm[warp] = acc;
    __syncthreads();
    if (threadIdx.x == 0) {
        float t = 0.f;
        int nw = blockDim.x >> 5;
        for (int i = 0; i < nw; i++) t += sm[i];
        sm[0] = rsqrtf(t + 1e-8f);
    }
    __syncthreads();
    float iv = sm[0];
    for (int i = threadIdx.x; i < rowlen; i += blockDim.x) dst[i] = s[i] * iv;
}

/* ---------------- proj closed-form pixel norm --------------------------- */
__global__ void proj_moments(const float* __restrict__ pw, const float* __restrict__ pb,
                             float* __restrict__ pm) {
    if (threadIdx.x == 0) {
        float a = 0.f, b2 = 0.f, c2 = 0.f;
        for (int i = 0; i < 64; i++) {
            float w = pw[i], bb = pb[i];
            a = fmaf(w, w, a); b2 = fmaf(w, bb, b2); c2 = fmaf(bb, bb, c2);
        }
        pm[0] = a * (1.f / 64.f); pm[1] = b2 * (1.f / 64.f); pm[2] = c2 * (1.f / 64.f);
    }
}

__global__ void proj_pixelnorm(const float* __restrict__ audio, const float* __restrict__ pw,
                               const float* __restrict__ pb, const float* __restrict__ pm,
                               float* __restrict__ xn) {
    long long p = (long long)blockIdx.x * blockDim.x + threadIdx.x;
    if (p >= 524288LL) return;
    float A = audio[p];
    float ms = fmaf(A * A, pm[0], fmaf(2.f * A, pm[1], pm[2]));
    float iv = rsqrtf(ms + EPSN);
    long long b = p >> 18;
    long long rem = p & 262143LL;
    float* o = xn + b * 64LL * 262144LL + rem;
#pragma unroll
    for (int c = 0; c < 64; c++)
        o[(long long)c * 262144LL] = fmaf(A, pw[c], pb[c]) * iv;
}

/* ---------------- generic pixel norm (thread per position) -------------- */
__global__ void pixelnorm(const float* __restrict__ x, float* __restrict__ xn,
                          int C, long long P, long long BP) {
    long long p = (long long)blockIdx.x * blockDim.x + threadIdx.x;
    if (p >= BP) return;
    long long b = p / P, pp = p % P;
    const float* xi = x + b * (long long)C * P + pp;
    float s = 0.f;
#pragma unroll 8
    for (int c = 0; c < C; c++) { float v = xi[(long long)c * P]; s = fmaf(v, v, s); }
    float iv = rsqrtf(s / (float)C + EPSN);
    float* o = xn + b * (long long)C * P + pp;
#pragma unroll 8
    for (int c = 0; c < C; c++) o[(long long)c * P] = xi[(long long)c * P] * iv;
}

/* ------------- fp32x2 GEMM, 128x128 block tile, 8x8/thread -------------- */
/* Y[M,P] = W[M,K] @ X[K,P].  MT = 64*MH rows per block.                   */
/* grid = (P/128, M/MT, B), 256 threads.                                   */
/* Thread (mi=tid>>4, pi=tid&15): rows {mi*4+i, 64+mi*4+i}, cols           */
/* {pi*4+j, 64+pi*4+j}. p-pairs natural from Xs; W dup'ed in registers.    */
template <int MH, bool SILU_LOAD, bool MPADD>
__global__ void __launch_bounds__(256, 2) gemmX(const float* __restrict__ W,
                                                const float* __restrict__ X,
                                                float* __restrict__ Y,
                                                const float* __restrict__ R,
                                                int M, int K, long long P) {
    constexpr int MT = 64 * MH;
    __shared__ __align__(16) float Ws[16][MT + 4];
    __shared__ __align__(16) float Xs[16][132];
    const int tid = threadIdx.x;
    const long long p0 = (long long)blockIdx.x * 128;
    const int m0 = blockIdx.y * MT;
    const int b = blockIdx.z;
    const float* Xb = X + (long long)b * K * P;
    float* Yb = Y + (long long)b * M * P;
    const float* Rb = MPADD ? (R + (long long)b * M * P) : (const float*)0;

    const int mi = tid >> 4;          /* 0..15 */
    const int pi = tid & 15;          /* 0..15 */
    const int xk = tid >> 4;
    const int xp = (tid & 15) << 3;

    ull acc[MH][4][4];
#pragma unroll
    for (int h = 0; h < MH; h++)
#pragma unroll
        for (int i = 0; i < 4; i++)
#pragma unroll
            for (int j = 0; j < 4; j++) acc[h][i][j] = 0ull;

    for (int k0 = 0; k0 < K; k0 += 16) {
        /* ---- stage W tile (transpose K-major gmem -> m-major smem) ---- */
        if (MH == 2) {
            int wm = tid >> 1, wk = (tid & 1) << 3;
            const float* wsrc = W + (long long)(m0 + wm) * K + (k0 + wk);
            float4 a = *(const float4*)(wsrc);
            float4 c = *(const float4*)(wsrc + 4);
            Ws[wk + 0][wm] = a.x; Ws[wk + 1][wm] = a.y;
            Ws[wk + 2][wm] = a.z; Ws[wk + 3][wm] = a.w;
            Ws[wk + 4][wm] = c.x; Ws[wk + 5][wm] = c.y;
            Ws[wk + 6][wm] = c.z; Ws[wk + 7][wm] = c.w;
        } else {
            int wm = tid >> 2, wk = (tid & 3) << 2;
            const float* wsrc = W + (long long)(m0 + wm) * K + (k0 + wk);
            float4 a = *(const float4*)(wsrc);
            Ws[wk + 0][wm] = a.x; Ws[wk + 1][wm] = a.y;
            Ws[wk + 2][wm] = a.z; Ws[wk + 3][wm] = a.w;
        }
        /* ---- stage X tile ---- */
        const float* xsrc = Xb + (long long)(k0 + xk) * P + (p0 + xp);
        float4 x0 = *(const float4*)(xsrc);
        float4 x1 = *(const float4*)(xsrc + 4);
        if (SILU_LOAD) {
            x0.x = mp_siluf(x0.x); x0.y = mp_siluf(x0.y);
            x0.z = mp_siluf(x0.z); x0.w = mp_siluf(x0.w);
            x1.x = mp_siluf(x1.x); x1.y = mp_siluf(x1.y);
            x1.z = mp_siluf(x1.z); x1.w = mp_siluf(x1.w);
        }
        *(float4*)(&Xs[xk][xp]) = x0;
        *(float4*)(&Xs[xk][xp + 4]) = x1;
        __syncthreads();

#pragma unroll
        for (int kk = 0; kk < 16; kk++) {
            const ulonglong2 xa = *(const ulonglong2*)(&Xs[kk][pi << 2]);
            const ulonglong2 xc = *(const ulonglong2*)(&Xs[kk][(pi << 2) + 64]);
#pragma unroll
            for (int h = 0; h < MH; h++) {
                const float4 wv = *(const float4*)(&Ws[kk][(mi << 2) + h * 64]);
                ull wd;
                wd = dup2(wv.x);
                acc[h][0][0] = ffma2(wd, xa.x, acc[h][0][0]);
                acc[h][0][1] = ffma2(wd, xa.y, acc[h][0][1]);
                acc[h][0][2] = ffma2(wd, xc.x, acc[h][0][2]);
                acc[h][0][3] = ffma2(wd, xc.y, acc[h][0][3]);
                wd = dup2(wv.y);
                acc[h][1][0] = ffma2(wd, xa.x, acc[h][1][0]);
                acc[h][1][1] = ffma2(wd, xa.y, acc[h][1][1]);
                acc[h][1][2] = ffma2(wd, xc.x, acc[h][1][2]);
                acc[h][1][3] = ffma2(wd, xc.y, acc[h][1][3]);
                wd = dup2(wv.z);
                acc[h][2][0] = ffma2(wd, xa.x, acc[h][2][0]);
                acc[h][2][1] = ffma2(wd, xa.y, acc[h][2][1]);
                acc[h][2][2] = ffma2(wd, xc.x, acc[h][2][2]);
                acc[h][2][3] = ffma2(wd, xc.y, acc[h][2][3]);
                wd = dup2(wv.w);
                acc[h][3][0] = ffma2(wd, xa.x, acc[h][3][0]);
                acc[h][3][1] = ffma2(wd, xa.y, acc[h][3][1]);
                acc[h][3][2] = ffma2(wd, xc.x, acc[h][3][2]);
                acc[h][3][3] = ffma2(wd, xc.y, acc[h][3][3]);
            }
        }
        __syncthreads();
    }

    /* ---- epilogue ---- */
#pragma unroll
    for (int h = 0; h < MH; h++) {
#pragma unroll
        for (int i = 0; i < 4; i++) {
            long long row = (long long)(m0 + h * 64 + (mi << 2) + i);
#pragma unroll
            for (int half = 0; half < 2; half++) {
                float2 lo = unpack2(acc[h][i][half * 2 + 0]);
                float2 hi = unpack2(acc[h][i][half * 2 + 1]);
                float4 o = make_float4(lo.x, lo.y, hi.x, hi.y);
                long long base = row * P + p0 + (pi << 2) + half * 64;
                if (MPADD) {
                    float4 r4 = *(const float4*)(Rb + base);
                    o.x = fmaf(0.7f, r4.x, 0.3f * o.x) * INV058;
                    o.y = fmaf(0.7f, r4.y, 0.3f * o.y) * INV058;
                    o.z = fmaf(0.7f, r4.z, 0.3f * o.z) * INV058;
                    o.w = fmaf(0.7f, r4.w, 0.3f * o.w) * INV058;
                }
                *(float4*)(Yb + base) = o;
            }
        }
    }
}

/* ---------------- depthwise 5x3 conv2d (pad 2,1), silu at output -------- */
__global__ void dwconv2d_silu(const float* __restrict__ in, const float* __restrict__ w,
                              float* __restrict__ out, int C, int F, long long total) {
    long long t = (long long)blockIdx.x * blockDim.x + threadIdx.x;
    if (t >= total) return;
    int l0 = (int)(t & 511) << 2;
    long long r = t >> 9;
    int f = (int)(r % F); r /= F;
    int c = (int)(r % C);
    int b = (int)(r / C);
    const float* base = in + ((long long)(b * C + c)) * F * 2048LL;
    const float* wc = w + c * 15;
    float a0 = 0.f, a1 = 0.f, a2 = 0.f, a3 = 0.f;
#pragma unroll
    for (int df = 0; df < 5; df++) {
        int ff = f + df - 2;
        if (ff < 0 || ff >= F) continue;
        const float* row = base + (long long)ff * 2048;
        float v[6];
#pragma unroll
        for (int j = 0; j < 6; j++) {
            int ll = l0 + j - 1;
            v[j] = (ll >= 0 && ll < 2048) ? row[ll] : 0.f;
        }
#pragma unroll
        for (int dl = 0; dl < 3; dl++) {
            float wv = wc[df * 3 + dl];
            a0 = fmaf(wv, v[dl + 0], a0);
            a1 = fmaf(wv, v[dl + 1], a1);
            a2 = fmaf(wv, v[dl + 2], a2);
            a3 = fmaf(wv, v[dl + 3], a3);
        }
    }
    float* o = out + (((long long)(b * C + c)) * F + f) * 2048LL + l0;
    o[0] = mp_siluf(a0); o[1] = mp_siluf(a1);
    o[2] = mp_siluf(a2); o[3] = mp_siluf(a3);
}

/* ---------------- freq average pool ------------------------------------ */
__global__ void avgpool_f(const float* __restrict__ in, float* __restrict__ out,
                          int C, int F, int Fo, int s, long long total) {
    long long t = (long long)blockIdx.x * blockDim.x + threadIdx.x;
    if (t >= total) return;
    int l = (int)(t & 2047);
    long long r = t >> 11;
    int fo = (int)(r % Fo); r /= Fo;
    int c = (int)(r % C);
    int b = (int)(r / C);
    const float* p = in + (((long long)(b * C + c)) * F + fo * s) * 2048LL + l;
    float sum = 0.f;
    for (int j = 0; j < s; j++) sum += p[(long long)j * 2048];
    out[t] = sum * (1.f / (float)s);
}

/* ---------------- seq: silu -> depthwise k3 -> silu --------------------- */
__global__ void dwconv1d_silu(const float* __restrict__ hg, const float* __restrict__ w,
                              float* __restrict__ out) {
    long long t = (long long)blockIdx.x * blockDim.x + threadIdx.x;
    if (t >= 1048576LL) return;
    int l0 = (int)(t & 511) << 2;
    int c = (int)((t >> 9) & 1023);
    int b = (int)(t >> 19);
    const float* row = hg + ((long long)b * 2048 + c) * 2048LL;
    const float* wc = w + c * 3;
    float v[6];
#pragma unroll
    for (int j = 0; j < 6; j++) {
        int ll = l0 + j - 1;
        v[j] = (ll >= 0 && ll < 2048) ? mp_siluf(row[ll]) : 0.f;
    }
    float a0 = 0.f, a1 = 0.f, a2 = 0.f, a3 = 0.f;
#pragma unroll
    for (int dl = 0; dl < 3; dl++) {
        float wv = wc[dl];
        a0 = fmaf(wv, v[dl + 0], a0);
        a1 = fmaf(wv, v[dl + 1], a1);
        a2 = fmaf(wv, v[dl + 2], a2);
        a3 = fmaf(wv, v[dl + 3], a3);
    }
    float* o = out + ((long long)b * 1024 + c) * 2048LL + l0;
    o[0] = mp_siluf(a0); o[1] = mp_siluf(a1);
    o[2] = mp_siluf(a2); o[3] = mp_siluf(a3);
}

/* ---------------- minGRU warp scan fused with output gate --------------- */
__global__ void gru_scan(const float* __restrict__ u, const float* __restrict__ hg,
                         float* __restrict__ out) {
    int w = (int)((blockIdx.x * blockDim.x + threadIdx.x) >> 5);
    int lane = threadIdx.x & 31;
    if (w >= 2048) return;
    int bt = w >> 10, c = w & 1023;
    const float* zrow = u + ((long long)bt * 2048 + c) * 2048LL;
    const float* crow = zrow + 1024LL * 2048LL;
    const float* grow = hg + ((long long)bt * 2048 + 1024 + c) * 2048LL;
    float* orow = out + ((long long)bt * 1024 + c) * 2048LL;
    float carry = 0.f;
    for (int l0 = 0; l0 < 2048; l0 += 32) {
        float z = sigmoidf_fast(zrow[l0 + lane]);
        float a = 1.f - z;
        float bb = z * crow[l0 + lane];
#pragma unroll
        for (int off = 1; off < 32; off <<= 1) {
            float ap = __shfl_up_sync(0xffffffffu, a, off);
            float bp = __shfl_up_sync(0xffffffffu, bb, off);
            if (lane >= off) { bb = fmaf(a, bp, bb); a *= ap; }
        }
        float ov = fmaf(a, carry, bb);
        carry = __shfl_sync(0xffffffffu, ov, 31);
        orow[l0 + lane] = ov * mp_siluf(grow[l0 + lane]);
    }
}

/* ---------------- final activation -------------------------------------- */
__global__ void silu_out(const float* __restrict__ in, float* __restrict__ out, long long n) {
    long long i = (long long)blockIdx.x * blockDim.x + threadIdx.x;
    if (i < n) out[i] = mp_siluf(in[i]);
}

/* ======================================================================== */
extern "C" void kernel_launch(void* const* d_in, const int* in_sizes, int n_in,
                              void* d_out, int out_size) {
    const float* audio = (const float*)d_in[0];
    const float* pw    = (const float*)d_in[1];
    const float* pb    = (const float*)d_in[2];
    const float* c0w1  = (const float*)d_in[3];
    const float* c0wd  = (const float*)d_in[4];
    const float* c0w2  = (const float*)d_in[5];
    const float* c0dn  = (const float*)d_in[6];
    const float* c1w1  = (const float*)d_in[7];
    const float* c1wd  = (const float*)d_in[8];
    const float* c1w2  = (const float*)d_in[9];
    const float* c1dn  = (const float*)d_in[10];
    const float* c2w1  = (const float*)d_in[11];
    const float* c2wd  = (const float*)d_in[12];
    const float* c2w2  = (const float*)d_in[13];
    const float* c2dn  = (const float*)d_in[14];
    const float* hgw   = (const float*)d_in[15];
    const float* dww   = (const float*)d_in[16];
    const float* gruw  = (const float*)d_in[17];
    const float* outw  = (const float*)d_in[18];

    float *wp, *pm, *xn, *bufA, *bufB, *hb, *pool, *xb;
    cudaGetSymbolAddress((void**)&wp,   g_wpool);
    cudaGetSymbolAddress((void**)&pm,   g_pm);
    cudaGetSymbolAddress((void**)&xn,   g_xn);
    cudaGetSymbolAddress((void**)&bufA, g_bufA);
    cudaGetSymbolAddress((void**)&bufB, g_bufB);
    cudaGetSymbolAddress((void**)&hb,   g_h);
    cudaGetSymbolAddress((void**)&pool, g_pool);
    cudaGetSymbolAddress((void**)&xb,   g_x);

    /* fused weight normalization: one launch for all 16 weight tensors */
    NormDescs nd;
    int acc = 0;
    const float* srcs[16] = {c0w1, c0wd, c0w2, c0dn, c1w1, c1wd, c1w2, c1dn,
                             c2w1, c2wd, c2w2, c2dn, hgw, dww, gruw, outw};
    float* dsts[16] = {wp + O_C0W1, wp + O_C0WD, wp + O_C0W2, wp + O_C0DN,
                       wp + O_C1W1, wp + O_C1WD, wp + O_C1W2, wp + O_C1DN,
                       wp + O_C2W1, wp + O_C2WD, wp + O_C2W2, wp + O_C2DN,
                       wp + O_HG, wp + O_DW, wp + O_GRU, wp + O_OUT};
    int rows[16]   = {128, 128, 64, 128, 256, 256, 128, 256, 512, 512, 256, 512,
                      8192, 4096, 8192, 2048};
    int rowlen[16] = {64, 15, 128, 64, 128, 15, 256, 128, 256, 15, 512, 256,
                      512, 3, 1024, 1024};
    for (int i = 0; i < 16; i++) {
        acc += rows[i];
        nd.s[i].src = srcs[i]; nd.s[i].dst = dsts[i];
        nd.s[i].rowlen = rowlen[i]; nd.s[i].row_end = acc;
    }
    norm_rows_multi<<<acc, 128>>>(nd);

    /* block 0  (C 64->128->64->pool4->128, F=128, P=262144) */
    proj_moments<<<1, 32>>>(pw, pb, pm);
    proj_pixelnorm<<<2048, 256>>>(audio, pw, pb, pm, xn);
    gemmX<2, true, false><<<dim3(2048, 1, 2), 256>>>(wp + O_C0W1, xn, bufA, (const float*)0, 128, 64, 262144LL);
    dwconv2d_silu<<<65536, 256>>>(bufA, wp + O_C0WD, bufB, 128, 128, 16777216LL);
    gemmX<1, false, true><<<dim3(2048, 1, 2), 256>>>(wp + O_C0W2, bufB, hb, xn, 64, 128, 262144LL);
    avgpool_f<<<32768, 256>>>(hb, pool, 64, 128, 32, 4, 8388608LL);
    gemmX<2, false, false><<<dim3(512, 1, 2), 256>>>(wp + O_C0DN, pool, xb, (const float*)0, 128, 64, 65536LL);

    /* block 1  (C 128->256->128->pool4->256, F=32, P=65536) */
    pixelnorm<<<512, 256>>>(xb, xn, 128, 65536LL, 131072LL);
    gemmX<2, true, false><<<dim3(512, 2, 2), 256>>>(wp + O_C1W1, xn, bufA, (const float*)0, 256, 128, 65536LL);
    dwconv2d_silu<<<32768, 256>>>(bufA, wp + O_C1WD, bufB, 256, 32, 8388608LL);
    gemmX<2, false, true><<<dim3(512, 1, 2), 256>>>(wp + O_C1W2, bufB, hb, xn, 128, 256, 65536LL);
    avgpool_f<<<16384, 256>>>(hb, pool, 128, 32, 8, 4, 4194304LL);
    gemmX<2, false, false><<<dim3(128, 2, 2), 256>>>(wp + O_C1DN, pool, xb, (const float*)0, 256, 128, 16384LL);

    /* block 2  (C 256->512->256->pool8->512, F=8, P=16384) */
    pixelnorm<<<128, 256>>>(xb, xn, 256, 16384LL, 32768LL);
    gemmX<2, true, false><<<dim3(128, 4, 2), 256>>>(wp + O_C2W1, xn, bufA, (const float*)0, 512, 256, 16384LL);
    dwconv2d_silu<<<16384, 256>>>(bufA, wp + O_C2WD, bufB, 512, 8, 4194304LL);
    gemmX<2, false, true><<<dim3(128, 2, 2), 256>>>(wp + O_C2W2, bufB, hb, xn, 256, 512, 16384LL);
    avgpool_f<<<4096, 256>>>(hb, pool, 256, 8, 1, 8, 1048576LL);
    gemmX<2, false, false><<<dim3(16, 4, 2), 256>>>(wp + O_C2DN, pool, xb, (const float*)0, 512, 256, 2048LL);

    /* seq blocks ×4  (C=512, L=2048) */
    for (int i = 0; i < 4; i++) {
        pixelnorm<<<16, 256>>>(xb, xn, 512, 2048LL, 4096LL);
        gemmX<2, false, false><<<dim3(16, 16, 2), 256>>>(wp + O_HG + i * 1048576, xn, bufA, (const float*)0, 2048, 512, 2048LL);
        dwconv1d_silu<<<4096, 256>>>(bufA, wp + O_DW + i * 3072, bufB);
        gemmX<2, false, false><<<dim3(16, 16, 2), 256>>>(wp + O_GRU + i * 2097152, bufB, hb, (const float*)0, 2048, 1024, 2048LL);
        gru_scan<<<256, 256>>>(hb, bufA, pool);
        gemmX<2, false, true><<<dim3(16, 4, 2), 256>>>(wp + O_OUT + i * 524288, pool, xb, xn, 512, 1024, 2048LL);
    }

    silu_out<<<8192, 256>>>(xb, (float*)d_out, 2097152LL);
}

// round 8
// speedup vs baseline: 1.5590x; 1.0975x over previous
#include <cuda_runtime.h>
#include <cstdint>

#define GAIN   1.6778523489932886f   /* 1/0.596 */
#define INV058 1.3130643285972254f   /* 1/sqrt(0.7^2+0.3^2) */
#define EPSN   1e-4f

typedef unsigned long long ull;

/* ---------------- static device scratch (no allocations allowed) -------- */
__device__ __align__(16) float g_wpool[15230976];
__device__ __align__(16) float g_wpoolT[15230976];
__device__ __align__(16) float g_pm[4];
__device__ __align__(16) float g_xn[33554432];
__device__ __align__(16) float g_xs[33554432];
__device__ __align__(16) float g_bufA[67108864];
__device__ __align__(16) float g_bufB[67108864];
__device__ __align__(16) float g_h[33554432];
__device__ __align__(16) float g_pool[8388608];
__device__ __align__(16) float g_x[16777216];

/* weight pool offsets (floats), all 16B aligned */
#define O_C0W1 0
#define O_C0WD 8192
#define O_C0W2 10112
#define O_C0DN 18304
#define O_C1W1 26496
#define O_C1WD 59264
#define O_C1W2 63104
#define O_C1DN 95872
#define O_C2W1 128640
#define O_C2WD 259712
#define O_C2W2 267392
#define O_C2DN 398464
#define O_HG   529536
#define O_DW   4723840
#define O_GRU  4736128
#define O_OUT  13124736

__device__ __forceinline__ float sigmoidf_fast(float x) {
    return __fdividef(1.f, 1.f + __expf(-x));
}
__device__ __forceinline__ float mp_siluf(float x) {
    return x * sigmoidf_fast(x) * GAIN;
}

/* packed fp32x2 helpers */
__device__ __forceinline__ ull ffma2(ull a, ull b, ull c) {
    ull d;
    asm("fma.rn.f32x2 %0, %1, %2, %3;" : "=l"(d) : "l"(a), "l"(b), "l"(c));
    return d;
}
__device__ __forceinline__ ull dup2(float v) {
    ull r;
    asm("mov.b64 %0, {%1, %1};" : "=l"(r) : "f"(v));
    return r;
}
__device__ __forceinline__ float2 unpack2(ull v) {
    float2 f;
    asm("mov.b64 {%0, %1}, %2;" : "=f"(f.x), "=f"(f.y) : "l"(v));
    return f;
}
__device__ __forceinline__ void cpa16(float* s, const float* g) {
    unsigned sa = (unsigned)__cvta_generic_to_shared(s);
    asm volatile("cp.async.cg.shared.global [%0], [%1], 16;" :: "r"(sa), "l"(g) : "memory");
}

/* ---------------- fused weight normalization (segmented) ----------------- */
struct NormSeg { const float* src; float* dst; int rowlen; int row_end; };
struct NormDescs { NormSeg s[16]; };

__global__ void norm_rows_multi(NormDescs d) {
    int blk = blockIdx.x;
    int seg = 0, row_start = 0;
#pragma unroll
    for (int i = 0; i < 16; i++) {
        if (blk >= d.s[i].row_end) { seg = i + 1; row_start = d.s[i].row_end; }
    }
    int r = blk - row_start;
    int rowlen = d.s[seg].rowlen;
    const float* s = d.s[seg].src + (long long)r * rowlen;
    float* dst = d.s[seg].dst + (long long)r * rowlen;
    float acc = 0.f;
    for (int i = threadIdx.x; i < rowlen; i += blockDim.x) { float v = s[i]; acc = fmaf(v, v, acc); }
#pragma unroll
    for (int off = 16; off; off >>= 1) acc += __shfl_down_sync(0xffffffffu, acc, off);
    __shared__ float sm[8];
    int warp = threadIdx.x >> 5, lane = threadIdx.x & 31;
    if (lane == 0) sm[warp] = acc;
    __syncthreads();
    if (threadIdx.x == 0) {
        float t = 0.f;
        int nw = blockDim.x >> 5;
        for (int i = 0; i < nw; i++) t += sm[i];
        sm[0] = rsqrtf(t + 1e-8f);
    }
    __syncthreads();
    float iv = sm[0];
    for (int i = threadIdx.x; i < rowlen; i += blockDim.x) dst[i] = s[i] * iv;
}

/* ---------------- fused weight transpose (segmented, 32x32 tiles) ------- */
struct TSeg { const float* src; float* dst; int M; int K; int tile_end; };
struct TDescs { TSeg s[21]; };

__global__ void transpose_multi(TDescs d) {
    int blk = blockIdx.x;
    int seg = 0, start = 0;
#pragma unroll
    for (int i = 0; i < 21; i++) {
        if (blk >= d.s[i].tile_end) { seg = i + 1; start = d.s[i].tile_end; }
    }
    TSeg sg = d.s[seg];
    int local = blk - start;
    int ktiles = sg.K >> 5;
    int tm = local / ktiles, tk = local - tm * ktiles;
    __shared__ float t[32][33];
    int tid = threadIdx.x;
    int r = tid >> 3;
    int c4 = (tid & 7) << 2;
    const float* s = sg.src + (long long)(tm * 32 + r) * sg.K + tk * 32 + c4;
    float4 v = *(const float4*)s;
    t[r][c4 + 0] = v.x; t[r][c4 + 1] = v.y; t[r][c4 + 2] = v.z; t[r][c4 + 3] = v.w;
    __syncthreads();
    float4 o = make_float4(t[c4 + 0][r], t[c4 + 1][r], t[c4 + 2][r], t[c4 + 3][r]);
    float* dd = sg.dst + (long long)(tk * 32 + r) * sg.M + tm * 32 + c4;
    *(float4*)dd = o;
}

/* ---------------- proj closed-form pixel norm --------------------------- */
__global__ void proj_moments(const float* __restrict__ pw, const float* __restrict__ pb,
                             float* __restrict__ pm) {
    if (threadIdx.x == 0) {
        float a = 0.f, b2 = 0.f, c2 = 0.f;
        for (int i = 0; i < 64; i++) {
            float w = pw[i], bb = pb[i];
            a = fmaf(w, w, a); b2 = fmaf(w, bb, b2); c2 = fmaf(bb, bb, c2);
        }
        pm[0] = a * (1.f / 64.f); pm[1] = b2 * (1.f / 64.f); pm[2] = c2 * (1.f / 64.f);
    }
}

__global__ void proj_pixelnorm(const float* __restrict__ audio, const float* __restrict__ pw,
                               const float* __restrict__ pb, const float* __restrict__ pm,
                               float* __restrict__ xn, float* __restrict__ xs) {
    long long p = (long long)blockIdx.x * blockDim.x + threadIdx.x;
    if (p >= 524288LL) return;
    float A = audio[p];
    float ms = fmaf(A * A, pm[0], fmaf(2.f * A, pm[1], pm[2]));
    float iv = rsqrtf(ms + EPSN);
    long long b = p >> 18;
    long long rem = p & 262143LL;
    long long base = b * 64LL * 262144LL + rem;
#pragma unroll
    for (int c = 0; c < 64; c++) {
        float v = fmaf(A, pw[c], pb[c]) * iv;
        xn[base + (long long)c * 262144LL] = v;
        xs[base + (long long)c * 262144LL] = mp_siluf(v);
    }
}

/* ---------------- generic pixel norm (thread per position) -------------- */
template <bool WS>
__global__ void pixelnorm(const float* __restrict__ x, float* __restrict__ xn,
                          float* __restrict__ xs, int C, long long P, long long BP) {
    long long p = (long long)blockIdx.x * blockDim.x + threadIdx.x;
    if (p >= BP) return;
    long long b = p / P, pp = p % P;
    const float* xi = x + b * (long long)C * P + pp;
    float s = 0.f;
#pragma unroll 8
    for (int c = 0; c < C; c++) { float v = xi[(long long)c * P]; s = fmaf(v, v, s); }
    float iv = rsqrtf(s / (float)C + EPSN);
    long long base = b * (long long)C * P + pp;
#pragma unroll 8
    for (int c = 0; c < C; c++) {
        float v = xi[(long long)c * P] * iv;
        xn[base + (long long)c * P] = v;
        if (WS) xs[base + (long long)c * P] = mp_siluf(v);
    }
}

/* ------- fp32x2 GEMM, cp.async 3-stage pipeline, 128-wide P tile -------- */
/* Y[M,P] = Wn[M,K] @ X[K,P] with Wt = transposed normalized W [K][M].     */
/* MT = 64*MH rows per block. grid = (P/128, M/MT, B), 256 threads.        */
template <int MH, bool MPADD>
__global__ void __launch_bounds__(256, 2) gemmX(const float* __restrict__ Wt,
                                                const float* __restrict__ X,
                                                float* __restrict__ Y,
                                                const float* __restrict__ R,
                                                int M, int K, long long P) {
    constexpr int MT = 64 * MH;
    extern __shared__ float dynsm[];
    float* WsBase = dynsm;                     /* 3 * 16 * MT  */
    float* XsBase = dynsm + 3 * 16 * MT;       /* 3 * 16 * 128 */
    const int tid = threadIdx.x;
    const long long p0 = (long long)blockIdx.x * 128;
    const int m0 = blockIdx.y * MT;
    const int b = blockIdx.z;
    const float* Xb = X + (long long)b * K * P;
    float* Yb = Y + (long long)b * M * P;
    const float* Rb = MPADD ? (R + (long long)b * M * P) : (const float*)0;

    const int mi = tid >> 4;
    const int pi = tid & 15;
    const int lrow = tid >> 4;          /* 0..15 k-row for loads */
    const int xcol = (tid & 15) << 3;   /* 8 floats              */
    const int nt = K >> 4;

    ull acc[MH][4][4];
#pragma unroll
    for (int h = 0; h < MH; h++)
#pragma unroll
        for (int i = 0; i < 4; i++)
#pragma unroll
            for (int j = 0; j < 4; j++) acc[h][i][j] = 0ull;

    auto issue_tile = [&](int kt, int s) {
        float* xsm = XsBase + s * (16 * 128);
        const float* xsrc = Xb + (long long)(kt * 16 + lrow) * P + p0 + xcol;
        cpa16(xsm + lrow * 128 + xcol, xsrc);
        cpa16(xsm + lrow * 128 + xcol + 4, xsrc + 4);
        float* wsm = WsBase + s * (16 * MT);
        if (MH == 2) {
            const float* wsrc = Wt + (long long)(kt * 16 + lrow) * M + m0 + xcol;
            cpa16(wsm + lrow * MT + xcol, wsrc);
            cpa16(wsm + lrow * MT + xcol + 4, wsrc + 4);
        } else {
            const int wcol = (tid & 15) << 2;
            const float* wsrc = Wt + (long long)(kt * 16 + lrow) * M + m0 + wcol;
            cpa16(wsm + lrow * MT + wcol, wsrc);
        }
        asm volatile("cp.async.commit_group;" ::: "memory");
    };

    issue_tile(0, 0);
    for (int kt = 0; kt < nt; kt++) {
        if (kt + 1 < nt) {
            issue_tile(kt + 1, (kt + 1) % 3);
            asm volatile("cp.async.wait_group 1;" ::: "memory");
        } else {
            asm volatile("cp.async.wait_group 0;" ::: "memory");
        }
        __syncthreads();
        const float* ws = WsBase + (kt % 3) * (16 * MT);
        const float* xs = XsBase + (kt % 3) * (16 * 128);
#pragma unroll
        for (int kk = 0; kk < 16; kk++) {
            const ulonglong2 xa = *(const ulonglong2*)(xs + kk * 128 + (pi << 2));
            const ulonglong2 xc = *(const ulonglong2*)(xs + kk * 128 + (pi << 2) + 64);
#pragma unroll
            for (int h = 0; h < MH; h++) {
                const float4 wv = *(const float4*)(ws + kk * MT + (mi << 2) + h * 64);
                ull wd;
                wd = dup2(wv.x);
                acc[h][0][0] = ffma2(wd, xa.x, acc[h][0][0]);
                acc[h][0][1] = ffma2(wd, xa.y, acc[h][0][1]);
                acc[h][0][2] = ffma2(wd, xc.x, acc[h][0][2]);
                acc[h][0][3] = ffma2(wd, xc.y, acc[h][0][3]);
                wd = dup2(wv.y);
                acc[h][1][0] = ffma2(wd, xa.x, acc[h][1][0]);
                acc[h][1][1] = ffma2(wd, xa.y, acc[h][1][1]);
                acc[h][1][2] = ffma2(wd, xc.x, acc[h][1][2]);
                acc[h][1][3] = ffma2(wd, xc.y, acc[h][1][3]);
                wd = dup2(wv.z);
                acc[h][2][0] = ffma2(wd, xa.x, acc[h][2][0]);
                acc[h][2][1] = ffma2(wd, xa.y, acc[h][2][1]);
                acc[h][2][2] = ffma2(wd, xc.x, acc[h][2][2]);
                acc[h][2][3] = ffma2(wd, xc.y, acc[h][2][3]);
                wd = dup2(wv.w);
                acc[h][3][0] = ffma2(wd, xa.x, acc[h][3][0]);
                acc[h][3][1] = ffma2(wd, xa.y, acc[h][3][1]);
                acc[h][3][2] = ffma2(wd, xc.x, acc[h][3][2]);
                acc[h][3][3] = ffma2(wd, xc.y, acc[h][3][3]);
            }
        }
        __syncthreads();
    }

    /* ---- epilogue ---- */
#pragma unroll
    for (int h = 0; h < MH; h++) {
#pragma unroll
        for (int i = 0; i < 4; i++) {
            long long row = (long long)(m0 + h * 64 + (mi << 2) + i);
#pragma unroll
            for (int half = 0; half < 2; half++) {
                float2 lo = unpack2(acc[h][i][half * 2 + 0]);
                float2 hi = unpack2(acc[h][i][half * 2 + 1]);
                float4 o = make_float4(lo.x, lo.y, hi.x, hi.y);
                long long base = row * P + p0 + (pi << 2) + half * 64;
                if (MPADD) {
                    float4 r4 = *(const float4*)(Rb + base);
                    o.x = fmaf(0.7f, r4.x, 0.3f * o.x) * INV058;
                    o.y = fmaf(0.7f, r4.y, 0.3f * o.y) * INV058;
                    o.z = fmaf(0.7f, r4.z, 0.3f * o.z) * INV058;
                    o.w = fmaf(0.7f, r4.w, 0.3f * o.w) * INV058;
                }
                *(float4*)(Yb + base) = o;
            }
        }
    }
}

/* ---------------- depthwise 5x3 conv2d (pad 2,1), silu at output -------- */
__global__ void dwconv2d_silu(const float* __restrict__ in, const float* __restrict__ w,
                              float* __restrict__ out, int C, int F, long long total) {
    long long t = (long long)blockIdx.x * blockDim.x + threadIdx.x;
    if (t >= total) return;
    int l0 = (int)(t & 511) << 2;
    long long r = t >> 9;
    int f = (int)(r % F); r /= F;
    int c = (int)(r % C);
    int b = (int)(r / C);
    const float* base = in + ((long long)(b * C + c)) * F * 2048LL;
    const float* wc = w + c * 15;
    float a0 = 0.f, a1 = 0.f, a2 = 0.f, a3 = 0.f;
#pragma unroll
    for (int df = 0; df < 5; df++) {
        int ff = f + df - 2;
        if (ff < 0 || ff >= F) continue;
        const float* row = base + (long long)ff * 2048;
        float v[6];
#pragma unroll
        for (int j = 0; j < 6; j++) {
            int ll = l0 + j - 1;
            v[j] = (ll >= 0 && ll < 2048) ? row[ll] : 0.f;
        }
#pragma unroll
        for (int dl = 0; dl < 3; dl++) {
            float wv = wc[df * 3 + dl];
            a0 = fmaf(wv, v[dl + 0], a0);
            a1 = fmaf(wv, v[dl + 1], a1);
            a2 = fmaf(wv, v[dl + 2], a2);
            a3 = fmaf(wv, v[dl + 3], a3);
        }
    }
    float* o = out + (((long long)(b * C + c)) * F + f) * 2048LL + l0;
    o[0] = mp_siluf(a0); o[1] = mp_siluf(a1);
    o[2] = mp_siluf(a2); o[3] = mp_siluf(a3);
}

/* ---------------- freq average pool ------------------------------------ */
__global__ void avgpool_f(const float* __restrict__ in, float* __restrict__ out,
                          int C, int F, int Fo, int s, long long total) {
    long long t = (long long)blockIdx.x * blockDim.x + threadIdx.x;
    if (t >= total) return;
    int l = (int)(t & 2047);
    long long r = t >> 11;
    int fo = (int)(r % Fo); r /= Fo;
    int c = (int)(r % C);
    int b = (int)(r / C);
    const float* p = in + (((long long)(b * C + c)) * F + fo * s) * 2048LL + l;
    float sum = 0.f;
    for (int j = 0; j < s; j++) sum += p[(long long)j * 2048];
    out[t] = sum * (1.f / (float)s);
}

/* ---------------- seq: silu -> depthwise k3 -> silu --------------------- */
__global__ void dwconv1d_silu(const float* __restrict__ hg, const float* __restrict__ w,
                              float* __restrict__ out) {
    long long t = (long long)blockIdx.x * blockDim.x + threadIdx.x;
    if (t >= 1048576LL) return;
    int l0 = (int)(t & 511) << 2;
    int c = (int)((t >> 9) & 1023);
    int b = (int)(t >> 19);
    const float* row = hg + ((long long)b * 2048 + c) * 2048LL;
    const float* wc = w + c * 3;
    float v[6];
#pragma unroll
    for (int j = 0; j < 6; j++) {
        int ll = l0 + j - 1;
        v[j] = (ll >= 0 && ll < 2048) ? mp_siluf(row[ll]) : 0.f;
    }
    float a0 = 0.f, a1 = 0.f, a2 = 0.f, a3 = 0.f;
#pragma unroll
    for (int dl = 0; dl < 3; dl++) {
        float wv = wc[dl];
        a0 = fmaf(wv, v[dl + 0], a0);
        a1 = fmaf(wv, v[dl + 1], a1);
        a2 = fmaf(wv, v[dl + 2], a2);
        a3 = fmaf(wv, v[dl + 3], a3);
    }
    float* o = out + ((long long)b * 1024 + c) * 2048LL + l0;
    o[0] = mp_siluf(a0); o[1] = mp_siluf(a1);
    o[2] = mp_siluf(a2); o[3] = mp_siluf(a3);
}

/* ---------------- minGRU warp scan fused with output gate --------------- */
__global__ void gru_scan(const float* __restrict__ u, const float* __restrict__ hg,
                         float* __restrict__ out) {
    int w = (int)((blockIdx.x * blockDim.x + threadIdx.x) >> 5);
    int lane = threadIdx.x & 31;
    if (w >= 2048) return;
    int bt = w >> 10, c = w & 1023;
    const float* zrow = u + ((long long)bt * 2048 + c) * 2048LL;
    const float* crow = zrow + 1024LL * 2048LL;
    const float* grow = hg + ((long long)bt * 2048 + 1024 + c) * 2048LL;
    float* orow = out + ((long long)bt * 1024 + c) * 2048LL;
    float carry = 0.f;
    for (int l0 = 0; l0 < 2048; l0 += 32) {
        float z = sigmoidf_fast(zrow[l0 + lane]);
        float a = 1.f - z;
        float bb = z * crow[l0 + lane];
#pragma unroll
        for (int off = 1; off < 32; off <<= 1) {
            float ap = __shfl_up_sync(0xffffffffu, a, off);
            float bp = __shfl_up_sync(0xffffffffu, bb, off);
            if (lane >= off) { bb = fmaf(a, bp, bb); a *= ap; }
        }
        float ov = fmaf(a, carry, bb);
        carry = __shfl_sync(0xffffffffu, ov, 31);
        orow[l0 + lane] = ov * mp_siluf(grow[l0 + lane]);
    }
}

/* ---------------- final activation -------------------------------------- */
__global__ void silu_out(const float* __restrict__ in, float* __restrict__ out, long long n) {
    long long i = (long long)blockIdx.x * blockDim.x + threadIdx.x;
    if (i < n) out[i] = mp_siluf(i < n ? in[i] : 0.f);
}

/* ======================================================================== */
extern "C" void kernel_launch(void* const* d_in, const int* in_sizes, int n_in,
                              void* d_out, int out_size) {
    const float* audio = (const float*)d_in[0];
    const float* pw    = (const float*)d_in[1];
    const float* pb    = (const float*)d_in[2];
    const float* c0w1  = (const float*)d_in[3];
    const float* c0wd  = (const float*)d_in[4];
    const float* c0w2  = (const float*)d_in[5];
    const float* c0dn  = (const float*)d_in[6];
    const float* c1w1  = (const float*)d_in[7];
    const float* c1wd  = (const float*)d_in[8];
    const float* c1w2  = (const float*)d_in[9];
    const float* c1dn  = (const float*)d_in[10];
    const float* c2w1  = (const float*)d_in[11];
    const float* c2wd  = (const float*)d_in[12];
    const float* c2w2  = (const float*)d_in[13];
    const float* c2dn  = (const float*)d_in[14];
    const float* hgw   = (const float*)d_in[15];
    const float* dww   = (const float*)d_in[16];
    const float* gruw  = (const float*)d_in[17];
    const float* outw  = (const float*)d_in[18];

    float *wp, *wpT, *pm, *xn, *xsb, *bufA, *bufB, *hb, *pool, *xb;
    cudaGetSymbolAddress((void**)&wp,   g_wpool);
    cudaGetSymbolAddress((void**)&wpT,  g_wpoolT);
    cudaGetSymbolAddress((void**)&pm,   g_pm);
    cudaGetSymbolAddress((void**)&xn,   g_xn);
    cudaGetSymbolAddress((void**)&xsb,  g_xs);
    cudaGetSymbolAddress((void**)&bufA, g_bufA);
    cudaGetSymbolAddress((void**)&bufB, g_bufB);
    cudaGetSymbolAddress((void**)&hb,   g_h);
    cudaGetSymbolAddress((void**)&pool, g_pool);
    cudaGetSymbolAddress((void**)&xb,   g_x);

    cudaFuncSetAttribute(gemmX<2, false>, cudaFuncAttributeMaxDynamicSharedMemorySize, 49152);
    cudaFuncSetAttribute(gemmX<2, true>,  cudaFuncAttributeMaxDynamicSharedMemorySize, 49152);
    cudaFuncSetAttribute(gemmX<1, true>,  cudaFuncAttributeMaxDynamicSharedMemorySize, 36864);

    /* fused weight normalization: one launch for all 16 weight tensors */
    NormDescs nd;
    int acc = 0;
    const float* srcs[16] = {c0w1, c0wd, c0w2, c0dn, c1w1, c1wd, c1w2, c1dn,
                             c2w1, c2wd, c2w2, c2dn, hgw, dww, gruw, outw};
    float* dsts[16] = {wp + O_C0W1, wp + O_C0WD, wp + O_C0W2, wp + O_C0DN,
                       wp + O_C1W1, wp + O_C1WD, wp + O_C1W2, wp + O_C1DN,
                       wp + O_C2W1, wp + O_C2WD, wp + O_C2W2, wp + O_C2DN,
                       wp + O_HG, wp + O_DW, wp + O_GRU, wp + O_OUT};
    int rows[16]   = {128, 128, 64, 128, 256, 256, 128, 256, 512, 512, 256, 512,
                      8192, 4096, 8192, 2048};
    int rowlen[16] = {64, 15, 128, 64, 128, 15, 256, 128, 256, 15, 512, 256,
                      512, 3, 1024, 1024};
    for (int i = 0; i < 16; i++) {
        acc += rows[i];
        nd.s[i].src = srcs[i]; nd.s[i].dst = dsts[i];
        nd.s[i].rowlen = rowlen[i]; nd.s[i].row_end = acc;
    }
    norm_rows_multi<<<acc, 128>>>(nd);

    /* fused weight transpose for all GEMM weights -> [K][M] layout */
    TDescs td;
    {
        int toffs[21]; int tM[21]; int tK[21];
        const int offs9[9]  = {O_C0W1, O_C0W2, O_C0DN, O_C1W1, O_C1W2, O_C1DN,
                               O_C2W1, O_C2W2, O_C2DN};
        const int Ms9[9]    = {128, 64, 128, 256, 128, 256, 512, 256, 512};
        const int Ks9[9]    = {64, 128, 64, 128, 256, 128, 256, 512, 256};
        for (int i = 0; i < 9; i++) { toffs[i] = offs9[i]; tM[i] = Ms9[i]; tK[i] = Ks9[i]; }
        for (int i = 0; i < 4; i++) { toffs[9 + i]  = O_HG  + i * 1048576; tM[9 + i]  = 2048; tK[9 + i]  = 512; }
        for (int i = 0; i < 4; i++) { toffs[13 + i] = O_GRU + i * 2097152; tM[13 + i] = 2048; tK[13 + i] = 1024; }
        for (int i = 0; i < 4; i++) { toffs[17 + i] = O_OUT + i * 524288;  tM[17 + i] = 512;  tK[17 + i] = 1024; }
        int tacc = 0;
        for (int i = 0; i < 21; i++) {
            tacc += (tM[i] >> 5) * (tK[i] >> 5);
            td.s[i].src = wp + toffs[i]; td.s[i].dst = wpT + toffs[i];
            td.s[i].M = tM[i]; td.s[i].K = tK[i]; td.s[i].tile_end = tacc;
        }
        transpose_multi<<<tacc, 256>>>(td);
    }

    /* block 0  (C 64->128->64->pool4->128, F=128, P=262144) */
    proj_moments<<<1, 32>>>(pw, pb, pm);
    proj_pixelnorm<<<2048, 256>>>(audio, pw, pb, pm, xn, xsb);
    gemmX<2, false><<<dim3(2048, 1, 2), 256, 49152>>>(wpT + O_C0W1, xsb, bufA, (const float*)0, 128, 64, 262144LL);
    dwconv2d_silu<<<65536, 256>>>(bufA, wp + O_C0WD, bufB, 128, 128, 16777216LL);
    gemmX<1, true><<<dim3(2048, 1, 2), 256, 36864>>>(wpT + O_C0W2, bufB, hb, xn, 64, 128, 262144LL);
    avgpool_f<<<32768, 256>>>(hb, pool, 64, 128, 32, 4, 8388608LL);
    gemmX<2, false><<<dim3(512, 1, 2), 256, 49152>>>(wpT + O_C0DN, pool, xb, (const float*)0, 128, 64, 65536LL);

    /* block 1  (C 128->256->128->pool4->256, F=32, P=65536) */
    pixelnorm<true><<<512, 256>>>(xb, xn, xsb, 128, 65536LL, 131072LL);
    gemmX<2, false><<<dim3(512, 2, 2), 256, 49152>>>(wpT + O_C1W1, xsb, bufA, (const float*)0, 256, 128, 65536LL);
    dwconv2d_silu<<<32768, 256>>>(bufA, wp + O_C1WD, bufB, 256, 32, 8388608LL);
    gemmX<2, true><<<dim3(512, 1, 2), 256, 49152>>>(wpT + O_C1W2, bufB, hb, xn, 128, 256, 65536LL);
    avgpool_f<<<16384, 256>>>(hb, pool, 128, 32, 8, 4, 4194304LL);
    gemmX<2, false><<<dim3(128, 2, 2), 256, 49152>>>(wpT + O_C1DN, pool, xb, (const float*)0, 256, 128, 16384LL);

    /* block 2  (C 256->512->256->pool8->512, F=8, P=16384) */
    pixelnorm<true><<<128, 256>>>(xb, xn, xsb, 256, 16384LL, 32768LL);
    gemmX<2, false><<<dim3(128, 4, 2), 256, 49152>>>(wpT + O_C2W1, xsb, bufA, (const float*)0, 512, 256, 16384LL);
    dwconv2d_silu<<<16384, 256>>>(bufA, wp + O_C2WD, bufB, 512, 8, 4194304LL);
    gemmX<2, true><<<dim3(128, 2, 2), 256, 49152>>>(wpT + O_C2W2, bufB, hb, xn, 256, 512, 16384LL);
    avgpool_f<<<4096, 256>>>(hb, pool, 256, 8, 1, 8, 1048576LL);
    gemmX<2, false><<<dim3(16, 4, 2), 256, 49152>>>(wpT + O_C2DN, pool, xb, (const float*)0, 512, 256, 2048LL);

    /* seq blocks ×4  (C=512, L=2048) */
    for (int i = 0; i < 4; i++) {
        pixelnorm<false><<<16, 256>>>(xb, xn, (float*)0, 512, 2048LL, 4096LL);
        gemmX<2, false><<<dim3(16, 16, 2), 256, 49152>>>(wpT + O_HG + i * 1048576, xn, bufA, (const float*)0, 2048, 512, 2048LL);
        dwconv1d_silu<<<4096, 256>>>(bufA, wp + O_DW + i * 3072, bufB);
        gemmX<2, false><<<dim3(16, 16, 2), 256, 49152>>>(wpT + O_GRU + i * 2097152, bufB, hb, (const float*)0, 2048, 1024, 2048LL);
        gru_scan<<<256, 256>>>(hb, bufA, pool);
        gemmX<2, true><<<dim3(16, 4, 2), 256, 49152>>>(wpT + O_OUT + i * 524288, pool, xb, xn, 512, 1024, 2048LL);
    }

    silu_out<<<8192, 256>>>(xb, (float*)d_out, 2097152LL);
}

// round 10
// speedup vs baseline: 2.0287x; 1.3012x over previous
#include <cuda_runtime.h>
#include <cuda_bf16.h>
#include <cstdint>

#define GAIN   1.6778523489932886f   /* 1/0.596 */
#define INV058 1.3130643285972254f   /* 1/sqrt(0.7^2+0.3^2) */
#define EPSN   1e-4f

typedef unsigned long long ull;

/* ---------------- static device scratch (no allocations allowed) -------- */
__device__ __align__(16) float g_wpool[15230976];
__device__ __align__(16) float g_wpoolT[15230976];
__device__ __align__(16) float g_pm[4];
__device__ __align__(16) float g_xn[33554432];
__device__ __align__(16) float g_xs[33554432];
__device__ __align__(16) float g_bufA[67108864];
__device__ __align__(16) float g_bufB[67108864];
__device__ __align__(16) float g_h[33554432];
__device__ __align__(16) float g_pool[8388608];
__device__ __align__(16) float g_x[16777216];
__device__ __align__(16) __nv_bfloat16 g_wbf[29360128];  /* seq weights hi/lo */
__device__ __align__(16) __nv_bfloat16 g_xt[8388608];    /* XT hi plane + lo plane */

#define XT_LO 4194304

/* weight pool offsets (floats), all 16B aligned */
#define O_C0W1 0
#define O_C0WD 8192
#define O_C0W2 10112
#define O_C0DN 18304
#define O_C1W1 26496
#define O_C1WD 59264
#define O_C1W2 63104
#define O_C1DN 95872
#define O_C2W1 128640
#define O_C2WD 259712
#define O_C2W2 267392
#define O_C2DN 398464
#define O_HG   529536
#define O_DW   4723840
#define O_GRU  4736128
#define O_OUT  13124736

/* bf16 split-weight offsets inside g_wbf */
#define WB_HG(i)  (2097152 * (i))                 /* +1048576 for lo */
#define WB_GRU(i) (8388608 + 4194304 * (i))       /* +2097152 for lo */
#define WB_OUT(i) (25165824 + 1048576 * (i))      /* +524288  for lo */

__device__ __forceinline__ float sigmoidf_fast(float x) {
    return __fdividef(1.f, 1.f + __expf(-x));
}
__device__ __forceinline__ float mp_siluf(float x) {
    return x * sigmoidf_fast(x) * GAIN;
}

/* packed fp32x2 helpers */
__device__ __forceinline__ ull ffma2(ull a, ull b, ull c) {
    ull d;
    asm("fma.rn.f32x2 %0, %1, %2, %3;" : "=l"(d) : "l"(a), "l"(b), "l"(c));
    return d;
}
__device__ __forceinline__ ull dup2(float v) {
    ull r;
    asm("mov.b64 %0, {%1, %1};" : "=l"(r) : "f"(v));
    return r;
}
__device__ __forceinline__ float2 unpack2(ull v) {
    float2 f;
    asm("mov.b64 {%0, %1}, %2;" : "=f"(f.x), "=f"(f.y) : "l"(v));
    return f;
}
__device__ __forceinline__ void cpa16(float* s, const float* g) {
    unsigned sa = (unsigned)__cvta_generic_to_shared(s);
    asm volatile("cp.async.cg.shared.global [%0], [%1], 16;" :: "r"(sa), "l"(g) : "memory");
}
__device__ __forceinline__ void cpa16s(uint32_t saddr, const void* g) {
    asm volatile("cp.async.cg.shared.global [%0], [%1], 16;" :: "r"(saddr), "l"(g) : "memory");
}
__device__ __forceinline__ uint32_t smem_u32(const void* p) {
    uint32_t a;
    asm("{ .reg .u64 t; cvta.to.shared.u64 t, %1; cvt.u32.u64 %0, t; }" : "=r"(a) : "l"(p));
    return a;
}

/* ---------------- warp-MMA helpers (baseline PTX, sm_80+) --------------- */
__device__ __forceinline__ void ldm_x4(uint32_t& a0, uint32_t& a1, uint32_t& a2,
                                       uint32_t& a3, uint32_t addr) {
    asm volatile("ldmatrix.sync.aligned.m8n8.x4.shared.b16 {%0,%1,%2,%3}, [%4];"
                 : "=r"(a0), "=r"(a1), "=r"(a2), "=r"(a3) : "r"(addr));
}
__device__ __forceinline__ void mma16816(float* d, const uint32_t* a, uint32_t b0, uint32_t b1) {
    asm volatile("mma.sync.aligned.m16n8k16.row.col.f32.bf16.bf16.f32 "
                 "{%0,%1,%2,%3}, {%4,%5,%6,%7}, {%8,%9}, {%0,%1,%2,%3};"
                 : "+f"(d[0]), "+f"(d[1]), "+f"(d[2]), "+f"(d[3])
                 : "r"(a[0]), "r"(a[1]), "r"(a[2]), "r"(a[3]), "r"(b0), "r"(b1));
}

/* ---------------- fused weight normalization (segmented) ----------------- */
struct NormSeg { const float* src; float* dst; int rowlen; int row_end; };
struct NormDescs { NormSeg s[16]; };

__global__ void norm_rows_multi(NormDescs d) {
    int blk = blockIdx.x;
    int seg = 0, row_start = 0;
#pragma unroll
    for (int i = 0; i < 16; i++) {
        if (blk >= d.s[i].row_end) { seg = i + 1; row_start = d.s[i].row_end; }
    }
    int r = blk - row_start;
    int rowlen = d.s[seg].rowlen;
    const float* s = d.s[seg].src + (long long)r * rowlen;
    float* dst = d.s[seg].dst + (long long)r * rowlen;
    float acc = 0.f;
    for (int i = threadIdx.x; i < rowlen; i += blockDim.x) { float v = s[i]; acc = fmaf(v, v, acc); }
#pragma unroll
    for (int off = 16; off; off >>= 1) acc += __shfl_down_sync(0xffffffffu, acc, off);
    __shared__ float sm[8];
    int warp = threadIdx.x >> 5, lane = threadIdx.x & 31;
    if (lane == 0) sm[warp] = acc;
    __syncthreads();
    if (threadIdx.x == 0) {
        float t = 0.f;
        int nw = blockDim.x >> 5;
        for (int i = 0; i < nw; i++) t += sm[i];
        sm[0] = rsqrtf(t + 1e-8f);
    }
    __syncthreads();
    float iv = sm[0];
    for (int i = threadIdx.x; i < rowlen; i += blockDim.x) dst[i] = s[i] * iv;
}

/* ---------------- bf16 split of weights --------------------------------- */
__global__ void wsplit(const float* __restrict__ src, __nv_bfloat16* __restrict__ h,
                       __nv_bfloat16* __restrict__ l, int n) {
    int i = blockIdx.x * blockDim.x + threadIdx.x;
    if (i < n) {
        float w = src[i];
        __nv_bfloat16 hi = __float2bfloat16(w);
        h[i] = hi;
        l[i] = __float2bfloat16(w - __bfloat162float(hi));
    }
}

/* ---------------- transpose + bf16 split of activations ------------------ */
/* in: [2][C][2048] fp32; out XT hi/lo: [2][2048][C] bf16                   */
__global__ void xtsplit(const float* __restrict__ x, __nv_bfloat16* __restrict__ xh,
                        __nv_bfloat16* __restrict__ xl, int C) {
    __shared__ float t[32][33];
    int b = blockIdx.z, ct = blockIdx.y, lt = blockIdx.x;
    int tid = threadIdx.x;
    int r = tid >> 3, c4 = (tid & 7) << 2;
    const float* src = x + ((long long)b * C + ct * 32 + r) * 2048LL + lt * 32 + c4;
    float4 v = *(const float4*)src;
    t[r][c4 + 0] = v.x; t[r][c4 + 1] = v.y; t[r][c4 + 2] = v.z; t[r][c4 + 3] = v.w;
    __syncthreads();
    long long o = ((long long)b * 2048 + lt * 32 + r) * C + ct * 32 + c4;
#pragma unroll
    for (int j = 0; j < 4; j++) {
        float val = t[c4 + j][r];
        __nv_bfloat16 hi = __float2bfloat16(val);
        xh[o + j] = hi;
        xl[o + j] = __float2bfloat16(val - __bfloat162float(hi));
    }
}

/* ---------------- fused weight transpose (segmented, 32x32 tiles) ------- */
struct TSeg { const float* src; float* dst; int M; int K; int tile_end; };
struct TDescs { TSeg s[9]; };

__global__ void transpose_multi(TDescs d) {
    int blk = blockIdx.x;
    int seg = 0, start = 0;
#pragma unroll
    for (int i = 0; i < 9; i++) {
        if (blk >= d.s[i].tile_end) { seg = i + 1; start = d.s[i].tile_end; }
    }
    TSeg sg = d.s[seg];
    int local = blk - start;
    int ktiles = sg.K >> 5;
    int tm = local / ktiles, tk = local - tm * ktiles;
    __shared__ float t[32][33];
    int tid = threadIdx.x;
    int r = tid >> 3;
    int c4 = (tid & 7) << 2;
    const float* s = sg.src + (long long)(tm * 32 + r) * sg.K + tk * 32 + c4;
    float4 v = *(const float4*)s;
    t[r][c4 + 0] = v.x; t[r][c4 + 1] = v.y; t[r][c4 + 2] = v.z; t[r][c4 + 3] = v.w;
    __syncthreads();
    float4 o = make_float4(t[c4 + 0][r], t[c4 + 1][r], t[c4 + 2][r], t[c4 + 3][r]);
    float* dd = sg.dst + (long long)(tk * 32 + r) * sg.M + tm * 32 + c4;
    *(float4*)dd = o;
}

/* ---------------- proj closed-form pixel norm --------------------------- */
__global__ void proj_moments(const float* __restrict__ pw, const float* __restrict__ pb,
                             float* __restrict__ pm) {
    if (threadIdx.x == 0) {
        float a = 0.f, b2 = 0.f, c2 = 0.f;
        for (int i = 0; i < 64; i++) {
            float w = pw[i], bb = pb[i];
            a = fmaf(w, w, a); b2 = fmaf(w, bb, b2); c2 = fmaf(bb, bb, c2);
        }
        pm[0] = a * (1.f / 64.f); pm[1] = b2 * (1.f / 64.f); pm[2] = c2 * (1.f / 64.f);
    }
}

__global__ void proj_pixelnorm(const float* __restrict__ audio, const float* __restrict__ pw,
                               const float* __restrict__ pb, const float* __restrict__ pm,
                               float* __restrict__ xn, float* __restrict__ xs) {
    long long p = (long long)blockIdx.x * blockDim.x + threadIdx.x;
    if (p >= 524288LL) return;
    float A = audio[p];
    float ms = fmaf(A * A, pm[0], fmaf(2.f * A, pm[1], pm[2]));
    float iv = rsqrtf(ms + EPSN);
    long long b = p >> 18;
    long long rem = p & 262143LL;
    long long base = b * 64LL * 262144LL + rem;
#pragma unroll
    for (int c = 0; c < 64; c++) {
        float v = fmaf(A, pw[c], pb[c]) * iv;
        xn[base + (long long)c * 262144LL] = v;
        xs[base + (long long)c * 262144LL] = mp_siluf(v);
    }
}

/* ---------------- generic pixel norm (thread per position) -------------- */
template <bool WS>
__global__ void pixelnorm(const float* __restrict__ x, float* __restrict__ xn,
                          float* __restrict__ xs, int C, long long P, long long BP) {
    long long p = (long long)blockIdx.x * blockDim.x + threadIdx.x;
    if (p >= BP) return;
    long long b = p / P, pp = p % P;
    const float* xi = x + b * (long long)C * P + pp;
    float s = 0.f;
#pragma unroll 8
    for (int c = 0; c < C; c++) { float v = xi[(long long)c * P]; s = fmaf(v, v, s); }
    float iv = rsqrtf(s / (float)C + EPSN);
    long long base = b * (long long)C * P + pp;
#pragma unroll 8
    for (int c = 0; c < C; c++) {
        float v = xi[(long long)c * P] * iv;
        xn[base + (long long)c * P] = v;
        if (WS) xs[base + (long long)c * P] = mp_siluf(v);
    }
}

/* ------- fp32x2 GEMM (conv blocks), cp.async 3-stage pipeline ----------- */
template <int MH, bool MPADD>
__global__ void __launch_bounds__(256, 2) gemmX(const float* __restrict__ Wt,
                                                const float* __restrict__ X,
                                                float* __restrict__ Y,
                                                const float* __restrict__ R,
                                                int M, int K, long long P) {
    constexpr int MT = 64 * MH;
    extern __shared__ float dynsm[];
    float* WsBase = dynsm;
    float* XsBase = dynsm + 3 * 16 * MT;
    const int tid = threadIdx.x;
    const long long p0 = (long long)blockIdx.x * 128;
    const int m0 = blockIdx.y * MT;
    const int b = blockIdx.z;
    const float* Xb = X + (long long)b * K * P;
    float* Yb = Y + (long long)b * M * P;
    const float* Rb = MPADD ? (R + (long long)b * M * P) : (const float*)0;

    const int mi = tid >> 4;
    const int pi = tid & 15;
    const int lrow = tid >> 4;
    const int xcol = (tid & 15) << 3;
    const int nt = K >> 4;

    ull acc[MH][4][4];
#pragma unroll
    for (int h = 0; h < MH; h++)
#pragma unroll
        for (int i = 0; i < 4; i++)
#pragma unroll
            for (int j = 0; j < 4; j++) acc[h][i][j] = 0ull;

    auto issue_tile = [&](int kt, int s) {
        float* xsm = XsBase + s * (16 * 128);
        const float* xsrc = Xb + (long long)(kt * 16 + lrow) * P + p0 + xcol;
        cpa16(xsm + lrow * 128 + xcol, xsrc);
        cpa16(xsm + lrow * 128 + xcol + 4, xsrc + 4);
        float* wsm = WsBase + s * (16 * MT);
        if (MH == 2) {
            const float* wsrc = Wt + (long long)(kt * 16 + lrow) * M + m0 + xcol;
            cpa16(wsm + lrow * MT + xcol, wsrc);
            cpa16(wsm + lrow * MT + xcol + 4, wsrc + 4);
        } else {
            const int wcol = (tid & 15) << 2;
            const float* wsrc = Wt + (long long)(kt * 16 + lrow) * M + m0 + wcol;
            cpa16(wsm + lrow * MT + wcol, wsrc);
        }
        asm volatile("cp.async.commit_group;" ::: "memory");
    };

    issue_tile(0, 0);
    for (int kt = 0; kt < nt; kt++) {
        if (kt + 1 < nt) {
            issue_tile(kt + 1, (kt + 1) % 3);
            asm volatile("cp.async.wait_group 1;" ::: "memory");
        } else {
            asm volatile("cp.async.wait_group 0;" ::: "memory");
        }
        __syncthreads();
        const float* ws = WsBase + (kt % 3) * (16 * MT);
        const float* xs = XsBase + (kt % 3) * (16 * 128);
#pragma unroll
        for (int kk = 0; kk < 16; kk++) {
            const ulonglong2 xa = *(const ulonglong2*)(xs + kk * 128 + (pi << 2));
            const ulonglong2 xc = *(const ulonglong2*)(xs + kk * 128 + (pi << 2) + 64);
#pragma unroll
            for (int h = 0; h < MH; h++) {
                const float4 wv = *(const float4*)(ws + kk * MT + (mi << 2) + h * 64);
                ull wd;
                wd = dup2(wv.x);
                acc[h][0][0] = ffma2(wd, xa.x, acc[h][0][0]);
                acc[h][0][1] = ffma2(wd, xa.y, acc[h][0][1]);
                acc[h][0][2] = ffma2(wd, xc.x, acc[h][0][2]);
                acc[h][0][3] = ffma2(wd, xc.y, acc[h][0][3]);
                wd = dup2(wv.y);
                acc[h][1][0] = ffma2(wd, xa.x, acc[h][1][0]);
                acc[h][1][1] = ffma2(wd, xa.y, acc[h][1][1]);
                acc[h][1][2] = ffma2(wd, xc.x, acc[h][1][2]);
                acc[h][1][3] = ffma2(wd, xc.y, acc[h][1][3]);
                wd = dup2(wv.z);
                acc[h][2][0] = ffma2(wd, xa.x, acc[h][2][0]);
                acc[h][2][1] = ffma2(wd, xa.y, acc[h][2][1]);
                acc[h][2][2] = ffma2(wd, xc.x, acc[h][2][2]);
                acc[h][2][3] = ffma2(wd, xc.y, acc[h][2][3]);
                wd = dup2(wv.w);
                acc[h][3][0] = ffma2(wd, xa.x, acc[h][3][0]);
                acc[h][3][1] = ffma2(wd, xa.y, acc[h][3][1]);
                acc[h][3][2] = ffma2(wd, xc.x, acc[h][3][2]);
                acc[h][3][3] = ffma2(wd, xc.y, acc[h][3][3]);
            }
        }
        __syncthreads();
    }

#pragma unroll
    for (int h = 0; h < MH; h++) {
#pragma unroll
        for (int i = 0; i < 4; i++) {
            long long row = (long long)(m0 + h * 64 + (mi << 2) + i);
#pragma unroll
            for (int half = 0; half < 2; half++) {
                float2 lo = unpack2(acc[h][i][half * 2 + 0]);
                float2 hi = unpack2(acc[h][i][half * 2 + 1]);
                float4 o = make_float4(lo.x, lo.y, hi.x, hi.y);
                long long base = row * P + p0 + (pi << 2) + half * 64;
                if (MPADD) {
                    float4 r4 = *(const float4*)(Rb + base);
                    o.x = fmaf(0.7f, r4.x, 0.3f * o.x) * INV058;
                    o.y = fmaf(0.7f, r4.y, 0.3f * o.y) * INV058;
                    o.z = fmaf(0.7f, r4.z, 0.3f * o.z) * INV058;
                    o.w = fmaf(0.7f, r4.w, 0.3f * o.w) * INV058;
                }
                *(float4*)(Yb + base) = o;
            }
        }
    }
}

/* ------------- warp-MMA split-bf16 GEMM (seq blocks) --------------------- */
/* Y[b][M][P] = W[M][K] @ X[b][K][P]; A = W[m][k], B = Xt[p][k] (NT form). */
/* Block tile 128(m) x 128(p) x 32(k); warps 4(m) x 2(p); 256 threads.     */
/* SMEM stage: Wh(0) Wl(8K) Xh(16K) Xl(24K), 2 stages = 64KB.              */
template <bool MPADD>
__global__ void __launch_bounds__(256) mgemm(
    const __nv_bfloat16* __restrict__ Wh, const __nv_bfloat16* __restrict__ Wl,
    const __nv_bfloat16* __restrict__ Xh, const __nv_bfloat16* __restrict__ Xl,
    float* __restrict__ Y, const float* __restrict__ R,
    int M, int K, int P)
{
    extern __shared__ __align__(128) char smraw[];
    const uint32_t smb = smem_u32(smraw);
    const int tid = threadIdx.x;
    const int p0 = blockIdx.x * 128;
    const int m0 = blockIdx.y * 128;
    const int b = blockIdx.z;
    const int ntk = K >> 5;

    const int wid = tid >> 5, lane = tid & 31;
    const int wm = wid & 3, wp = wid >> 2;

    /* load indexing: lanes 0-3 cover one 64B row segment */
    const int lr = tid >> 2;    /* 0..63 */
    const int lc = tid & 3;     /* 16B chunk within row */

    auto load_stage = [&](int kt, int s) {
        uint32_t base = smb + s * 32768;
        int kb = kt * 32 + lc * 8;
        uint32_t swz_c;
#pragma unroll
        for (int g = 0; g < 2; g++) {
            int r = lr + g * 64;
            swz_c = (uint32_t)(r * 64 + ((lc ^ ((r >> 1) & 3)) << 4));
            const __nv_bfloat16* wh = Wh + (long long)(m0 + r) * K + kb;
            const __nv_bfloat16* wl = Wl + (long long)(m0 + r) * K + kb;
            const __nv_bfloat16* xh = Xh + ((long long)b * P + p0 + r) * K + kb;
            const __nv_bfloat16* xl = Xl + ((long long)b * P + p0 + r) * K + kb;
            cpa16s(base + swz_c, wh);
            cpa16s(base + 8192 + swz_c, wl);
            cpa16s(base + 16384 + swz_c, xh);
            cpa16s(base + 24576 + swz_c, xl);
        }
        asm volatile("cp.async.commit_group;" ::: "memory");
    };

    float acc[2][8][4];
#pragma unroll
    for (int i = 0; i < 2; i++)
#pragma unroll
        for (int j = 0; j < 8; j++)
#pragma unroll
            for (int k = 0; k < 4; k++) acc[i][j][k] = 0.f;

    load_stage(0, 0);
    load_stage(1, 1);
    for (int kt = 0; kt < ntk; kt++) {
        const int s = kt & 1;
        if (kt + 1 < ntk) asm volatile("cp.async.wait_group 1;" ::: "memory");
        else              asm volatile("cp.async.wait_group 0;" ::: "memory");
        __syncthreads();
        const uint32_t base = smb + s * 32768;
#pragma unroll
        for (int ks = 0; ks < 2; ks++) {
            /* B fragments: 4 ldmatrix.x4 per plane; x4 covers 2 n-tiles */
            uint32_t bh[4][4], bl[4][4];
#pragma unroll
            for (int np = 0; np < 4; np++) {
                int r = wp * 64 + np * 16 + (lane & 15);
                int c = ks * 2 + (lane >> 4);
                uint32_t ad = base + 16384 + (uint32_t)(r * 64 + ((c ^ ((r >> 1) & 3)) << 4));
                ldm_x4(bh[np][0], bh[np][1], bh[np][2], bh[np][3], ad);
                ldm_x4(bl[np][0], bl[np][1], bl[np][2], bl[np][3], ad + 8192);
            }
#pragma unroll
            for (int mt = 0; mt < 2; mt++) {
                int r = wm * 32 + mt * 16 + (lane & 15);
                int c = ks * 2 + (lane >> 4);
                uint32_t ad = base + (uint32_t)(r * 64 + ((c ^ ((r >> 1) & 3)) << 4));
                uint32_t ah[4], al[4];
                ldm_x4(ah[0], ah[1], ah[2], ah[3], ad);
                ldm_x4(al[0], al[1], al[2], al[3], ad + 8192);
#pragma unroll
                for (int np = 0; np < 4; np++) {
                    /* even n-tile = {r0, r2}, odd = {r1, r3} */
                    mma16816(acc[mt][np * 2],     ah, bh[np][0], bh[np][2]);
                    mma16816(acc[mt][np * 2],     al, bh[np][0], bh[np][2]);
                    mma16816(acc[mt][np * 2],     ah, bl[np][0], bl[np][2]);
                    mma16816(acc[mt][np * 2 + 1], ah, bh[np][1], bh[np][3]);
                    mma16816(acc[mt][np * 2 + 1], al, bh[np][1], bh[np][3]);
                    mma16816(acc[mt][np * 2 + 1], ah, bl[np][1], bl[np][3]);
                }
            }
        }
        __syncthreads();
        if (kt + 2 < ntk) load_stage(kt + 2, s);
    }

    /* epilogue: thread (row = l>>2 (+8), cols 2*(l&3)+{0,1}) */
    const int qrow = lane >> 2;
    const int qcol = (lane & 3) << 1;
#pragma unroll
    for (int mt = 0; mt < 2; mt++) {
#pragma unroll
        for (int nt = 0; nt < 8; nt++) {
            int m = m0 + wm * 32 + mt * 16 + qrow;
            int p = p0 + wp * 64 + nt * 8 + qcol;
            long long o0 = ((long long)b * M + m) * P + p;
            long long o1 = ((long long)b * M + m + 8) * P + p;
            float2 v0 = make_float2(acc[mt][nt][0], acc[mt][nt][1]);
            float2 v1 = make_float2(acc[mt][nt][2], acc[mt][nt][3]);
            if (MPADD) {
                const float2 r0 = *(const float2*)(R + o0);
                const float2 r1 = *(const float2*)(R + o1);
                v0.x = fmaf(0.7f, r0.x, 0.3f * v0.x) * INV058;
                v0.y = fmaf(0.7f, r0.y, 0.3f * v0.y) * INV058;
                v1.x = fmaf(0.7f, r1.x, 0.3f * v1.x) * INV058;
                v1.y = fmaf(0.7f, r1.y, 0.3f * v1.y) * INV058;
            }
            *(float2*)(Y + o0) = v0;
            *(float2*)(Y + o1) = v1;
        }
    }
}

/* ---------------- depthwise 5x3 conv2d (pad 2,1), silu at output -------- */
__global__ void dwconv2d_silu(const float* __restrict__ in, const float* __restrict__ w,
                              float* __restrict__ out, int C, int F, long long total) {
    long long t = (long long)blockIdx.x * blockDim.x + threadIdx.x;
    if (t >= total) return;
    int l0 = (int)(t & 511) << 2;
    long long r = t >> 9;
    int f = (int)(r % F); r /= F;
    int c = (int)(r % C);
    int b = (int)(r / C);
    const float* base = in + ((long long)(b * C + c)) * F * 2048LL;
    const float* wc = w + c * 15;
    float a0 = 0.f, a1 = 0.f, a2 = 0.f, a3 = 0.f;
#pragma unroll
    for (int df = 0; df < 5; df++) {
        int ff = f + df - 2;
        if (ff < 0 || ff >= F) continue;
        const float* row = base + (long long)ff * 2048;
        float v[6];
#pragma unroll
        for (int j = 0; j < 6; j++) {
            int ll = l0 + j - 1;
            v[j] = (ll >= 0 && ll < 2048) ? row[ll] : 0.f;
        }
#pragma unroll
        for (int dl = 0; dl < 3; dl++) {
            float wv = wc[df * 3 + dl];
            a0 = fmaf(wv, v[dl + 0], a0);
            a1 = fmaf(wv, v[dl + 1], a1);
            a2 = fmaf(wv, v[dl + 2], a2);
            a3 = fmaf(wv, v[dl + 3], a3);
        }
    }
    float* o = out + (((long long)(b * C + c)) * F + f) * 2048LL + l0;
    o[0] = mp_siluf(a0); o[1] = mp_siluf(a1);
    o[2] = mp_siluf(a2); o[3] = mp_siluf(a3);
}

/* ---------------- freq average pool ------------------------------------ */
__global__ void avgpool_f(const float* __restrict__ in, float* __restrict__ out,
                          int C, int F, int Fo, int s, long long total) {
    long long t = (long long)blockIdx.x * blockDim.x + threadIdx.x;
    if (t >= total) return;
    int l = (int)(t & 2047);
    long long r = t >> 11;
    int fo = (int)(r % Fo); r /= Fo;
    int c = (int)(r % C);
    int b = (int)(r / C);
    const float* p = in + (((long long)(b * C + c)) * F + fo * s) * 2048LL + l;
    float sum = 0.f;
    for (int j = 0; j < s; j++) sum += p[(long long)j * 2048];
    out[t] = sum * (1.f / (float)s);
}

/* ---------------- seq: silu -> depthwise k3 -> silu --------------------- */
__global__ void dwconv1d_silu(const float* __restrict__ hg, const float* __restrict__ w,
                              float* __restrict__ out) {
    long long t = (long long)blockIdx.x * blockDim.x + threadIdx.x;
    if (t >= 1048576LL) return;
    int l0 = (int)(t & 511) << 2;
    int c = (int)((t >> 9) & 1023);
    int b = (int)(t >> 19);
    const float* row = hg + ((long long)b * 2048 + c) * 2048LL;
    const float* wc = w + c * 3;
    float v[6];
#pragma unroll
    for (int j = 0; j < 6; j++) {
        int ll = l0 + j - 1;
        v[j] = (ll >= 0 && ll < 2048) ? mp_siluf(row[ll]) : 0.f;
    }
    float a0 = 0.f, a1 = 0.f, a2 = 0.f, a3 = 0.f;
#pragma unroll
    for (int dl = 0; dl < 3; dl++) {
        float wv = wc[dl];
        a0 = fmaf(wv, v[dl + 0], a0);
        a1 = fmaf(wv, v[dl + 1], a1);
        a2 = fmaf(wv, v[dl + 2], a2);
        a3 = fmaf(wv, v[dl + 3], a3);
    }
    float* o = out + ((long long)b * 1024 + c) * 2048LL + l0;
    o[0] = mp_siluf(a0); o[1] = mp_siluf(a1);
    o[2] = mp_siluf(a2); o[3] = mp_siluf(a3);
}

/* ---------------- minGRU warp scan fused with output gate --------------- */
__global__ void gru_scan(const float* __restrict__ u, const float* __restrict__ hg,
                         float* __restrict__ out) {
    int w = (int)((blockIdx.x * blockDim.x + threadIdx.x) >> 5);
    int lane = threadIdx.x & 31;
    if (w >= 2048) return;
    int bt = w >> 10, c = w & 1023;
    const float* zrow = u + ((long long)bt * 2048 + c) * 2048LL;
    const float* crow = zrow + 1024LL * 2048LL;
    const float* grow = hg + ((long long)bt * 2048 + 1024 + c) * 2048LL;
    float* orow = out + ((long long)bt * 1024 + c) * 2048LL;
    float carry = 0.f;
    for (int l0 = 0; l0 < 2048; l0 += 32) {
        float z = sigmoidf_fast(zrow[l0 + lane]);
        float a = 1.f - z;
        float bb = z * crow[l0 + lane];
#pragma unroll
        for (int off = 1; off < 32; off <<= 1) {
            float ap = __shfl_up_sync(0xffffffffu, a, off);
            float bp = __shfl_up_sync(0xffffffffu, bb, off);
            if (lane >= off) { bb = fmaf(a, bp, bb); a *= ap; }
        }
        float ov = fmaf(a, carry, bb);
        carry = __shfl_sync(0xffffffffu, ov, 31);
        orow[l0 + lane] = ov * mp_siluf(grow[l0 + lane]);
    }
}

/* ---------------- final activation -------------------------------------- */
__global__ void silu_out(const float* __restrict__ in, float* __restrict__ out, long long n) {
    long long i = (long long)blockIdx.x * blockDim.x + threadIdx.x;
    if (i < n) out[i] = mp_siluf(in[i]);
}

/* ======================================================================== */
extern "C" void kernel_launch(void* const* d_in, const int* in_sizes, int n_in,
                              void* d_out, int out_size) {
    const float* audio = (const float*)d_in[0];
    const float* pw    = (const float*)d_in[1];
    const float* pb    = (const float*)d_in[2];
    const float* c0w1  = (const float*)d_in[3];
    const float* c0wd  = (const float*)d_in[4];
    const float* c0w2  = (const float*)d_in[5];
    const float* c0dn  = (const float*)d_in[6];
    const float* c1w1  = (const float*)d_in[7];
    const float* c1wd  = (const float*)d_in[8];
    const float* c1w2  = (const float*)d_in[9];
    const float* c1dn  = (const float*)d_in[10];
    const float* c2w1  = (const float*)d_in[11];
    const float* c2wd  = (const float*)d_in[12];
    const float* c2w2  = (const float*)d_in[13];
    const float* c2dn  = (const float*)d_in[14];
    const float* hgw   = (const float*)d_in[15];
    const float* dww   = (const float*)d_in[16];
    const float* gruw  = (const float*)d_in[17];
    const float* outw  = (const float*)d_in[18];

    float *wp, *wpT, *pm, *xn, *xsb, *bufA, *bufB, *hb, *pool, *xb;
    __nv_bfloat16 *wbf, *xt;
    cudaGetSymbolAddress((void**)&wp,   g_wpool);
    cudaGetSymbolAddress((void**)&wpT,  g_wpoolT);
    cudaGetSymbolAddress((void**)&pm,   g_pm);
    cudaGetSymbolAddress((void**)&xn,   g_xn);
    cudaGetSymbolAddress((void**)&xsb,  g_xs);
    cudaGetSymbolAddress((void**)&bufA, g_bufA);
    cudaGetSymbolAddress((void**)&bufB, g_bufB);
    cudaGetSymbolAddress((void**)&hb,   g_h);
    cudaGetSymbolAddress((void**)&pool, g_pool);
    cudaGetSymbolAddress((void**)&xb,   g_x);
    cudaGetSymbolAddress((void**)&wbf,  g_wbf);
    cudaGetSymbolAddress((void**)&xt,   g_xt);

    cudaFuncSetAttribute(gemmX<2, false>, cudaFuncAttributeMaxDynamicSharedMemorySize, 49152);
    cudaFuncSetAttribute(gemmX<2, true>,  cudaFuncAttributeMaxDynamicSharedMemorySize, 49152);
    cudaFuncSetAttribute(gemmX<1, true>,  cudaFuncAttributeMaxDynamicSharedMemorySize, 36864);
    cudaFuncSetAttribute(mgemm<false>, cudaFuncAttributeMaxDynamicSharedMemorySize, 65536);
    cudaFuncSetAttribute(mgemm<true>,  cudaFuncAttributeMaxDynamicSharedMemorySize, 65536);

    /* fused weight normalization: one launch for all 16 weight tensors */
    NormDescs nd;
    int acc = 0;
    const float* srcs[16] = {c0w1, c0wd, c0w2, c0dn, c1w1, c1wd, c1w2, c1dn,
                             c2w1, c2wd, c2w2, c2dn, hgw, dww, gruw, outw};
    float* dsts[16] = {wp + O_C0W1, wp + O_C0WD, wp + O_C0W2, wp + O_C0DN,
                       wp + O_C1W1, wp + O_C1WD, wp + O_C1W2, wp + O_C1DN,
                       wp + O_C2W1, wp + O_C2WD, wp + O_C2W2, wp + O_C2DN,
                       wp + O_HG, wp + O_DW, wp + O_GRU, wp + O_OUT};
    int rows[16]   = {128, 128, 64, 128, 256, 256, 128, 256, 512, 512, 256, 512,
                      8192, 4096, 8192, 2048};
    int rowlen[16] = {64, 15, 128, 64, 128, 15, 256, 128, 256, 15, 512, 256,
                      512, 3, 1024, 1024};
    for (int i = 0; i < 16; i++) {
        acc += rows[i];
        nd.s[i].src = srcs[i]; nd.s[i].dst = dsts[i];
        nd.s[i].rowlen = rowlen[i]; nd.s[i].row_end = acc;
    }
    norm_rows_multi<<<acc, 128>>>(nd);

    /* bf16 split of seq weights (hi/lo) */
    for (int i = 0; i < 4; i++) {
        wsplit<<<4096, 256>>>(wp + O_HG + i * 1048576, wbf + WB_HG(i), wbf + WB_HG(i) + 1048576, 1048576);
        wsplit<<<8192, 256>>>(wp + O_GRU + i * 2097152, wbf + WB_GRU(i), wbf + WB_GRU(i) + 2097152, 2097152);
        wsplit<<<2048, 256>>>(wp + O_OUT + i * 524288, wbf + WB_OUT(i), wbf + WB_OUT(i) + 524288, 524288);
    }

    /* weight transpose for conv-block GEMM weights (9 segments) */
    TDescs td;
    {
        const int offs9[9] = {O_C0W1, O_C0W2, O_C0DN, O_C1W1, O_C1W2, O_C1DN,
                              O_C2W1, O_C2W2, O_C2DN};
        const int Ms9[9]   = {128, 64, 128, 256, 128, 256, 512, 256, 512};
        const int Ks9[9]   = {64, 128, 64, 128, 256, 128, 256, 512, 256};
        int tacc = 0;
        for (int i = 0; i < 9; i++) {
            tacc += (Ms9[i] >> 5) * (Ks9[i] >> 5);
            td.s[i].src = wp + offs9[i]; td.s[i].dst = wpT + offs9[i];
            td.s[i].M = Ms9[i]; td.s[i].K = Ks9[i]; td.s[i].tile_end = tacc;
        }
        transpose_multi<<<tacc, 256>>>(td);
    }

    /* block 0  (C 64->128->64->pool4->128, F=128, P=262144) */
    proj_moments<<<1, 32>>>(pw, pb, pm);
    proj_pixelnorm<<<2048, 256>>>(audio, pw, pb, pm, xn, xsb);
    gemmX<2, false><<<dim3(2048, 1, 2), 256, 49152>>>(wpT + O_C0W1, xsb, bufA, (const float*)0, 128, 64, 262144LL);
    dwconv2d_silu<<<65536, 256>>>(bufA, wp + O_C0WD, bufB, 128, 128, 16777216LL);
    gemmX<1, true><<<dim3(2048, 1, 2), 256, 36864>>>(wpT + O_C0W2, bufB, hb, xn, 64, 128, 262144LL);
    avgpool_f<<<32768, 256>>>(hb, pool, 64, 128, 32, 4, 8388608LL);
    gemmX<2, false><<<dim3(512, 1, 2), 256, 49152>>>(wpT + O_C0DN, pool, xb, (const float*)0, 128, 64, 65536LL);

    /* block 1  (C 128->256->128->pool4->256, F=32, P=65536) */
    pixelnorm<true><<<512, 256>>>(xb, xn, xsb, 128, 65536LL, 131072LL);
    gemmX<2, false><<<dim3(512, 2, 2), 256, 49152>>>(wpT + O_C1W1, xsb, bufA, (const float*)0, 256, 128, 65536LL);
    dwconv2d_silu<<<32768, 256>>>(bufA, wp + O_C1WD, bufB, 256, 32, 8388608LL);
    gemmX<2, true><<<dim3(512, 1, 2), 256, 49152>>>(wpT + O_C1W2, bufB, hb, xn, 128, 256, 65536LL);
    avgpool_f<<<16384, 256>>>(hb, pool, 128, 32, 8, 4, 4194304LL);
    gemmX<2, false><<<dim3(128, 2, 2), 256, 49152>>>(wpT + O_C1DN, pool, xb, (const float*)0, 256, 128, 16384LL);

    /* block 2  (C 256->512->256->pool8->512, F=8, P=16384) */
    pixelnorm<true><<<128, 256>>>(xb, xn, xsb, 256, 16384LL, 32768LL);
    gemmX<2, false><<<dim3(128, 4, 2), 256, 49152>>>(wpT + O_C2W1, xsb, bufA, (const float*)0, 512, 256, 16384LL);
    dwconv2d_silu<<<16384, 256>>>(bufA, wp + O_C2WD, bufB, 512, 8, 4194304LL);
    gemmX<2, true><<<dim3(128, 2, 2), 256, 49152>>>(wpT + O_C2W2, bufB, hb, xn, 256, 512, 16384LL);
    avgpool_f<<<4096, 256>>>(hb, pool, 256, 8, 1, 8, 1048576LL);
    gemmX<2, false><<<dim3(16, 4, 2), 256, 49152>>>(wpT + O_C2DN, pool, xb, (const float*)0, 512, 256, 2048LL);

    /* seq blocks ×4  (C=512, L=2048): warp-MMA split-bf16 GEMMs */
    for (int i = 0; i < 4; i++) {
        pixelnorm<false><<<16, 256>>>(xb, xn, (float*)0, 512, 2048LL, 4096LL);
        xtsplit<<<dim3(64, 16, 2), 256>>>(xn, xt, xt + XT_LO, 512);
        mgemm<false><<<dim3(16, 16, 2), 256, 65536>>>(
            wbf + WB_HG(i), wbf + WB_HG(i) + 1048576, xt, xt + XT_LO,
            bufA, (const float*)0, 2048, 512, 2048);
        dwconv1d_silu<<<4096, 256>>>(bufA, wp + O_DW + i * 3072, bufB);
        xtsplit<<<dim3(64, 32, 2), 256>>>(bufB, xt, xt + XT_LO, 1024);
        mgemm<false><<<dim3(16, 16, 2), 256, 65536>>>(
            wbf + WB_GRU(i), wbf + WB_GRU(i) + 2097152, xt, xt + XT_LO,
            hb, (const float*)0, 2048, 1024, 2048);
        gru_scan<<<256, 256>>>(hb, bufA, pool);
        xtsplit<<<dim3(64, 32, 2), 256>>>(pool, xt, xt + XT_LO, 1024);
        mgemm<true><<<dim3(16, 4, 2), 256, 65536>>>(
            wbf + WB_OUT(i), wbf + WB_OUT(i) + 524288, xt, xt + XT_LO,
            xb, xn, 512, 1024, 2048);
    }

    silu_out<<<8192, 256>>>(xb, (float*)d_out, 2097152LL);
}

// round 11
// speedup vs baseline: 2.6739x; 1.3181x over previous
#include <cuda_runtime.h>
#include <cuda_bf16.h>
#include <cstdint>

#define GAIN   1.6778523489932886f   /* 1/0.596 */
#define INV058 1.3130643285972254f   /* 1/sqrt(0.7^2+0.3^2) */
#define EPSN   1e-4f

typedef unsigned long long ull;
typedef __nv_bfloat16 bf16;

/* ---------------- static device scratch (no allocations allowed) -------- */
__device__ __align__(16) float g_wpool[15230976];
__device__ __align__(16) float g_pm[4];
__device__ __align__(16) float g_xn[33554432];
__device__ __align__(16) float g_xs[33554432];    /* bf16 planes: hi | lo   */
__device__ __align__(16) float g_bufA[67108864];
__device__ __align__(16) float g_bufB[67108864];  /* bf16 planes when conv  */
__device__ __align__(16) float g_h[33554432];
__device__ __align__(16) float g_pool[8388608];   /* bf16 planes            */
__device__ __align__(16) float g_x[16777216];
__device__ __align__(16) bf16 g_wbf[29360128];    /* seq weights hi/lo      */
__device__ __align__(16) bf16 g_cwbf[1048576];    /* conv weights hi/lo     */

/* lo-plane offsets (bf16 elements) for buffers reused as bf16 planes */
#define XS_LO   33554432
#define BUFB_LO 67108864
#define POOL_LO 8388608

/* weight pool offsets (floats) */
#define O_C0W1 0
#define O_C0WD 8192
#define O_C0W2 10112
#define O_C0DN 18304
#define O_C1W1 26496
#define O_C1WD 59264
#define O_C1W2 63104
#define O_C1DN 95872
#define O_C2W1 128640
#define O_C2WD 259712
#define O_C2W2 267392
#define O_C2DN 398464
#define O_HG   529536
#define O_DW   4723840
#define O_GRU  4736128
#define O_OUT  13124736

/* bf16 split seq-weight offsets inside g_wbf */
#define WB_HG(i)  (2097152 * (i))
#define WB_GRU(i) (8388608 + 4194304 * (i))
#define WB_OUT(i) (25165824 + 1048576 * (i))

/* bf16 split conv-weight offsets inside g_cwbf (hi, then lo at +size) */
#define CW_C0W1 0
#define CW_C0W2 16384
#define CW_C0DN 32768
#define CW_C1W1 49152
#define CW_C1W2 114688
#define CW_C1DN 180224
#define CW_C2W1 245760
#define CW_C2W2 507904
#define CW_C2DN 770048

__device__ __forceinline__ float sigmoidf_fast(float x) {
    return __fdividef(1.f, 1.f + __expf(-x));
}
__device__ __forceinline__ float mp_siluf(float x) {
    return x * sigmoidf_fast(x) * GAIN;
}
__device__ __forceinline__ void st_split(bf16* h, bf16* l, long long i, float v) {
    bf16 hi = __float2bfloat16(v);
    h[i] = hi;
    l[i] = __float2bfloat16(v - __bfloat162float(hi));
}
__device__ __forceinline__ void cpa16s(uint32_t saddr, const void* g) {
    asm volatile("cp.async.cg.shared.global [%0], [%1], 16;" :: "r"(saddr), "l"(g) : "memory");
}
__device__ __forceinline__ uint32_t smem_u32(const void* p) {
    uint32_t a;
    asm("{ .reg .u64 t; cvta.to.shared.u64 t, %1; cvt.u32.u64 %0, t; }" : "=r"(a) : "l"(p));
    return a;
}

/* ---------------- warp-MMA helpers (baseline PTX, sm_80+) --------------- */
__device__ __forceinline__ void ldm_x4(uint32_t& a0, uint32_t& a1, uint32_t& a2,
                                       uint32_t& a3, uint32_t addr) {
    asm volatile("ldmatrix.sync.aligned.m8n8.x4.shared.b16 {%0,%1,%2,%3}, [%4];"
                 : "=r"(a0), "=r"(a1), "=r"(a2), "=r"(a3) : "r"(addr));
}
__device__ __forceinline__ void ldm_x4t(uint32_t* r, uint32_t addr) {
    asm volatile("ldmatrix.sync.aligned.m8n8.x4.trans.shared.b16 {%0,%1,%2,%3}, [%4];"
                 : "=r"(r[0]), "=r"(r[1]), "=r"(r[2]), "=r"(r[3]) : "r"(addr));
}
__device__ __forceinline__ void mma16816(float* d, const uint32_t* a, uint32_t b0, uint32_t b1) {
    asm volatile("mma.sync.aligned.m16n8k16.row.col.f32.bf16.bf16.f32 "
                 "{%0,%1,%2,%3}, {%4,%5,%6,%7}, {%8,%9}, {%0,%1,%2,%3};"
                 : "+f"(d[0]), "+f"(d[1]), "+f"(d[2]), "+f"(d[3])
                 : "r"(a[0]), "r"(a[1]), "r"(a[2]), "r"(a[3]), "r"(b0), "r"(b1));
}

/* ---------------- fused weight normalization (segmented) ----------------- */
struct NormSeg { const float* src; float* dst; int rowlen; int row_end; };
struct NormDescs { NormSeg s[16]; };

__global__ void norm_rows_multi(NormDescs d) {
    int blk = blockIdx.x;
    int seg = 0, row_start = 0;
#pragma unroll
    for (int i = 0; i < 16; i++) {
        if (blk >= d.s[i].row_end) { seg = i + 1; row_start = d.s[i].row_end; }
    }
    int r = blk - row_start;
    int rowlen = d.s[seg].rowlen;
    const float* s = d.s[seg].src + (long long)r * rowlen;
    float* dst = d.s[seg].dst + (long long)r * rowlen;
    float acc = 0.f;
    for (int i = threadIdx.x; i < rowlen; i += blockDim.x) { float v = s[i]; acc = fmaf(v, v, acc); }
#pragma unroll
    for (int off = 16; off; off >>= 1) acc += __shfl_down_sync(0xffffffffu, acc, off);
    __shared__ float sm[8];
    int warp = threadIdx.x >> 5, lane = threadIdx.x & 31;
    if (lane == 0) sm[warp] = acc;
    __syncthreads();
    if (threadIdx.x == 0) {
        float t = 0.f;
        int nw = blockDim.x >> 5;
        for (int i = 0; i < nw; i++) t += sm[i];
        sm[0] = rsqrtf(t + 1e-8f);
    }
    __syncthreads();
    float iv = sm[0];
    for (int i = threadIdx.x; i < rowlen; i += blockDim.x) dst[i] = s[i] * iv;
}

/* ---------------- bf16 split of weights --------------------------------- */
__global__ void wsplit(const float* __restrict__ src, bf16* __restrict__ h,
                       bf16* __restrict__ l, int n) {
    int i = blockIdx.x * blockDim.x + threadIdx.x;
    if (i < n) {
        float w = src[i];
        bf16 hi = __float2bfloat16(w);
        h[i] = hi;
        l[i] = __float2bfloat16(w - __bfloat162float(hi));
    }
}

/* ---------------- proj closed-form pixel norm --------------------------- */
__global__ void proj_moments(const float* __restrict__ pw, const float* __restrict__ pb,
                             float* __restrict__ pm) {
    if (threadIdx.x == 0) {
        float a = 0.f, b2 = 0.f, c2 = 0.f;
        for (int i = 0; i < 64; i++) {
            float w = pw[i], bb = pb[i];
            a = fmaf(w, w, a); b2 = fmaf(w, bb, b2); c2 = fmaf(bb, bb, c2);
        }
        pm[0] = a * (1.f / 64.f); pm[1] = b2 * (1.f / 64.f); pm[2] = c2 * (1.f / 64.f);
    }
}

/* writes xn fp32 (residual) + silu'd bf16 hi/lo planes (GEMM input) */
__global__ void proj_pixelnorm(const float* __restrict__ audio, const float* __restrict__ pw,
                               const float* __restrict__ pb, const float* __restrict__ pm,
                               float* __restrict__ xn, bf16* __restrict__ xh,
                               bf16* __restrict__ xl) {
    long long p = (long long)blockIdx.x * blockDim.x + threadIdx.x;
    if (p >= 524288LL) return;
    float A = audio[p];
    float ms = fmaf(A * A, pm[0], fmaf(2.f * A, pm[1], pm[2]));
    float iv = rsqrtf(ms + EPSN);
    long long b = p >> 18;
    long long rem = p & 262143LL;
    long long base = b * 64LL * 262144LL + rem;
#pragma unroll
    for (int c = 0; c < 64; c++) {
        float v = fmaf(A, pw[c], pb[c]) * iv;
        long long o = base + (long long)c * 262144LL;
        xn[o] = v;
        st_split(xh, xl, o, mp_siluf(v));
    }
}

/* ---------------- generic pixel norm ------------------------------------ */
/* xn fp32 always; bf16 planes hold silu(v) if SILU else v                  */
template <bool SILU>
__global__ void pixelnorm(const float* __restrict__ x, float* __restrict__ xn,
                          bf16* __restrict__ xh, bf16* __restrict__ xl,
                          int C, long long P, long long BP) {
    long long p = (long long)blockIdx.x * blockDim.x + threadIdx.x;
    if (p >= BP) return;
    long long b = p / P, pp = p % P;
    const float* xi = x + b * (long long)C * P + pp;
    float s = 0.f;
#pragma unroll 8
    for (int c = 0; c < C; c++) { float v = xi[(long long)c * P]; s = fmaf(v, v, s); }
    float iv = rsqrtf(s / (float)C + EPSN);
    long long base = b * (long long)C * P + pp;
#pragma unroll 8
    for (int c = 0; c < C; c++) {
        float v = xi[(long long)c * P] * iv;
        long long o = base + (long long)c * P;
        xn[o] = v;
        st_split(xh, xl, o, SILU ? mp_siluf(v) : v);
    }
}

/* -------- unified split-bf16 tensor GEMM, X in natural [K][P] ----------- */
/* Y[b][M][P] = W[M][K] @ X[b][K][P].  A = W tile [m][k] (non-trans ldsm), */
/* B = X tile [k][p] (trans ldsm).  Block tile BM x 128p x 32k, 256 thr.   */
/* grid = (P/128, M/BM, B).                                                */
template <int BM, bool MPADD>
__global__ void __launch_bounds__(256) cgemm(
    const bf16* __restrict__ Wh, const bf16* __restrict__ Wl,
    const bf16* __restrict__ Xh, const bf16* __restrict__ Xl,
    float* __restrict__ Y, const float* __restrict__ R,
    int M, int K, long long P)
{
    constexpr int WPM = BM / 32;           /* warps along m  */
    constexpr int WPP = 8 / WPM;           /* warps along p  */
    constexpr int PW  = 128 / WPP;         /* p per warp     */
    constexpr int NT  = PW / 8;            /* n-tiles/warp   */
    constexpr int ASZ = BM * 64;           /* bytes/A plane  */
    constexpr int STG = 2 * ASZ + 16384;   /* stage stride   */

    extern __shared__ __align__(128) char smraw[];
    const uint32_t smb = smem_u32(smraw);
    const int tid = threadIdx.x;
    const long long p0 = (long long)blockIdx.x * 128;
    const int m0 = blockIdx.y * BM;
    const int b = blockIdx.z;
    const int ntk = K >> 5;
    const int wid = tid >> 5, lane = tid & 31;
    const int wm = wid % WPM, wp = wid / WPM;

    auto load_stage = [&](int kt, int s) {
        uint32_t base = smb + s * STG;
        /* A planes: rows BM x 64B (32 k bf16), swizzle c^((r>>1)&3) */
#pragma unroll
        for (int g = 0; g < BM / 64; g++) {
            int r = (tid >> 2) + g * 64;
            int c = tid & 3;
            uint32_t off = (uint32_t)(r * 64 + ((c ^ ((r >> 1) & 3)) << 4));
            const bf16* wh = Wh + (long long)(m0 + r) * K + kt * 32 + c * 8;
            const bf16* wl = Wl + (long long)(m0 + r) * K + kt * 32 + c * 8;
            cpa16s(base + off, wh);
            cpa16s(base + ASZ + off, wl);
        }
        /* X planes: rows 32 k x 256B (128 p bf16), swizzle c^(r&7) */
        {
            int r = tid >> 3;
            int cx = tid & 7;
#pragma unroll
            for (int gg = 0; gg < 2; gg++) {
                int c = cx + gg * 8;
                uint32_t off = (uint32_t)(r * 256 + ((c ^ (r & 7)) << 4));
                long long src = ((long long)b * K + kt * 32 + r) * P + p0 + c * 8;
                cpa16s(base + 2 * ASZ + off, Xh + src);
                cpa16s(base + 2 * ASZ + 8192 + off, Xl + src);
            }
        }
        asm volatile("cp.async.commit_group;" ::: "memory");
    };

    float acc[2][NT][4];
#pragma unroll
    for (int i = 0; i < 2; i++)
#pragma unroll
        for (int j = 0; j < NT; j++)
#pragma unroll
            for (int k = 0; k < 4; k++) acc[i][j][k] = 0.f;

    load_stage(0, 0);
    load_stage(1, 1);
    for (int kt = 0; kt < ntk; kt++) {
        const int s = kt & 1;
        if (kt + 1 < ntk) asm volatile("cp.async.wait_group 1;" ::: "memory");
        else              asm volatile("cp.async.wait_group 0;" ::: "memory");
        __syncthreads();
        const uint32_t base = smb + s * STG;
#pragma unroll
        for (int ks = 0; ks < 2; ks++) {
            /* B fragments via trans ldsm: r0,r1 = n-tile even (k0-7, k8-15);
               r2,r3 = n-tile odd */
            uint32_t bh[NT / 2][4], bl[NT / 2][4];
#pragma unroll
            for (int np = 0; np < NT / 2; np++) {
                int r = ks * 16 + (lane & 15);
                int chunk = wp * (PW / 8) + np * 2 + (lane >> 4);
                uint32_t ad = base + 2 * ASZ +
                              (uint32_t)(r * 256 + ((chunk ^ (r & 7)) << 4));
                ldm_x4t(bh[np], ad);
                ldm_x4t(bl[np], ad + 8192);
            }
#pragma unroll
            for (int mt = 0; mt < 2; mt++) {
                int r = wm * 32 + mt * 16 + (lane & 15);
                int chunk = ks * 2 + (lane >> 4);
                uint32_t ad = base + (uint32_t)(r * 64 + ((chunk ^ ((r >> 1) & 3)) << 4));
                uint32_t ah[4], al[4];
                ldm_x4(ah[0], ah[1], ah[2], ah[3], ad);
                ldm_x4(al[0], al[1], al[2], al[3], ad + ASZ);
#pragma unroll
                for (int np = 0; np < NT / 2; np++) {
                    mma16816(acc[mt][np * 2],     ah, bh[np][0], bh[np][1]);
                    mma16816(acc[mt][np * 2],     al, bh[np][0], bh[np][1]);
                    mma16816(acc[mt][np * 2],     ah, bl[np][0], bl[np][1]);
                    mma16816(acc[mt][np * 2 + 1], ah, bh[np][2], bh[np][3]);
                    mma16816(acc[mt][np * 2 + 1], al, bh[np][2], bh[np][3]);
                    mma16816(acc[mt][np * 2 + 1], ah, bl[np][2], bl[np][3]);
                }
            }
        }
        __syncthreads();
        if (kt + 2 < ntk) load_stage(kt + 2, s);
    }

    /* epilogue: thread holds D[m = qrow(+8)][p = qcol + {0,1}] */
    const int qrow = lane >> 2;
    const int qcol = (lane & 3) << 1;
#pragma unroll
    for (int mt = 0; mt < 2; mt++) {
#pragma unroll
        for (int nt = 0; nt < NT; nt++) {
            int m = m0 + wm * 32 + mt * 16 + qrow;
            long long p = p0 + wp * PW + nt * 8 + qcol;
            long long o0 = ((long long)b * M + m) * P + p;
            long long o1 = ((long long)b * M + m + 8) * P + p;
            float2 v0 = make_float2(acc[mt][nt][0], acc[mt][nt][1]);
            float2 v1 = make_float2(acc[mt][nt][2], acc[mt][nt][3]);
            if (MPADD) {
                const float2 r0 = *(const float2*)(R + o0);
                const float2 r1 = *(const float2*)(R + o1);
                v0.x = fmaf(0.7f, r0.x, 0.3f * v0.x) * INV058;
                v0.y = fmaf(0.7f, r0.y, 0.3f * v0.y) * INV058;
                v1.x = fmaf(0.7f, r1.x, 0.3f * v1.x) * INV058;
                v1.y = fmaf(0.7f, r1.y, 0.3f * v1.y) * INV058;
            }
            *(float2*)(Y + o0) = v0;
            *(float2*)(Y + o1) = v1;
        }
    }
}

/* ------- depthwise 5x3 conv2d (pad 2,1), silu, bf16-split output -------- */
__global__ void dwconv2d_silu(const float* __restrict__ in, const float* __restrict__ w,
                              bf16* __restrict__ oh, bf16* __restrict__ ol,
                              int C, int F, long long total) {
    long long t = (long long)blockIdx.x * blockDim.x + threadIdx.x;
    if (t >= total) return;
    int l0 = (int)(t & 511) << 2;
    long long r = t >> 9;
    int f = (int)(r % F); r /= F;
    int c = (int)(r % C);
    int b = (int)(r / C);
    const float* base = in + ((long long)(b * C + c)) * F * 2048LL;
    const float* wc = w + c * 15;
    float a0 = 0.f, a1 = 0.f, a2 = 0.f, a3 = 0.f;
#pragma unroll
    for (int df = 0; df < 5; df++) {
        int ff = f + df - 2;
        if (ff < 0 || ff >= F) continue;
        const float* row = base + (long long)ff * 2048;
        float v[6];
#pragma unroll
        for (int j = 0; j < 6; j++) {
            int ll = l0 + j - 1;
            v[j] = (ll >= 0 && ll < 2048) ? row[ll] : 0.f;
        }
#pragma unroll
        for (int dl = 0; dl < 3; dl++) {
            float wv = wc[df * 3 + dl];
            a0 = fmaf(wv, v[dl + 0], a0);
            a1 = fmaf(wv, v[dl + 1], a1);
            a2 = fmaf(wv, v[dl + 2], a2);
            a3 = fmaf(wv, v[dl + 3], a3);
        }
    }
    long long o = (((long long)(b * C + c)) * F + f) * 2048LL + l0;
    st_split(oh, ol, o + 0, mp_siluf(a0));
    st_split(oh, ol, o + 1, mp_siluf(a1));
    st_split(oh, ol, o + 2, mp_siluf(a2));
    st_split(oh, ol, o + 3, mp_siluf(a3));
}

/* ---------------- freq average pool, bf16-split output ------------------ */
__global__ void avgpool_f(const float* __restrict__ in, bf16* __restrict__ oh,
                          bf16* __restrict__ ol,
                          int C, int F, int Fo, int s, long long total) {
    long long t = (long long)blockIdx.x * blockDim.x + threadIdx.x;
    if (t >= total) return;
    int l = (int)(t & 2047);
    long long r = t >> 11;
    int fo = (int)(r % Fo); r /= Fo;
    int c = (int)(r % C);
    int b = (int)(r / C);
    const float* p = in + (((long long)(b * C + c)) * F + fo * s) * 2048LL + l;
    float sum = 0.f;
    for (int j = 0; j < s; j++) sum += p[(long long)j * 2048];
    st_split(oh, ol, t, sum * (1.f / (float)s));
}

/* --------- seq: silu -> depthwise k3 -> silu, bf16-split output --------- */
__global__ void dwconv1d_silu(const float* __restrict__ hg, const float* __restrict__ w,
                              bf16* __restrict__ oh, bf16* __restrict__ ol) {
    long long t = (long long)blockIdx.x * blockDim.x + threadIdx.x;
    if (t >= 1048576LL) return;
    int l0 = (int)(t & 511) << 2;
    int c = (int)((t >> 9) & 1023);
    int b = (int)(t >> 19);
    const float* row = hg + ((long long)b * 2048 + c) * 2048LL;
    const float* wc = w + c * 3;
    float v[6];
#pragma unroll
    for (int j = 0; j < 6; j++) {
        int ll = l0 + j - 1;
        v[j] = (ll >= 0 && ll < 2048) ? mp_siluf(row[ll]) : 0.f;
    }
    float a0 = 0.f, a1 = 0.f, a2 = 0.f, a3 = 0.f;
#pragma unroll
    for (int dl = 0; dl < 3; dl++) {
        float wv = wc[dl];
        a0 = fmaf(wv, v[dl + 0], a0);
        a1 = fmaf(wv, v[dl + 1], a1);
        a2 = fmaf(wv, v[dl + 2], a2);
        a3 = fmaf(wv, v[dl + 3], a3);
    }
    long long o = ((long long)b * 1024 + c) * 2048LL + l0;
    st_split(oh, ol, o + 0, mp_siluf(a0));
    st_split(oh, ol, o + 1, mp_siluf(a1));
    st_split(oh, ol, o + 2, mp_siluf(a2));
    st_split(oh, ol, o + 3, mp_siluf(a3));
}

/* --------- minGRU warp scan + output gate, bf16-split output ------------ */
__global__ void gru_scan(const float* __restrict__ u, const float* __restrict__ hg,
                         bf16* __restrict__ oh, bf16* __restrict__ ol) {
    int w = (int)((blockIdx.x * blockDim.x + threadIdx.x) >> 5);
    int lane = threadIdx.x & 31;
    if (w >= 2048) return;
    int bt = w >> 10, c = w & 1023;
    const float* zrow = u + ((long long)bt * 2048 + c) * 2048LL;
    const float* crow = zrow + 1024LL * 2048LL;
    const float* grow = hg + ((long long)bt * 2048 + 1024 + c) * 2048LL;
    long long obase = ((long long)bt * 1024 + c) * 2048LL;
    float carry = 0.f;
    for (int l0 = 0; l0 < 2048; l0 += 32) {
        float z = sigmoidf_fast(zrow[l0 + lane]);
        float a = 1.f - z;
        float bb = z * crow[l0 + lane];
#pragma unroll
        for (int off = 1; off < 32; off <<= 1) {
            float ap = __shfl_up_sync(0xffffffffu, a, off);
            float bp = __shfl_up_sync(0xffffffffu, bb, off);
            if (lane >= off) { bb = fmaf(a, bp, bb); a *= ap; }
        }
        float ov = fmaf(a, carry, bb);
        carry = __shfl_sync(0xffffffffu, ov, 31);
        st_split(oh, ol, obase + l0 + lane, ov * mp_siluf(grow[l0 + lane]));
    }
}

/* ---------------- final activation -------------------------------------- */
__global__ void silu_out(const float* __restrict__ in, float* __restrict__ out, long long n) {
    long long i = (long long)blockIdx.x * blockDim.x + threadIdx.x;
    if (i < n) out[i] = mp_siluf(in[i]);
}

/* ======================================================================== */
extern "C" void kernel_launch(void* const* d_in, const int* in_sizes, int n_in,
                              void* d_out, int out_size) {
    const float* audio = (const float*)d_in[0];
    const float* pw    = (const float*)d_in[1];
    const float* pb    = (const float*)d_in[2];
    const float* c0w1  = (const float*)d_in[3];
    const float* c0wd  = (const float*)d_in[4];
    const float* c0w2  = (const float*)d_in[5];
    const float* c0dn  = (const float*)d_in[6];
    const float* c1w1  = (const float*)d_in[7];
    const float* c1wd  = (const float*)d_in[8];
    const float* c1w2  = (const float*)d_in[9];
    const float* c1dn  = (const float*)d_in[10];
    const float* c2w1  = (const float*)d_in[11];
    const float* c2wd  = (const float*)d_in[12];
    const float* c2w2  = (const float*)d_in[13];
    const float* c2dn  = (const float*)d_in[14];
    const float* hgw   = (const float*)d_in[15];
    const float* dww   = (const float*)d_in[16];
    const float* gruw  = (const float*)d_in[17];
    const float* outw  = (const float*)d_in[18];

    float *wp, *pm, *xn, *xsf, *bufA, *bufBf, *hb, *poolf, *xb;
    bf16 *wbf, *cw;
    cudaGetSymbolAddress((void**)&wp,    g_wpool);
    cudaGetSymbolAddress((void**)&pm,    g_pm);
    cudaGetSymbolAddress((void**)&xn,    g_xn);
    cudaGetSymbolAddress((void**)&xsf,   g_xs);
    cudaGetSymbolAddress((void**)&bufA,  g_bufA);
    cudaGetSymbolAddress((void**)&bufBf, g_bufB);
    cudaGetSymbolAddress((void**)&hb,    g_h);
    cudaGetSymbolAddress((void**)&poolf, g_pool);
    cudaGetSymbolAddress((void**)&xb,    g_x);
    cudaGetSymbolAddress((void**)&wbf,   g_wbf);
    cudaGetSymbolAddress((void**)&cw,    g_cwbf);

    bf16* xs   = (bf16*)xsf;      /* hi | lo @ XS_LO   */
    bf16* bufB = (bf16*)bufBf;    /* hi | lo @ BUFB_LO */
    bf16* pool = (bf16*)poolf;    /* hi | lo @ POOL_LO */

    cudaFuncSetAttribute(cgemm<128, false>, cudaFuncAttributeMaxDynamicSharedMemorySize, 65536);
    cudaFuncSetAttribute(cgemm<128, true>,  cudaFuncAttributeMaxDynamicSharedMemorySize, 65536);
    cudaFuncSetAttribute(cgemm<64, true>,   cudaFuncAttributeMaxDynamicSharedMemorySize, 49152);

    /* fused weight normalization: one launch for all 16 weight tensors */
    NormDescs nd;
    int acc = 0;
    const float* srcs[16] = {c0w1, c0wd, c0w2, c0dn, c1w1, c1wd, c1w2, c1dn,
                             c2w1, c2wd, c2w2, c2dn, hgw, dww, gruw, outw};
    float* dsts[16] = {wp + O_C0W1, wp + O_C0WD, wp + O_C0W2, wp + O_C0DN,
                       wp + O_C1W1, wp + O_C1WD, wp + O_C1W2, wp + O_C1DN,
                       wp + O_C2W1, wp + O_C2WD, wp + O_C2W2, wp + O_C2DN,
                       wp + O_HG, wp + O_DW, wp + O_GRU, wp + O_OUT};
    int rows[16]   = {128, 128, 64, 128, 256, 256, 128, 256, 512, 512, 256, 512,
                      8192, 4096, 8192, 2048};
    int rowlen[16] = {64, 15, 128, 64, 128, 15, 256, 128, 256, 15, 512, 256,
                      512, 3, 1024, 1024};
    for (int i = 0; i < 16; i++) {
        acc += rows[i];
        nd.s[i].src = srcs[i]; nd.s[i].dst = dsts[i];
        nd.s[i].rowlen = rowlen[i]; nd.s[i].row_end = acc;
    }
    norm_rows_multi<<<acc, 128>>>(nd);

    /* bf16 split of seq weights (hi/lo) */
    for (int i = 0; i < 4; i++) {
        wsplit<<<4096, 256>>>(wp + O_HG + i * 1048576, wbf + WB_HG(i), wbf + WB_HG(i) + 1048576, 1048576);
        wsplit<<<8192, 256>>>(wp + O_GRU + i * 2097152, wbf + WB_GRU(i), wbf + WB_GRU(i) + 2097152, 2097152);
        wsplit<<<2048, 256>>>(wp + O_OUT + i * 524288, wbf + WB_OUT(i), wbf + WB_OUT(i) + 524288, 524288);
    }
    /* bf16 split of conv GEMM weights */
    {
        const int co[9] = {O_C0W1, O_C0W2, O_C0DN, O_C1W1, O_C1W2, O_C1DN,
                           O_C2W1, O_C2W2, O_C2DN};
        const int cd[9] = {CW_C0W1, CW_C0W2, CW_C0DN, CW_C1W1, CW_C1W2, CW_C1DN,
                           CW_C2W1, CW_C2W2, CW_C2DN};
        const int cn[9] = {8192, 8192, 8192, 32768, 32768, 32768,
                           131072, 131072, 131072};
        for (int i = 0; i < 9; i++)
            wsplit<<<(cn[i] + 255) / 256, 256>>>(wp + co[i], cw + cd[i], cw + cd[i] + cn[i], cn[i]);
    }

    /* block 0  (C 64->128->64->pool4->128, F=128, P=262144) */
    proj_moments<<<1, 32>>>(pw, pb, pm);
    proj_pixelnorm<<<2048, 256>>>(audio, pw, pb, pm, xn, xs, xs + XS_LO);
    cgemm<128, false><<<dim3(2048, 1, 2), 256, 65536>>>(cw + CW_C0W1, cw + CW_C0W1 + 8192,
        xs, xs + XS_LO, bufA, (const float*)0, 128, 64, 262144LL);
    dwconv2d_silu<<<65536, 256>>>(bufA, wp + O_C0WD, bufB, bufB + BUFB_LO, 128, 128, 16777216LL);
    cgemm<64, true><<<dim3(2048, 1, 2), 256, 49152>>>(cw + CW_C0W2, cw + CW_C0W2 + 8192,
        bufB, bufB + BUFB_LO, hb, xn, 64, 128, 262144LL);
    avgpool_f<<<32768, 256>>>(hb, pool, pool + POOL_LO, 64, 128, 32, 4, 8388608LL);
    cgemm<128, false><<<dim3(512, 1, 2), 256, 65536>>>(cw + CW_C0DN, cw + CW_C0DN + 8192,
        pool, pool + POOL_LO, xb, (const float*)0, 128, 64, 65536LL);

    /* block 1  (C 128->256->128->pool4->256, F=32, P=65536) */
    pixelnorm<true><<<512, 256>>>(xb, xn, xs, xs + XS_LO, 128, 65536LL, 131072LL);
    cgemm<128, false><<<dim3(512, 2, 2), 256, 65536>>>(cw + CW_C1W1, cw + CW_C1W1 + 32768,
        xs, xs + XS_LO, bufA, (const float*)0, 256, 128, 65536LL);
    dwconv2d_silu<<<32768, 256>>>(bufA, wp + O_C1WD, bufB, bufB + BUFB_LO, 256, 32, 8388608LL);
    cgemm<128, true><<<dim3(512, 1, 2), 256, 65536>>>(cw + CW_C1W2, cw + CW_C1W2 + 32768,
        bufB, bufB + BUFB_LO, hb, xn, 128, 256, 65536LL);
    avgpool_f<<<16384, 256>>>(hb, pool, pool + POOL_LO, 128, 32, 8, 4, 4194304LL);
    cgemm<128, false><<<dim3(128, 2, 2), 256, 65536>>>(cw + CW_C1DN, cw + CW_C1DN + 32768,
        pool, pool + POOL_LO, xb, (const float*)0, 256, 128, 16384LL);

    /* block 2  (C 256->512->256->pool8->512, F=8, P=16384) */
    pixelnorm<true><<<128, 256>>>(xb, xn, xs, xs + XS_LO, 256, 16384LL, 32768LL);
    cgemm<128, false><<<dim3(128, 4, 2), 256, 65536>>>(cw + CW_C2W1, cw + CW_C2W1 + 131072,
        xs, xs + XS_LO, bufA, (const float*)0, 512, 256, 16384LL);
    dwconv2d_silu<<<16384, 256>>>(bufA, wp + O_C2WD, bufB, bufB + BUFB_LO, 512, 8, 4194304LL);
    cgemm<128, true><<<dim3(128, 2, 2), 256, 65536>>>(cw + CW_C2W2, cw + CW_C2W2 + 131072,
        bufB, bufB + BUFB_LO, hb, xn, 256, 512, 16384LL);
    avgpool_f<<<4096, 256>>>(hb, pool, pool + POOL_LO, 256, 8, 1, 8, 1048576LL);
    cgemm<128, false><<<dim3(16, 4, 2), 256, 65536>>>(cw + CW_C2DN, cw + CW_C2DN + 131072,
        pool, pool + POOL_LO, xb, (const float*)0, 512, 256, 2048LL);

    /* seq blocks ×4  (C=512, L=2048) */
    for (int i = 0; i < 4; i++) {
        pixelnorm<false><<<16, 256>>>(xb, xn, xs, xs + XS_LO, 512, 2048LL, 4096LL);
        cgemm<128, false><<<dim3(16, 16, 2), 256, 65536>>>(
            wbf + WB_HG(i), wbf + WB_HG(i) + 1048576, xs, xs + XS_LO,
            bufA, (const float*)0, 2048, 512, 2048LL);
        dwconv1d_silu<<<4096, 256>>>(bufA, wp + O_DW + i * 3072, bufB, bufB + BUFB_LO);
        cgemm<128, false><<<dim3(16, 16, 2), 256, 65536>>>(
            wbf + WB_GRU(i), wbf + WB_GRU(i) + 2097152, bufB, bufB + BUFB_LO,
            hb, (const float*)0, 2048, 1024, 2048LL);
        gru_scan<<<256, 256>>>(hb, bufA, pool, pool + POOL_LO);
        cgemm<128, true><<<dim3(16, 4, 2), 256, 65536>>>(
            wbf + WB_OUT(i), wbf + WB_OUT(i) + 524288, pool, pool + POOL_LO,
            xb, xn, 512, 1024, 2048LL);
    }

    silu_out<<<8192, 256>>>(xb, (float*)d_out, 2097152LL);
}

// round 12
// speedup vs baseline: 2.8672x; 1.0723x over previous
#include <cuda_runtime.h>
#include <cuda_bf16.h>
#include <cstdint>

#define GAIN   1.6778523489932886f   /* 1/0.596 */
#define INV058 1.3130643285972254f   /* 1/sqrt(0.7^2+0.3^2) */
#define EPSN   1e-4f

typedef unsigned long long ull;
typedef __nv_bfloat16 bf16;

/* ---------------- static device scratch (no allocations allowed) -------- */
__device__ __align__(16) float g_wpool[15230976];
__device__ __align__(16) float g_xn[33554432];
__device__ __align__(16) float g_xs[33554432];    /* bf16 planes: hi | lo   */
__device__ __align__(16) float g_bufA[67108864];
__device__ __align__(16) float g_bufB[67108864];  /* bf16 planes            */
__device__ __align__(16) float g_h[33554432];
__device__ __align__(16) float g_pool[8388608];   /* bf16 planes            */
__device__ __align__(16) float g_x[16777216];
__device__ __align__(16) bf16 g_wbf[29360128];    /* seq weights: hi | lo   */
__device__ __align__(16) bf16 g_cwbf[1048576];    /* conv weights: hi | lo  */

/* lo-plane offsets (bf16 elements) for buffers reused as bf16 planes */
#define XS_LO   33554432
#define BUFB_LO 67108864
#define POOL_LO 8388608

/* fp32 weight pool offsets (depthwise weights only) */
#define O_C0WD 8192
#define O_C1WD 59264
#define O_C2WD 259712
#define O_DW   4723840

/* bf16 conv-weight hi offsets in g_cwbf; lo at +CWLO */
#define CWLO 516096
#define CWH_C0W1 0
#define CWH_C0W2 8192
#define CWH_C0DN 16384
#define CWH_C1W1 24576
#define CWH_C1W2 57344
#define CWH_C1DN 90112
#define CWH_C2W1 122880
#define CWH_C2W2 253952
#define CWH_C2DN 385024

/* bf16 seq-weight hi offsets in g_wbf; lo at +WLO */
#define WLO 14680064
#define WH_HG(i)  ((i) * 1048576)
#define WH_GRU(i) (4194304 + (i) * 2097152)
#define WH_OUT(i) (12582912 + (i) * 524288)

__device__ __forceinline__ float sigmoidf_fast(float x) {
    return __fdividef(1.f, 1.f + __expf(-x));
}
__device__ __forceinline__ float mp_siluf(float x) {
    return x * sigmoidf_fast(x) * GAIN;
}
__device__ __forceinline__ void st_split(bf16* h, bf16* l, long long i, float v) {
    bf16 hi = __float2bfloat16(v);
    h[i] = hi;
    l[i] = __float2bfloat16(v - __bfloat162float(hi));
}
__device__ __forceinline__ void cpa16s(uint32_t saddr, const void* g) {
    asm volatile("cp.async.cg.shared.global [%0], [%1], 16;" :: "r"(saddr), "l"(g) : "memory");
}
__device__ __forceinline__ uint32_t smem_u32(const void* p) {
    uint32_t a;
    asm("{ .reg .u64 t; cvta.to.shared.u64 t, %1; cvt.u32.u64 %0, t; }" : "=r"(a) : "l"(p));
    return a;
}

/* ---------------- warp-MMA helpers (baseline PTX, sm_80+) --------------- */
__device__ __forceinline__ void ldm_x4(uint32_t& a0, uint32_t& a1, uint32_t& a2,
                                       uint32_t& a3, uint32_t addr) {
    asm volatile("ldmatrix.sync.aligned.m8n8.x4.shared.b16 {%0,%1,%2,%3}, [%4];"
                 : "=r"(a0), "=r"(a1), "=r"(a2), "=r"(a3) : "r"(addr));
}
__device__ __forceinline__ void ldm_x4t(uint32_t* r, uint32_t addr) {
    asm volatile("ldmatrix.sync.aligned.m8n8.x4.trans.shared.b16 {%0,%1,%2,%3}, [%4];"
                 : "=r"(r[0]), "=r"(r[1]), "=r"(r[2]), "=r"(r[3]) : "r"(addr));
}
__device__ __forceinline__ void mma16816(float* d, const uint32_t* a, uint32_t b0, uint32_t b1) {
    asm volatile("mma.sync.aligned.m16n8k16.row.col.f32.bf16.bf16.f32 "
                 "{%0,%1,%2,%3}, {%4,%5,%6,%7}, {%8,%9}, {%0,%1,%2,%3};"
                 : "+f"(d[0]), "+f"(d[1]), "+f"(d[2]), "+f"(d[3])
                 : "r"(a[0]), "r"(a[1]), "r"(a[2]), "r"(a[3]), "r"(b0), "r"(b1));
}

/* -------- fused weight normalization + bf16 split (segmented) ----------- */
struct NormSeg { const float* src; float* dstf; bf16* dsth; bf16* dstl;
                 int rowlen; int row_end; };
struct NormDescs { NormSeg s[16]; };

__global__ void norm_rows_multi(NormDescs d) {
    int blk = blockIdx.x;
    int seg = 0, row_start = 0;
#pragma unroll
    for (int i = 0; i < 16; i++) {
        if (blk >= d.s[i].row_end) { seg = i + 1; row_start = d.s[i].row_end; }
    }
    int r = blk - row_start;
    int rowlen = d.s[seg].rowlen;
    const float* s = d.s[seg].src + (long long)r * rowlen;
    float acc = 0.f;
    for (int i = threadIdx.x; i < rowlen; i += blockDim.x) { float v = s[i]; acc = fmaf(v, v, acc); }
#pragma unroll
    for (int off = 16; off; off >>= 1) acc += __shfl_down_sync(0xffffffffu, acc, off);
    __shared__ float sm[8];
    int warp = threadIdx.x >> 5, lane = threadIdx.x & 31;
    if (lane == 0) sm[warp] = acc;
    __syncthreads();
    if (threadIdx.x == 0) {
        float t = 0.f;
        int nw = blockDim.x >> 5;
        for (int i = 0; i < nw; i++) t += sm[i];
        sm[0] = rsqrtf(t + 1e-8f);
    }
    __syncthreads();
    float iv = sm[0];
    if (d.s[seg].dstf) {
        float* dst = d.s[seg].dstf + (long long)r * rowlen;
        for (int i = threadIdx.x; i < rowlen; i += blockDim.x) dst[i] = s[i] * iv;
    } else {
        bf16* h = d.s[seg].dsth + (long long)r * rowlen;
        bf16* l = d.s[seg].dstl + (long long)r * rowlen;
        for (int i = threadIdx.x; i < rowlen; i += blockDim.x) {
            float v = s[i] * iv;
            bf16 hi = __float2bfloat16(v);
            h[i] = hi;
            l[i] = __float2bfloat16(v - __bfloat162float(hi));
        }
    }
}

/* -------- proj pixel norm (closed form); bf16 silu planes only ---------- */
__global__ void proj_pixelnorm(const float* __restrict__ audio, const float* __restrict__ pw,
                               const float* __restrict__ pb,
                               bf16* __restrict__ xh, bf16* __restrict__ xl) {
    long long p = (long long)blockIdx.x * blockDim.x + threadIdx.x;
    if (p >= 524288LL) return;
    float pm0 = 0.f, pm1 = 0.f, pm2 = 0.f;
#pragma unroll
    for (int i = 0; i < 64; i++) {
        float w = pw[i], bb = pb[i];
        pm0 = fmaf(w, w, pm0); pm1 = fmaf(w, bb, pm1); pm2 = fmaf(bb, bb, pm2);
    }
    pm0 *= (1.f / 64.f); pm1 *= (1.f / 64.f); pm2 *= (1.f / 64.f);
    float A = audio[p];
    float ms = fmaf(A * A, pm0, fmaf(2.f * A, pm1, pm2));
    float iv = rsqrtf(ms + EPSN);
    long long b = p >> 18;
    long long rem = p & 262143LL;
    long long base = b * 64LL * 262144LL + rem;
#pragma unroll
    for (int c = 0; c < 64; c++) {
        float v = fmaf(A, pw[c], pb[c]) * iv;
        st_split(xh, xl, base + (long long)c * 262144LL, mp_siluf(v));
    }
}

/* ---------------- generic pixel norm ------------------------------------ */
template <bool SILU>
__global__ void pixelnorm(const float* __restrict__ x, float* __restrict__ xn,
                          bf16* __restrict__ xh, bf16* __restrict__ xl,
                          int C, long long P, long long BP) {
    long long p = (long long)blockIdx.x * blockDim.x + threadIdx.x;
    if (p >= BP) return;
    long long b = p / P, pp = p % P;
    const float* xi = x + b * (long long)C * P + pp;
    float s = 0.f;
#pragma unroll 8
    for (int c = 0; c < C; c++) { float v = xi[(long long)c * P]; s = fmaf(v, v, s); }
    float iv = rsqrtf(s / (float)C + EPSN);
    long long base = b * (long long)C * P + pp;
#pragma unroll 8
    for (int c = 0; c < C; c++) {
        float v = xi[(long long)c * P] * iv;
        long long o = base + (long long)c * P;
        xn[o] = v;
        st_split(xh, xl, o, SILU ? mp_siluf(v) : v);
    }
}

/* -------- unified split-bf16 tensor GEMM, X in natural [K][P] ----------- */
/* Y[b][M][P] = W[M][K] @ X[b][K][P].  RES: 0 none, 1 mp_add with R,       */
/* 2 mp_add with residual recomputed from audio/pw/pb (block-0 c0w2).      */
template <int BM, int RES>
__global__ void __launch_bounds__(256, 2) cgemm(
    const bf16* __restrict__ Wh, const bf16* __restrict__ Wl,
    const bf16* __restrict__ Xh, const bf16* __restrict__ Xl,
    float* __restrict__ Y, const float* __restrict__ R,
    const float* __restrict__ AU, const float* __restrict__ PW2,
    const float* __restrict__ PB2,
    int M, int K, long long P)
{
    constexpr int WPM = BM / 32;
    constexpr int WPP = 8 / WPM;
    constexpr int PW  = 128 / WPP;
    constexpr int NT  = PW / 8;
    constexpr int ASZ = BM * 64;
    constexpr int STG = 2 * ASZ + 16384;

    extern __shared__ __align__(128) char smraw[];
    const uint32_t smb = smem_u32(smraw);
    const int tid = threadIdx.x;
    const long long p0 = (long long)blockIdx.x * 128;
    const int m0 = blockIdx.y * BM;
    const int b = blockIdx.z;
    const int ntk = K >> 5;
    const int wid = tid >> 5, lane = tid & 31;
    const int wm = wid % WPM, wp = wid / WPM;

    auto load_stage = [&](int kt, int s) {
        uint32_t base = smb + s * STG;
#pragma unroll
        for (int g = 0; g < BM / 64; g++) {
            int r = (tid >> 2) + g * 64;
            int c = tid & 3;
            uint32_t off = (uint32_t)(r * 64 + ((c ^ ((r >> 1) & 3)) << 4));
            const bf16* wh = Wh + (long long)(m0 + r) * K + kt * 32 + c * 8;
            const bf16* wl = Wl + (long long)(m0 + r) * K + kt * 32 + c * 8;
            cpa16s(base + off, wh);
            cpa16s(base + ASZ + off, wl);
        }
        {
            int r = tid >> 3;
            int cx = tid & 7;
#pragma unroll
            for (int gg = 0; gg < 2; gg++) {
                int c = cx + gg * 8;
                uint32_t off = (uint32_t)(r * 256 + ((c ^ (r & 7)) << 4));
                long long src = ((long long)b * K + kt * 32 + r) * P + p0 + c * 8;
                cpa16s(base + 2 * ASZ + off, Xh + src);
                cpa16s(base + 2 * ASZ + 8192 + off, Xl + src);
            }
        }
        asm volatile("cp.async.commit_group;" ::: "memory");
    };

    float acc[2][NT][4];
#pragma unroll
    for (int i = 0; i < 2; i++)
#pragma unroll
        for (int j = 0; j < NT; j++)
#pragma unroll
            for (int k = 0; k < 4; k++) acc[i][j][k] = 0.f;

    load_stage(0, 0);
    load_stage(1, 1);
    for (int kt = 0; kt < ntk; kt++) {
        const int s = kt & 1;
        if (kt + 1 < ntk) asm volatile("cp.async.wait_group 1;" ::: "memory");
        else              asm volatile("cp.async.wait_group 0;" ::: "memory");
        __syncthreads();
        const uint32_t base = smb + s * STG;
#pragma unroll
        for (int ks = 0; ks < 2; ks++) {
            uint32_t bh[NT / 2][4], bl[NT / 2][4];
#pragma unroll
            for (int np = 0; np < NT / 2; np++) {
                int r = ks * 16 + (lane & 15);
                int chunk = wp * (PW / 8) + np * 2 + (lane >> 4);
                uint32_t ad = base + 2 * ASZ +
                              (uint32_t)(r * 256 + ((chunk ^ (r & 7)) << 4));
                ldm_x4t(bh[np], ad);
                ldm_x4t(bl[np], ad + 8192);
            }
#pragma unroll
            for (int mt = 0; mt < 2; mt++) {
                int r = wm * 32 + mt * 16 + (lane & 15);
                int chunk = ks * 2 + (lane >> 4);
                uint32_t ad = base + (uint32_t)(r * 64 + ((chunk ^ ((r >> 1) & 3)) << 4));
                uint32_t ah[4], al[4];
                ldm_x4(ah[0], ah[1], ah[2], ah[3], ad);
                ldm_x4(al[0], al[1], al[2], al[3], ad + ASZ);
#pragma unroll
                for (int np = 0; np < NT / 2; np++) {
                    mma16816(acc[mt][np * 2],     ah, bh[np][0], bh[np][1]);
                    mma16816(acc[mt][np * 2],     al, bh[np][0], bh[np][1]);
                    mma16816(acc[mt][np * 2],     ah, bl[np][0], bl[np][1]);
                    mma16816(acc[mt][np * 2 + 1], ah, bh[np][2], bh[np][3]);
                    mma16816(acc[mt][np * 2 + 1], al, bh[np][2], bh[np][3]);
                    mma16816(acc[mt][np * 2 + 1], ah, bl[np][2], bl[np][3]);
                }
            }
        }
        __syncthreads();
        if (kt + 2 < ntk) load_stage(kt + 2, s);
    }

    /* proj moments for RES==2 (tiny, L1-resident) */
    float pm0 = 0.f, pm1 = 0.f, pm2 = 0.f;
    if (RES == 2) {
#pragma unroll
        for (int i = 0; i < 64; i++) {
            float w = PW2[i], bb = PB2[i];
            pm0 = fmaf(w, w, pm0); pm1 = fmaf(w, bb, pm1); pm2 = fmaf(bb, bb, pm2);
        }
        pm0 *= (1.f / 64.f); pm1 *= (1.f / 64.f); pm2 *= (1.f / 64.f);
    }

    const int qrow = lane >> 2;
    const int qcol = (lane & 3) << 1;
#pragma unroll
    for (int mt = 0; mt < 2; mt++) {
#pragma unroll
        for (int nt = 0; nt < NT; nt++) {
            int m = m0 + wm * 32 + mt * 16 + qrow;
            long long p = p0 + wp * PW + nt * 8 + qcol;
            long long o0 = ((long long)b * M + m) * P + p;
            long long o1 = ((long long)b * M + m + 8) * P + p;
            float2 v0 = make_float2(acc[mt][nt][0], acc[mt][nt][1]);
            float2 v1 = make_float2(acc[mt][nt][2], acc[mt][nt][3]);
            if (RES == 1) {
                const float2 r0 = *(const float2*)(R + o0);
                const float2 r1 = *(const float2*)(R + o1);
                v0.x = fmaf(0.7f, r0.x, 0.3f * v0.x) * INV058;
                v0.y = fmaf(0.7f, r0.y, 0.3f * v0.y) * INV058;
                v1.x = fmaf(0.7f, r1.x, 0.3f * v1.x) * INV058;
                v1.y = fmaf(0.7f, r1.y, 0.3f * v1.y) * INV058;
            } else if (RES == 2) {
                float A0 = AU[(long long)b * 262144LL + p];
                float A1 = AU[(long long)b * 262144LL + p + 1];
                float iv0 = rsqrtf(fmaf(A0 * A0, pm0, fmaf(2.f * A0, pm1, pm2)) + EPSN);
                float iv1 = rsqrtf(fmaf(A1 * A1, pm0, fmaf(2.f * A1, pm1, pm2)) + EPSN);
                float w0 = PW2[m], b0v = PB2[m];
                float w1 = PW2[m + 8], b1v = PB2[m + 8];
                float r00 = fmaf(A0, w0, b0v) * iv0, r01 = fmaf(A1, w0, b0v) * iv1;
                float r10 = fmaf(A0, w1, b1v) * iv0, r11 = fmaf(A1, w1, b1v) * iv1;
                v0.x = fmaf(0.7f, r00, 0.3f * v0.x) * INV058;
                v0.y = fmaf(0.7f, r01, 0.3f * v0.y) * INV058;
                v1.x = fmaf(0.7f, r10, 0.3f * v1.x) * INV058;
                v1.y = fmaf(0.7f, r11, 0.3f * v1.y) * INV058;
            }
            *(float2*)(Y + o0) = v0;
            *(float2*)(Y + o1) = v1;
        }
    }
}

/* ------- depthwise 5x3 conv2d (pad 2,1), silu, bf16-split output -------- */
__global__ void dwconv2d_silu(const float* __restrict__ in, const float* __restrict__ w,
                              bf16* __restrict__ oh, bf16* __restrict__ ol,
                              int C, int F, long long total) {
    long long t = (long long)blockIdx.x * blockDim.x + threadIdx.x;
    if (t >= total) return;
    int l0 = (int)(t & 511) << 2;
    long long r = t >> 9;
    int f = (int)(r % F); r /= F;
    int c = (int)(r % C);
    int b = (int)(r / C);
    const float* base = in + ((long long)(b * C + c)) * F * 2048LL;
    const float* wc = w + c * 15;
    float a0 = 0.f, a1 = 0.f, a2 = 0.f, a3 = 0.f;
#pragma unroll
    for (int df = 0; df < 5; df++) {
        int ff = f + df - 2;
        if (ff < 0 || ff >= F) continue;
        const float* row = base + (long long)ff * 2048;
        float v[6];
#pragma unroll
        for (int j = 0; j < 6; j++) {
            int ll = l0 + j - 1;
            v[j] = (ll >= 0 && ll < 2048) ? row[ll] : 0.f;
        }
#pragma unroll
        for (int dl = 0; dl < 3; dl++) {
            float wv = wc[df * 3 + dl];
            a0 = fmaf(wv, v[dl + 0], a0);
            a1 = fmaf(wv, v[dl + 1], a1);
            a2 = fmaf(wv, v[dl + 2], a2);
            a3 = fmaf(wv, v[dl + 3], a3);
        }
    }
    long long o = (((long long)(b * C + c)) * F + f) * 2048LL + l0;
    st_split(oh, ol, o + 0, mp_siluf(a0));
    st_split(oh, ol, o + 1, mp_siluf(a1));
    st_split(oh, ol, o + 2, mp_siluf(a2));
    st_split(oh, ol, o + 3, mp_siluf(a3));
}

/* ---------------- freq average pool, bf16-split output ------------------ */
__global__ void avgpool_f(const float* __restrict__ in, bf16* __restrict__ oh,
                          bf16* __restrict__ ol,
                          int C, int F, int Fo, int s, long long total) {
    long long t = (long long)blockIdx.x * blockDim.x + threadIdx.x;
    if (t >= total) return;
    int l = (int)(t & 2047);
    long long r = t >> 11;
    int fo = (int)(r % Fo); r /= Fo;
    int c = (int)(r % C);
    int b = (int)(r / C);
    const float* p = in + (((long long)(b * C + c)) * F + fo * s) * 2048LL + l;
    float sum = 0.f;
    for (int j = 0; j < s; j++) sum += p[(long long)j * 2048];
    st_split(oh, ol, t, sum * (1.f / (float)s));
}

/* --------- seq: silu -> depthwise k3 -> silu, bf16-split output --------- */
__global__ void dwconv1d_silu(const float* __restrict__ hg, const float* __restrict__ w,
                              bf16* __restrict__ oh, bf16* __restrict__ ol) {
    long long t = (long long)blockIdx.x * blockDim.x + threadIdx.x;
    if (t >= 1048576LL) return;
    int l0 = (int)(t & 511) << 2;
    int c = (int)((t >> 9) & 1023);
    int b = (int)(t >> 19);
    const float* row = hg + ((long long)b * 2048 + c) * 2048LL;
    const float* wc = w + c * 3;
    float v[6];
#pragma unroll
    for (int j = 0; j < 6; j++) {
        int ll = l0 + j - 1;
        v[j] = (ll >= 0 && ll < 2048) ? mp_siluf(row[ll]) : 0.f;
    }
    float a0 = 0.f, a1 = 0.f, a2 = 0.f, a3 = 0.f;
#pragma unroll
    for (int dl = 0; dl < 3; dl++) {
        float wv = wc[dl];
        a0 = fmaf(wv, v[dl + 0], a0);
        a1 = fmaf(wv, v[dl + 1], a1);
        a2 = fmaf(wv, v[dl + 2], a2);
        a3 = fmaf(wv, v[dl + 3], a3);
    }
    long long o = ((long long)b * 1024 + c) * 2048LL + l0;
    st_split(oh, ol, o + 0, mp_siluf(a0));
    st_split(oh, ol, o + 1, mp_siluf(a1));
    st_split(oh, ol, o + 2, mp_siluf(a2));
    st_split(oh, ol, o + 3, mp_siluf(a3));
}

/* --------- minGRU warp scan + output gate, bf16-split output ------------ */
__global__ void gru_scan(const float* __restrict__ u, const float* __restrict__ hg,
                         bf16* __restrict__ oh, bf16* __restrict__ ol) {
    int w = (int)((blockIdx.x * blockDim.x + threadIdx.x) >> 5);
    int lane = threadIdx.x & 31;
    if (w >= 2048) return;
    int bt = w >> 10, c = w & 1023;
    const float* zrow = u + ((long long)bt * 2048 + c) * 2048LL;
    const float* crow = zrow + 1024LL * 2048LL;
    const float* grow = hg + ((long long)bt * 2048 + 1024 + c) * 2048LL;
    long long obase = ((long long)bt * 1024 + c) * 2048LL;
    float carry = 0.f;
    for (int l0 = 0; l0 < 2048; l0 += 32) {
        float z = sigmoidf_fast(zrow[l0 + lane]);
        float a = 1.f - z;
        float bb = z * crow[l0 + lane];
#pragma unroll
        for (int off = 1; off < 32; off <<= 1) {
            float ap = __shfl_up_sync(0xffffffffu, a, off);
            float bp = __shfl_up_sync(0xffffffffu, bb, off);
            if (lane >= off) { bb = fmaf(a, bp, bb); a *= ap; }
        }
        float ov = fmaf(a, carry, bb);
        carry = __shfl_sync(0xffffffffu, ov, 31);
        st_split(oh, ol, obase + l0 + lane, ov * mp_siluf(grow[l0 + lane]));
    }
}

/* ---------------- final activation -------------------------------------- */
__global__ void silu_out(const float* __restrict__ in, float* __restrict__ out, long long n) {
    long long i = (long long)blockIdx.x * blockDim.x + threadIdx.x;
    if (i < n) out[i] = mp_siluf(in[i]);
}

/* ======================================================================== */
extern "C" void kernel_launch(void* const* d_in, const int* in_sizes, int n_in,
                              void* d_out, int out_size) {
    const float* audio = (const float*)d_in[0];
    const float* pw    = (const float*)d_in[1];
    const float* pb    = (const float*)d_in[2];
    const float* c0w1  = (const float*)d_in[3];
    const float* c0wd  = (const float*)d_in[4];
    const float* c0w2  = (const float*)d_in[5];
    const float* c0dn  = (const float*)d_in[6];
    const float* c1w1  = (const float*)d_in[7];
    const float* c1wd  = (const float*)d_in[8];
    const float* c1w2  = (const float*)d_in[9];
    const float* c1dn  = (const float*)d_in[10];
    const float* c2w1  = (const float*)d_in[11];
    const float* c2wd  = (const float*)d_in[12];
    const float* c2w2  = (const float*)d_in[13];
    const float* c2dn  = (const float*)d_in[14];
    const float* hgw   = (const float*)d_in[15];
    const float* dww   = (const float*)d_in[16];
    const float* gruw  = (const float*)d_in[17];
    const float* outw  = (const float*)d_in[18];

    float *wp, *xn, *xsf, *bufA, *bufBf, *hb, *poolf, *xb;
    bf16 *wbf, *cw;
    cudaGetSymbolAddress((void**)&wp,    g_wpool);
    cudaGetSymbolAddress((void**)&xn,    g_xn);
    cudaGetSymbolAddress((void**)&xsf,   g_xs);
    cudaGetSymbolAddress((void**)&bufA,  g_bufA);
    cudaGetSymbolAddress((void**)&bufBf, g_bufB);
    cudaGetSymbolAddress((void**)&hb,    g_h);
    cudaGetSymbolAddress((void**)&poolf, g_pool);
    cudaGetSymbolAddress((void**)&xb,    g_x);
    cudaGetSymbolAddress((void**)&wbf,   g_wbf);
    cudaGetSymbolAddress((void**)&cw,    g_cwbf);

    bf16* xs   = (bf16*)xsf;
    bf16* bufB = (bf16*)bufBf;
    bf16* pool = (bf16*)poolf;
    const float* NUL = (const float*)0;

    cudaFuncSetAttribute(cgemm<128, 0>, cudaFuncAttributeMaxDynamicSharedMemorySize, 65536);
    cudaFuncSetAttribute(cgemm<128, 1>, cudaFuncAttributeMaxDynamicSharedMemorySize, 65536);
    cudaFuncSetAttribute(cgemm<64, 2>,  cudaFuncAttributeMaxDynamicSharedMemorySize, 49152);

    /* fused weight normalization + bf16 split: one launch for all 16 */
    NormDescs nd;
    {
        const float* srcs[16] = {c0w1, c0wd, c0w2, c0dn, c1w1, c1wd, c1w2, c1dn,
                                 c2w1, c2wd, c2w2, c2dn, hgw, dww, gruw, outw};
        int rows[16]   = {128, 128, 64, 128, 256, 256, 128, 256, 512, 512, 256, 512,
                          8192, 4096, 8192, 2048};
        int rowlen[16] = {64, 15, 128, 64, 128, 15, 256, 128, 256, 15, 512, 256,
                          512, 3, 1024, 1024};
        float* dstf[16] = {0, wp + O_C0WD, 0, 0, 0, wp + O_C1WD, 0, 0,
                           0, wp + O_C2WD, 0, 0, 0, wp + O_DW, 0, 0};
        int hofs[16] = {CWH_C0W1, -1, CWH_C0W2, CWH_C0DN, CWH_C1W1, -1, CWH_C1W2,
                        CWH_C1DN, CWH_C2W1, -1, CWH_C2W2, CWH_C2DN, -1, -1, -1, -1};
        int acc = 0;
        for (int i = 0; i < 16; i++) {
            acc += rows[i];
            nd.s[i].src = srcs[i];
            nd.s[i].dstf = dstf[i];
            nd.s[i].rowlen = rowlen[i];
            nd.s[i].row_end = acc;
            if (dstf[i]) { nd.s[i].dsth = 0; nd.s[i].dstl = 0; }
            else if (hofs[i] >= 0) { nd.s[i].dsth = cw + hofs[i]; nd.s[i].dstl = cw + hofs[i] + CWLO; }
        }
        /* seq bf16 dests */
        nd.s[12].dsth = wbf + WH_HG(0);  nd.s[12].dstl = wbf + WH_HG(0) + WLO;
        nd.s[14].dsth = wbf + WH_GRU(0); nd.s[14].dstl = wbf + WH_GRU(0) + WLO;
        nd.s[15].dsth = wbf + WH_OUT(0); nd.s[15].dstl = wbf + WH_OUT(0) + WLO;
        norm_rows_multi<<<acc, 128>>>(nd);
    }

    /* block 0  (C 64->128->64->pool4->128, F=128, P=262144) */
    proj_pixelnorm<<<2048, 256>>>(audio, pw, pb, xs, xs + XS_LO);
    cgemm<128, 0><<<dim3(2048, 1, 2), 256, 65536>>>(cw + CWH_C0W1, cw + CWH_C0W1 + CWLO,
        xs, xs + XS_LO, bufA, NUL, NUL, NUL, NUL, 128, 64, 262144LL);
    dwconv2d_silu<<<65536, 256>>>(bufA, wp + O_C0WD, bufB, bufB + BUFB_LO, 128, 128, 16777216LL);
    cgemm<64, 2><<<dim3(2048, 1, 2), 256, 49152>>>(cw + CWH_C0W2, cw + CWH_C0W2 + CWLO,
        bufB, bufB + BUFB_LO, hb, NUL, audio, pw, pb, 64, 128, 262144LL);
    avgpool_f<<<32768, 256>>>(hb, pool, pool + POOL_LO, 64, 128, 32, 4, 8388608LL);
    cgemm<128, 0><<<dim3(512, 1, 2), 256, 65536>>>(cw + CWH_C0DN, cw + CWH_C0DN + CWLO,
        pool, pool + POOL_LO, xb, NUL, NUL, NUL, NUL, 128, 64, 65536LL);

    /* block 1  (C 128->256->128->pool4->256, F=32, P=65536) */
    pixelnorm<true><<<512, 256>>>(xb, xn, xs, xs + XS_LO, 128, 65536LL, 131072LL);
    cgemm<128, 0><<<dim3(512, 2, 2), 256, 65536>>>(cw + CWH_C1W1, cw + CWH_C1W1 + CWLO,
        xs, xs + XS_LO, bufA, NUL, NUL, NUL, NUL, 256, 128, 65536LL);
    dwconv2d_silu<<<32768, 256>>>(bufA, wp + O_C1WD, bufB, bufB + BUFB_LO, 256, 32, 8388608LL);
    cgemm<128, 1><<<dim3(512, 1, 2), 256, 65536>>>(cw + CWH_C1W2, cw + CWH_C1W2 + CWLO,
        bufB, bufB + BUFB_LO, hb, xn, NUL, NUL, NUL, 128, 256, 65536LL);
    avgpool_f<<<16384, 256>>>(hb, pool, pool + POOL_LO, 128, 32, 8, 4, 4194304LL);
    cgemm<128, 0><<<dim3(128, 2, 2), 256, 65536>>>(cw + CWH_C1DN, cw + CWH_C1DN + CWLO,
        pool, pool + POOL_LO, xb, NUL, NUL, NUL, NUL, 256, 128, 16384LL);

    /* block 2  (C 256->512->256->pool8->512, F=8, P=16384) */
    pixelnorm<true><<<128, 256>>>(xb, xn, xs, xs + XS_LO, 256, 16384LL, 32768LL);
    cgemm<128, 0><<<dim3(128, 4, 2), 256, 65536>>>(cw + CWH_C2W1, cw + CWH_C2W1 + CWLO,
        xs, xs + XS_LO, bufA, NUL, NUL, NUL, NUL, 512, 256, 16384LL);
    dwconv2d_silu<<<16384, 256>>>(bufA, wp + O_C2WD, bufB, bufB + BUFB_LO, 512, 8, 4194304LL);
    cgemm<128, 1><<<dim3(128, 2, 2), 256, 65536>>>(cw + CWH_C2W2, cw + CWH_C2W2 + CWLO,
        bufB, bufB + BUFB_LO, hb, xn, NUL, NUL, NUL, 256, 512, 16384LL);
    avgpool_f<<<4096, 256>>>(hb, pool, pool + POOL_LO, 256, 8, 1, 8, 1048576LL);
    cgemm<128, 0><<<dim3(16, 4, 2), 256, 65536>>>(cw + CWH_C2DN, cw + CWH_C2DN + CWLO,
        pool, pool + POOL_LO, xb, NUL, NUL, NUL, NUL, 512, 256, 2048LL);

    /* seq blocks ×4  (C=512, L=2048) */
    for (int i = 0; i < 4; i++) {
        pixelnorm<false><<<128, 32>>>(xb, xn, xs, xs + XS_LO, 512, 2048LL, 4096LL);
        cgemm<128, 0><<<dim3(16, 16, 2), 256, 65536>>>(
            wbf + WH_HG(i), wbf + WH_HG(i) + WLO, xs, xs + XS_LO,
            bufA, NUL, NUL, NUL, NUL, 2048, 512, 2048LL);
        dwconv1d_silu<<<4096, 256>>>(bufA, wp + O_DW + i * 3072, bufB, bufB + BUFB_LO);
        cgemm<128, 0><<<dim3(16, 16, 2), 256, 65536>>>(
            wbf + WH_GRU(i), wbf + WH_GRU(i) + WLO, bufB, bufB + BUFB_LO,
            hb, NUL, NUL, NUL, NUL, 2048, 1024, 2048LL);
        gru_scan<<<256, 256>>>(hb, bufA, pool, pool + POOL_LO);
        cgemm<128, 1><<<dim3(16, 4, 2), 256, 65536>>>(
            wbf + WH_OUT(i), wbf + WH_OUT(i) + WLO, pool, pool + POOL_LO,
            xb, xn, NUL, NUL, NUL, 512, 1024, 2048LL);
    }

    silu_out<<<8192, 256>>>(xb, (float*)d_out, 2097152LL);
}

// round 13
// speedup vs baseline: 3.0928x; 1.0787x over previous
#include <cuda_runtime.h>
#include <cuda_bf16.h>
#include <cstdint>

#define GAIN   1.6778523489932886f   /* 1/0.596 */
#define INV058 1.3130643285972254f   /* 1/sqrt(0.7^2+0.3^2) */
#define EPSN   1e-4f

typedef unsigned long long ull;
typedef __nv_bfloat16 bf16;

/* ---------------- static device scratch (no allocations allowed) -------- */
__device__ __align__(16) float g_wpool[15230976];
__device__ __align__(16) float g_xn[33554432];
__device__ __align__(16) float g_xs[33554432];    /* bf16 planes: hi | lo   */
__device__ __align__(16) float g_bufA[67108864];
__device__ __align__(16) float g_bufB[67108864];  /* bf16 planes            */
__device__ __align__(16) float g_h[33554432];
__device__ __align__(16) float g_pool[8388608];   /* bf16 planes            */
__device__ __align__(16) float g_x[16777216];
__device__ __align__(16) bf16 g_wbf[29360128];    /* seq weights: hi | lo   */
__device__ __align__(16) bf16 g_cwbf[1048576];    /* conv weights: hi | lo  */

#define XS_LO   33554432
#define BUFB_LO 67108864
#define POOL_LO 8388608

/* fp32 weight pool offsets (depthwise weights only) */
#define O_C0WD 8192
#define O_C1WD 59264
#define O_C2WD 259712
#define O_DW   4723840

/* bf16 conv-weight hi offsets in g_cwbf; lo at +CWLO */
#define CWLO 516096
#define CWH_C0W1 0
#define CWH_C0W2 8192
#define CWH_C0DN 16384
#define CWH_C1W1 24576
#define CWH_C1W2 57344
#define CWH_C1DN 90112
#define CWH_C2W1 122880
#define CWH_C2W2 253952
#define CWH_C2DN 385024

/* bf16 seq-weight hi offsets in g_wbf; lo at +WLO */
#define WLO 14680064
#define WH_HG(i)  ((i) * 1048576)
#define WH_GRU(i) (4194304 + (i) * 2097152)
#define WH_OUT(i) (12582912 + (i) * 524288)

__device__ __forceinline__ float sigmoidf_fast(float x) {
    return __fdividef(1.f, 1.f + __expf(-x));
}
__device__ __forceinline__ float mp_siluf(float x) {
    return x * sigmoidf_fast(x) * GAIN;
}
__device__ __forceinline__ void st_split(bf16* h, bf16* l, long long i, float v) {
    bf16 hi = __float2bfloat16(v);
    h[i] = hi;
    l[i] = __float2bfloat16(v - __bfloat162float(hi));
}
/* 4 consecutive values -> one 8B store per plane (i must be 4-aligned) */
__device__ __forceinline__ void st_split4(bf16* h, bf16* l, long long i,
                                          float a0, float a1, float a2, float a3) {
    union { bf16 b[4]; uint2 u; } H, L;
    H.b[0] = __float2bfloat16(a0); H.b[1] = __float2bfloat16(a1);
    H.b[2] = __float2bfloat16(a2); H.b[3] = __float2bfloat16(a3);
    L.b[0] = __float2bfloat16(a0 - __bfloat162float(H.b[0]));
    L.b[1] = __float2bfloat16(a1 - __bfloat162float(H.b[1]));
    L.b[2] = __float2bfloat16(a2 - __bfloat162float(H.b[2]));
    L.b[3] = __float2bfloat16(a3 - __bfloat162float(H.b[3]));
    *(uint2*)(h + i) = H.u;
    *(uint2*)(l + i) = L.u;
}
__device__ __forceinline__ void cpa16s(uint32_t saddr, const void* g) {
    asm volatile("cp.async.cg.shared.global [%0], [%1], 16;" :: "r"(saddr), "l"(g) : "memory");
}
__device__ __forceinline__ uint32_t smem_u32(const void* p) {
    uint32_t a;
    asm("{ .reg .u64 t; cvta.to.shared.u64 t, %1; cvt.u32.u64 %0, t; }" : "=r"(a) : "l"(p));
    return a;
}

/* ---------------- warp-MMA helpers (baseline PTX, sm_80+) --------------- */
__device__ __forceinline__ void ldm_x4(uint32_t& a0, uint32_t& a1, uint32_t& a2,
                                       uint32_t& a3, uint32_t addr) {
    asm volatile("ldmatrix.sync.aligned.m8n8.x4.shared.b16 {%0,%1,%2,%3}, [%4];"
                 : "=r"(a0), "=r"(a1), "=r"(a2), "=r"(a3) : "r"(addr));
}
__device__ __forceinline__ void ldm_x4t(uint32_t* r, uint32_t addr) {
    asm volatile("ldmatrix.sync.aligned.m8n8.x4.trans.shared.b16 {%0,%1,%2,%3}, [%4];"
                 : "=r"(r[0]), "=r"(r[1]), "=r"(r[2]), "=r"(r[3]) : "r"(addr));
}
__device__ __forceinline__ void mma16816(float* d, const uint32_t* a, uint32_t b0, uint32_t b1) {
    asm volatile("mma.sync.aligned.m16n8k16.row.col.f32.bf16.bf16.f32 "
                 "{%0,%1,%2,%3}, {%4,%5,%6,%7}, {%8,%9}, {%0,%1,%2,%3};"
                 : "+f"(d[0]), "+f"(d[1]), "+f"(d[2]), "+f"(d[3])
                 : "r"(a[0]), "r"(a[1]), "r"(a[2]), "r"(a[3]), "r"(b0), "r"(b1));
}

/* -------- fused weight normalization + bf16 split (segmented) ----------- */
struct NormSeg { const float* src; float* dstf; bf16* dsth; bf16* dstl;
                 int rowlen; int row_end; };
struct NormDescs { NormSeg s[16]; };

__global__ void norm_rows_multi(NormDescs d) {
    int blk = blockIdx.x;
    int seg = 0, row_start = 0;
#pragma unroll
    for (int i = 0; i < 16; i++) {
        if (blk >= d.s[i].row_end) { seg = i + 1; row_start = d.s[i].row_end; }
    }
    int r = blk - row_start;
    int rowlen = d.s[seg].rowlen;
    const float* s = d.s[seg].src + (long long)r * rowlen;
    float acc = 0.f;
    for (int i = threadIdx.x; i < rowlen; i += blockDim.x) { float v = s[i]; acc = fmaf(v, v, acc); }
#pragma unroll
    for (int off = 16; off; off >>= 1) acc += __shfl_down_sync(0xffffffffu, acc, off);
    __shared__ float sm[8];
    int warp = threadIdx.x >> 5, lane = threadIdx.x & 31;
    if (lane == 0) sm[warp] = acc;
    __syncthreads();
    if (threadIdx.x == 0) {
        float t = 0.f;
        int nw = blockDim.x >> 5;
        for (int i = 0; i < nw; i++) t += sm[i];
        sm[0] = rsqrtf(t + 1e-8f);
    }
    __syncthreads();
    float iv = sm[0];
    if (d.s[seg].dstf) {
        float* dst = d.s[seg].dstf + (long long)r * rowlen;
        for (int i = threadIdx.x; i < rowlen; i += blockDim.x) dst[i] = s[i] * iv;
    } else {
        bf16* h = d.s[seg].dsth + (long long)r * rowlen;
        bf16* l = d.s[seg].dstl + (long long)r * rowlen;
        for (int i = threadIdx.x; i < rowlen; i += blockDim.x) {
            float v = s[i] * iv;
            bf16 hi = __float2bfloat16(v);
            h[i] = hi;
            l[i] = __float2bfloat16(v - __bfloat162float(hi));
        }
    }
}

/* -------- proj pixel norm, 4 positions/thread, packed stores ------------ */
__global__ void proj_pixelnorm(const float* __restrict__ audio, const float* __restrict__ pw,
                               const float* __restrict__ pb,
                               bf16* __restrict__ xh, bf16* __restrict__ xl) {
    long long p = ((long long)blockIdx.x * blockDim.x + threadIdx.x) << 2;
    if (p >= 524288LL) return;
    float pm0 = 0.f, pm1 = 0.f, pm2 = 0.f;
#pragma unroll
    for (int i = 0; i < 64; i++) {
        float w = pw[i], bb = pb[i];
        pm0 = fmaf(w, w, pm0); pm1 = fmaf(w, bb, pm1); pm2 = fmaf(bb, bb, pm2);
    }
    pm0 *= (1.f / 64.f); pm1 *= (1.f / 64.f); pm2 *= (1.f / 64.f);
    float4 A = *(const float4*)(audio + p);
    float iv0 = rsqrtf(fmaf(A.x * A.x, pm0, fmaf(2.f * A.x, pm1, pm2)) + EPSN);
    float iv1 = rsqrtf(fmaf(A.y * A.y, pm0, fmaf(2.f * A.y, pm1, pm2)) + EPSN);
    float iv2 = rsqrtf(fmaf(A.z * A.z, pm0, fmaf(2.f * A.z, pm1, pm2)) + EPSN);
    float iv3 = rsqrtf(fmaf(A.w * A.w, pm0, fmaf(2.f * A.w, pm1, pm2)) + EPSN);
    long long b = p >> 18;
    long long rem = p & 262143LL;
    long long base = b * 64LL * 262144LL + rem;
#pragma unroll
    for (int c = 0; c < 64; c++) {
        float w = pw[c], bb = pb[c];
        st_split4(xh, xl, base + (long long)c * 262144LL,
                  mp_siluf(fmaf(A.x, w, bb) * iv0), mp_siluf(fmaf(A.y, w, bb) * iv1),
                  mp_siluf(fmaf(A.z, w, bb) * iv2), mp_siluf(fmaf(A.w, w, bb) * iv3));
    }
}

/* -------- pixel norm, 4 positions/thread (conv blocks) ------------------ */
template <bool SILU>
__global__ void pixelnorm4(const float* __restrict__ x, float* __restrict__ xn,
                           bf16* __restrict__ xh, bf16* __restrict__ xl,
                           int C, long long P, long long BP) {
    long long p = ((long long)blockIdx.x * blockDim.x + threadIdx.x) << 2;
    if (p >= BP) return;
    long long b = p / P, pp = p % P;
    const float* xi = x + b * (long long)C * P + pp;
    float s0 = 0.f, s1 = 0.f, s2 = 0.f, s3 = 0.f;
#pragma unroll 4
    for (int c = 0; c < C; c++) {
        float4 v = *(const float4*)(xi + (long long)c * P);
        s0 = fmaf(v.x, v.x, s0); s1 = fmaf(v.y, v.y, s1);
        s2 = fmaf(v.z, v.z, s2); s3 = fmaf(v.w, v.w, s3);
    }
    float ic = 1.f / (float)C;
    float iv0 = rsqrtf(s0 * ic + EPSN), iv1 = rsqrtf(s1 * ic + EPSN);
    float iv2 = rsqrtf(s2 * ic + EPSN), iv3 = rsqrtf(s3 * ic + EPSN);
    long long base = b * (long long)C * P + pp;
#pragma unroll 4
    for (int c = 0; c < C; c++) {
        long long o = base + (long long)c * P;
        float4 v = *(const float4*)(xi + (long long)c * P);
        float n0 = v.x * iv0, n1 = v.y * iv1, n2 = v.z * iv2, n3 = v.w * iv3;
        *(float4*)(xn + o) = make_float4(n0, n1, n2, n3);
        if (SILU) st_split4(xh, xl, o, mp_siluf(n0), mp_siluf(n1), mp_siluf(n2), mp_siluf(n3));
        else      st_split4(xh, xl, o, n0, n1, n2, n3);
    }
}

/* -------- pixel norm scalar (seq blocks, tiny) -------------------------- */
__global__ void pixelnorm_s(const float* __restrict__ x, float* __restrict__ xn,
                            bf16* __restrict__ xh, bf16* __restrict__ xl,
                            int C, long long P, long long BP) {
    long long p = (long long)blockIdx.x * blockDim.x + threadIdx.x;
    if (p >= BP) return;
    long long b = p / P, pp = p % P;
    const float* xi = x + b * (long long)C * P + pp;
    float s = 0.f;
#pragma unroll 8
    for (int c = 0; c < C; c++) { float v = xi[(long long)c * P]; s = fmaf(v, v, s); }
    float iv = rsqrtf(s / (float)C + EPSN);
    long long base = b * (long long)C * P + pp;
#pragma unroll 8
    for (int c = 0; c < C; c++) {
        float v = xi[(long long)c * P] * iv;
        long long o = base + (long long)c * P;
        xn[o] = v;
        st_split(xh, xl, o, v);
    }
}

/* -------- unified split-bf16 tensor GEMM, X in natural [K][P] ----------- */
template <int BM, int RES>
__global__ void __launch_bounds__(256, 2) cgemm(
    const bf16* __restrict__ Wh, const bf16* __restrict__ Wl,
    const bf16* __restrict__ Xh, const bf16* __restrict__ Xl,
    float* __restrict__ Y, const float* __restrict__ R,
    const float* __restrict__ AU, const float* __restrict__ PW2,
    const float* __restrict__ PB2,
    int M, int K, long long P)
{
    constexpr int WPM = BM / 32;
    constexpr int WPP = 8 / WPM;
    constexpr int PW  = 128 / WPP;
    constexpr int NT  = PW / 8;
    constexpr int ASZ = BM * 64;
    constexpr int STG = 2 * ASZ + 16384;

    extern __shared__ __align__(128) char smraw[];
    const uint32_t smb = smem_u32(smraw);
    const int tid = threadIdx.x;
    const long long p0 = (long long)blockIdx.x * 128;
    const int m0 = blockIdx.y * BM;
    const int b = blockIdx.z;
    const int ntk = K >> 5;
    const int wid = tid >> 5, lane = tid & 31;
    const int wm = wid % WPM, wp = wid / WPM;

    auto load_stage = [&](int kt, int s) {
        uint32_t base = smb + s * STG;
#pragma unroll
        for (int g = 0; g < BM / 64; g++) {
            int r = (tid >> 2) + g * 64;
            int c = tid & 3;
            uint32_t off = (uint32_t)(r * 64 + ((c ^ ((r >> 1) & 3)) << 4));
            const bf16* wh = Wh + (long long)(m0 + r) * K + kt * 32 + c * 8;
            const bf16* wl = Wl + (long long)(m0 + r) * K + kt * 32 + c * 8;
            cpa16s(base + off, wh);
            cpa16s(base + ASZ + off, wl);
        }
        {
            int r = tid >> 3;
            int cx = tid & 7;
#pragma unroll
            for (int gg = 0; gg < 2; gg++) {
                int c = cx + gg * 8;
                uint32_t off = (uint32_t)(r * 256 + ((c ^ (r & 7)) << 4));
                long long src = ((long long)b * K + kt * 32 + r) * P + p0 + c * 8;
                cpa16s(base + 2 * ASZ + off, Xh + src);
                cpa16s(base + 2 * ASZ + 8192 + off, Xl + src);
            }
        }
        asm volatile("cp.async.commit_group;" ::: "memory");
    };

    float acc[2][NT][4];
#pragma unroll
    for (int i = 0; i < 2; i++)
#pragma unroll
        for (int j = 0; j < NT; j++)
#pragma unroll
            for (int k = 0; k < 4; k++) acc[i][j][k] = 0.f;

    load_stage(0, 0);
    load_stage(1, 1);
    for (int kt = 0; kt < ntk; kt++) {
        const int s = kt & 1;
        if (kt + 1 < ntk) asm volatile("cp.async.wait_group 1;" ::: "memory");
        else              asm volatile("cp.async.wait_group 0;" ::: "memory");
        __syncthreads();
        const uint32_t base = smb + s * STG;
#pragma unroll
        for (int ks = 0; ks < 2; ks++) {
            uint32_t bh[NT / 2][4], bl[NT / 2][4];
#pragma unroll
            for (int np = 0; np < NT / 2; np++) {
                int r = ks * 16 + (lane & 15);
                int chunk = wp * (PW / 8) + np * 2 + (lane >> 4);
                uint32_t ad = base + 2 * ASZ +
                              (uint32_t)(r * 256 + ((chunk ^ (r & 7)) << 4));
                ldm_x4t(bh[np], ad);
                ldm_x4t(bl[np], ad + 8192);
            }
#pragma unroll
            for (int mt = 0; mt < 2; mt++) {
                int r = wm * 32 + mt * 16 + (lane & 15);
                int chunk = ks * 2 + (lane >> 4);
                uint32_t ad = base + (uint32_t)(r * 64 + ((chunk ^ ((r >> 1) & 3)) << 4));
                uint32_t ah[4], al[4];
                ldm_x4(ah[0], ah[1], ah[2], ah[3], ad);
                ldm_x4(al[0], al[1], al[2], al[3], ad + ASZ);
#pragma unroll
                for (int np = 0; np < NT / 2; np++) {
                    mma16816(acc[mt][np * 2],     ah, bh[np][0], bh[np][1]);
                    mma16816(acc[mt][np * 2],     al, bh[np][0], bh[np][1]);
                    mma16816(acc[mt][np * 2],     ah, bl[np][0], bl[np][1]);
                    mma16816(acc[mt][np * 2 + 1], ah, bh[np][2], bh[np][3]);
                    mma16816(acc[mt][np * 2 + 1], al, bh[np][2], bh[np][3]);
                    mma16816(acc[mt][np * 2 + 1], ah, bl[np][2], bl[np][3]);
                }
            }
        }
        __syncthreads();
        if (kt + 2 < ntk) load_stage(kt + 2, s);
    }

    float pm0 = 0.f, pm1 = 0.f, pm2 = 0.f;
    if (RES == 2) {
#pragma unroll
        for (int i = 0; i < 64; i++) {
            float w = PW2[i], bb = PB2[i];
            pm0 = fmaf(w, w, pm0); pm1 = fmaf(w, bb, pm1); pm2 = fmaf(bb, bb, pm2);
        }
        pm0 *= (1.f / 64.f); pm1 *= (1.f / 64.f); pm2 *= (1.f / 64.f);
    }

    const int qrow = lane >> 2;
    const int qcol = (lane & 3) << 1;
#pragma unroll
    for (int mt = 0; mt < 2; mt++) {
#pragma unroll
        for (int nt = 0; nt < NT; nt++) {
            int m = m0 + wm * 32 + mt * 16 + qrow;
            long long p = p0 + wp * PW + nt * 8 + qcol;
            long long o0 = ((long long)b * M + m) * P + p;
            long long o1 = ((long long)b * M + m + 8) * P + p;
            float2 v0 = make_float2(acc[mt][nt][0], acc[mt][nt][1]);
            float2 v1 = make_float2(acc[mt][nt][2], acc[mt][nt][3]);
            if (RES == 1) {
                const float2 r0 = *(const float2*)(R + o0);
                const float2 r1 = *(const float2*)(R + o1);
                v0.x = fmaf(0.7f, r0.x, 0.3f * v0.x) * INV058;
                v0.y = fmaf(0.7f, r0.y, 0.3f * v0.y) * INV058;
                v1.x = fmaf(0.7f, r1.x, 0.3f * v1.x) * INV058;
                v1.y = fmaf(0.7f, r1.y, 0.3f * v1.y) * INV058;
            } else if (RES == 2) {
                float A0 = AU[(long long)b * 262144LL + p];
                float A1 = AU[(long long)b * 262144LL + p + 1];
                float iv0 = rsqrtf(fmaf(A0 * A0, pm0, fmaf(2.f * A0, pm1, pm2)) + EPSN);
                float iv1 = rsqrtf(fmaf(A1 * A1, pm0, fmaf(2.f * A1, pm1, pm2)) + EPSN);
                float w0 = PW2[m], b0v = PB2[m];
                float w1 = PW2[m + 8], b1v = PB2[m + 8];
                float r00 = fmaf(A0, w0, b0v) * iv0, r01 = fmaf(A1, w0, b0v) * iv1;
                float r10 = fmaf(A0, w1, b1v) * iv0, r11 = fmaf(A1, w1, b1v) * iv1;
                v0.x = fmaf(0.7f, r00, 0.3f * v0.x) * INV058;
                v0.y = fmaf(0.7f, r01, 0.3f * v0.y) * INV058;
                v1.x = fmaf(0.7f, r10, 0.3f * v1.x) * INV058;
                v1.y = fmaf(0.7f, r11, 0.3f * v1.y) * INV058;
            }
            *(float2*)(Y + o0) = v0;
            *(float2*)(Y + o1) = v1;
        }
    }
}

/* ------- depthwise 5x3 conv2d, vector loads + packed stores ------------- */
__global__ void dwconv2d_silu(const float* __restrict__ in, const float* __restrict__ w,
                              bf16* __restrict__ oh, bf16* __restrict__ ol,
                              int C, int F, long long total) {
    long long t = (long long)blockIdx.x * blockDim.x + threadIdx.x;
    if (t >= total) return;
    int l0 = (int)(t & 511) << 2;
    long long r = t >> 9;
    int f = (int)(r % F); r /= F;
    int c = (int)(r % C);
    int b = (int)(r / C);
    const float* base = in + ((long long)(b * C + c)) * F * 2048LL;
    const float* wc = w + c * 15;
    float a0 = 0.f, a1 = 0.f, a2 = 0.f, a3 = 0.f;
#pragma unroll
    for (int df = 0; df < 5; df++) {
        int ff = f + df - 2;
        if (ff < 0 || ff >= F) continue;
        const float* row = base + (long long)ff * 2048;
        float4 mid = *(const float4*)(row + l0);
        float v0 = (l0 > 0) ? row[l0 - 1] : 0.f;
        float v5 = (l0 + 4 < 2048) ? row[l0 + 4] : 0.f;
        float w0 = wc[df * 3 + 0], w1 = wc[df * 3 + 1], w2 = wc[df * 3 + 2];
        a0 = fmaf(w0, v0,    fmaf(w1, mid.x, fmaf(w2, mid.y, a0)));
        a1 = fmaf(w0, mid.x, fmaf(w1, mid.y, fmaf(w2, mid.z, a1)));
        a2 = fmaf(w0, mid.y, fmaf(w1, mid.z, fmaf(w2, mid.w, a2)));
        a3 = fmaf(w0, mid.z, fmaf(w1, mid.w, fmaf(w2, v5,    a3)));
    }
    long long o = (((long long)(b * C + c)) * F + f) * 2048LL + l0;
    st_split4(oh, ol, o, mp_siluf(a0), mp_siluf(a1), mp_siluf(a2), mp_siluf(a3));
}

/* ------- freq average pool, 4 elems/thread, packed stores --------------- */
__global__ void avgpool_f(const float* __restrict__ in, bf16* __restrict__ oh,
                          bf16* __restrict__ ol,
                          int C, int F, int Fo, int s, long long total4) {
    long long t = (long long)blockIdx.x * blockDim.x + threadIdx.x;
    if (t >= total4) return;
    long long e = t << 2;
    int l = (int)(e & 2047);
    long long r = e >> 11;
    int fo = (int)(r % Fo); r /= Fo;
    int c = (int)(r % C);
    int b = (int)(r / C);
    const float* p = in + (((long long)(b * C + c)) * F + fo * s) * 2048LL + l;
    float4 sum = make_float4(0.f, 0.f, 0.f, 0.f);
    for (int j = 0; j < s; j++) {
        float4 v = *(const float4*)(p + (long long)j * 2048);
        sum.x += v.x; sum.y += v.y; sum.z += v.z; sum.w += v.w;
    }
    float is = 1.f / (float)s;
    st_split4(oh, ol, e, sum.x * is, sum.y * is, sum.z * is, sum.w * is);
}

/* ------- seq depthwise k3, vector loads + packed stores ----------------- */
__global__ void dwconv1d_silu(const float* __restrict__ hg, const float* __restrict__ w,
                              bf16* __restrict__ oh, bf16* __restrict__ ol) {
    long long t = (long long)blockIdx.x * blockDim.x + threadIdx.x;
    if (t >= 1048576LL) return;
    int l0 = (int)(t & 511) << 2;
    int c = (int)((t >> 9) & 1023);
    int b = (int)(t >> 19);
    const float* row = hg + ((long long)b * 2048 + c) * 2048LL;
    const float* wc = w + c * 3;
    float4 mid = *(const float4*)(row + l0);
    float v0 = (l0 > 0) ? mp_siluf(row[l0 - 1]) : 0.f;
    float v5 = (l0 + 4 < 2048) ? mp_siluf(row[l0 + 4]) : 0.f;
    float m0 = mp_siluf(mid.x), m1 = mp_siluf(mid.y);
    float m2 = mp_siluf(mid.z), m3 = mp_siluf(mid.w);
    float w0 = wc[0], w1 = wc[1], w2 = wc[2];
    float a0 = fmaf(w0, v0, fmaf(w1, m0, w2 * m1));
    float a1 = fmaf(w0, m0, fmaf(w1, m1, w2 * m2));
    float a2 = fmaf(w0, m1, fmaf(w1, m2, w2 * m3));
    float a3 = fmaf(w0, m2, fmaf(w1, m3, w2 * v5));
    long long o = ((long long)b * 1024 + c) * 2048LL + l0;
    st_split4(oh, ol, o, mp_siluf(a0), mp_siluf(a1), mp_siluf(a2), mp_siluf(a3));
}

/* --------- minGRU warp scan + output gate, bf16-split output ------------ */
__global__ void gru_scan(const float* __restrict__ u, const float* __restrict__ hg,
                         bf16* __restrict__ oh, bf16* __restrict__ ol) {
    int w = (int)((blockIdx.x * blockDim.x + threadIdx.x) >> 5);
    int lane = threadIdx.x & 31;
    if (w >= 2048) return;
    int bt = w >> 10, c = w & 1023;
    const float* zrow = u + ((long long)bt * 2048 + c) * 2048LL;
    const float* crow = zrow + 1024LL * 2048LL;
    const float* grow = hg + ((long long)bt * 2048 + 1024 + c) * 2048LL;
    long long obase = ((long long)bt * 1024 + c) * 2048LL;
    float carry = 0.f;
    for (int l0 = 0; l0 < 2048; l0 += 32) {
        float z = sigmoidf_fast(zrow[l0 + lane]);
        float a = 1.f - z;
        float bb = z * crow[l0 + lane];
#pragma unroll
        for (int off = 1; off < 32; off <<= 1) {
            float ap = __shfl_up_sync(0xffffffffu, a, off);
            float bp = __shfl_up_sync(0xffffffffu, bb, off);
            if (lane >= off) { bb = fmaf(a, bp, bb); a *= ap; }
        }
        float ov = fmaf(a, carry, bb);
        carry = __shfl_sync(0xffffffffu, ov, 31);
        st_split(oh, ol, obase + l0 + lane, ov * mp_siluf(grow[l0 + lane]));
    }
}

/* ---------------- final activation (float4) ----------------------------- */
__global__ void silu_out(const float* __restrict__ in, float* __restrict__ out, long long n4) {
    long long i = (long long)blockIdx.x * blockDim.x + threadIdx.x;
    if (i >= n4) return;
    float4 v = *(const float4*)(in + (i << 2));
    v.x = mp_siluf(v.x); v.y = mp_siluf(v.y);
    v.z = mp_siluf(v.z); v.w = mp_siluf(v.w);
    *(float4*)(out + (i << 2)) = v;
}

/* ======================================================================== */
extern "C" void kernel_launch(void* const* d_in, const int* in_sizes, int n_in,
                              void* d_out, int out_size) {
    const float* audio = (const float*)d_in[0];
    const float* pw    = (const float*)d_in[1];
    const float* pb    = (const float*)d_in[2];
    const float* c0w1  = (const float*)d_in[3];
    const float* c0wd  = (const float*)d_in[4];
    const float* c0w2  = (const float*)d_in[5];
    const float* c0dn  = (const float*)d_in[6];
    const float* c1w1  = (const float*)d_in[7];
    const float* c1wd  = (const float*)d_in[8];
    const float* c1w2  = (const float*)d_in[9];
    const float* c1dn  = (const float*)d_in[10];
    const float* c2w1  = (const float*)d_in[11];
    const float* c2wd  = (const float*)d_in[12];
    const float* c2w2  = (const float*)d_in[13];
    const float* c2dn  = (const float*)d_in[14];
    const float* hgw   = (const float*)d_in[15];
    const float* dww   = (const float*)d_in[16];
    const float* gruw  = (const float*)d_in[17];
    const float* outw  = (const float*)d_in[18];

    float *wp, *xn, *xsf, *bufA, *bufBf, *hb, *poolf, *xb;
    bf16 *wbf, *cw;
    cudaGetSymbolAddress((void**)&wp,    g_wpool);
    cudaGetSymbolAddress((void**)&xn,    g_xn);
    cudaGetSymbolAddress((void**)&xsf,   g_xs);
    cudaGetSymbolAddress((void**)&bufA,  g_bufA);
    cudaGetSymbolAddress((void**)&bufBf, g_bufB);
    cudaGetSymbolAddress((void**)&hb,    g_h);
    cudaGetSymbolAddress((void**)&poolf, g_pool);
    cudaGetSymbolAddress((void**)&xb,    g_x);
    cudaGetSymbolAddress((void**)&wbf,   g_wbf);
    cudaGetSymbolAddress((void**)&cw,    g_cwbf);

    bf16* xs   = (bf16*)xsf;
    bf16* bufB = (bf16*)bufBf;
    bf16* pool = (bf16*)poolf;
    const float* NUL = (const float*)0;

    cudaFuncSetAttribute(cgemm<128, 0>, cudaFuncAttributeMaxDynamicSharedMemorySize, 65536);
    cudaFuncSetAttribute(cgemm<128, 1>, cudaFuncAttributeMaxDynamicSharedMemorySize, 65536);
    cudaFuncSetAttribute(cgemm<64, 2>,  cudaFuncAttributeMaxDynamicSharedMemorySize, 49152);

    /* fused weight normalization + bf16 split: one launch for all 16 */
    NormDescs nd;
    {
        const float* srcs[16] = {c0w1, c0wd, c0w2, c0dn, c1w1, c1wd, c1w2, c1dn,
                                 c2w1, c2wd, c2w2, c2dn, hgw, dww, gruw, outw};
        int rows[16]   = {128, 128, 64, 128, 256, 256, 128, 256, 512, 512, 256, 512,
                          8192, 4096, 8192, 2048};
        int rowlen[16] = {64, 15, 128, 64, 128, 15, 256, 128, 256, 15, 512, 256,
                          512, 3, 1024, 1024};
        float* dstf[16] = {0, wp + O_C0WD, 0, 0, 0, wp + O_C1WD, 0, 0,
                           0, wp + O_C2WD, 0, 0, 0, wp + O_DW, 0, 0};
        int hofs[16] = {CWH_C0W1, -1, CWH_C0W2, CWH_C0DN, CWH_C1W1, -1, CWH_C1W2,
                        CWH_C1DN, CWH_C2W1, -1, CWH_C2W2, CWH_C2DN, -1, -1, -1, -1};
        int acc = 0;
        for (int i = 0; i < 16; i++) {
            acc += rows[i];
            nd.s[i].src = srcs[i];
            nd.s[i].dstf = dstf[i];
            nd.s[i].rowlen = rowlen[i];
            nd.s[i].row_end = acc;
            if (dstf[i]) { nd.s[i].dsth = 0; nd.s[i].dstl = 0; }
            else if (hofs[i] >= 0) { nd.s[i].dsth = cw + hofs[i]; nd.s[i].dstl = cw + hofs[i] + CWLO; }
        }
        nd.s[12].dsth = wbf + WH_HG(0);  nd.s[12].dstl = wbf + WH_HG(0) + WLO;
        nd.s[14].dsth = wbf + WH_GRU(0); nd.s[14].dstl = wbf + WH_GRU(0) + WLO;
        nd.s[15].dsth = wbf + WH_OUT(0); nd.s[15].dstl = wbf + WH_OUT(0) + WLO;
        norm_rows_multi<<<acc, 128>>>(nd);
    }

    /* block 0  (C 64->128->64->pool4->128, F=128, P=262144) */
    proj_pixelnorm<<<512, 256>>>(audio, pw, pb, xs, xs + XS_LO);
    cgemm<128, 0><<<dim3(2048, 1, 2), 256, 65536>>>(cw + CWH_C0W1, cw + CWH_C0W1 + CWLO,
        xs, xs + XS_LO, bufA, NUL, NUL, NUL, NUL, 128, 64, 262144LL);
    dwconv2d_silu<<<65536, 256>>>(bufA, wp + O_C0WD, bufB, bufB + BUFB_LO, 128, 128, 16777216LL);
    cgemm<64, 2><<<dim3(2048, 1, 2), 256, 49152>>>(cw + CWH_C0W2, cw + CWH_C0W2 + CWLO,
        bufB, bufB + BUFB_LO, hb, NUL, audio, pw, pb, 64, 128, 262144LL);
    avgpool_f<<<8192, 256>>>(hb, pool, pool + POOL_LO, 64, 128, 32, 4, 2097152LL);
    cgemm<128, 0><<<dim3(512, 1, 2), 256, 65536>>>(cw + CWH_C0DN, cw + CWH_C0DN + CWLO,
        pool, pool + POOL_LO, xb, NUL, NUL, NUL, NUL, 128, 64, 65536LL);

    /* block 1  (C 128->256->128->pool4->256, F=32, P=65536) */
    pixelnorm4<true><<<128, 256>>>(xb, xn, xs, xs + XS_LO, 128, 65536LL, 131072LL);
    cgemm<128, 0><<<dim3(512, 2, 2), 256, 65536>>>(cw + CWH_C1W1, cw + CWH_C1W1 + CWLO,
        xs, xs + XS_LO, bufA, NUL, NUL, NUL, NUL, 256, 128, 65536LL);
    dwconv2d_silu<<<32768, 256>>>(bufA, wp + O_C1WD, bufB, bufB + BUFB_LO, 256, 32, 8388608LL);
    cgemm<128, 1><<<dim3(512, 1, 2), 256, 65536>>>(cw + CWH_C1W2, cw + CWH_C1W2 + CWLO,
        bufB, bufB + BUFB_LO, hb, xn, NUL, NUL, NUL, 128, 256, 65536LL);
    avgpool_f<<<4096, 256>>>(hb, pool, pool + POOL_LO, 128, 32, 8, 4, 1048576LL);
    cgemm<128, 0><<<dim3(128, 2, 2), 256, 65536>>>(cw + CWH_C1DN, cw + CWH_C1DN + CWLO,
        pool, pool + POOL_LO, xb, NUL, NUL, NUL, NUL, 256, 128, 16384LL);

    /* block 2  (C 256->512->256->pool8->512, F=8, P=16384) */
    pixelnorm4<true><<<32, 256>>>(xb, xn, xs, xs + XS_LO, 256, 16384LL, 32768LL);
    cgemm<128, 0><<<dim3(128, 4, 2), 256, 65536>>>(cw + CWH_C2W1, cw + CWH_C2W1 + CWLO,
        xs, xs + XS_LO, bufA, NUL, NUL, NUL, NUL, 512, 256, 16384LL);
    dwconv2d_silu<<<16384, 256>>>(bufA, wp + O_C2WD, bufB, bufB + BUFB_LO, 512, 8, 4194304LL);
    cgemm<128, 1><<<dim3(128, 2, 2), 256, 65536>>>(cw + CWH_C2W2, cw + CWH_C2W2 + CWLO,
        bufB, bufB + BUFB_LO, hb, xn, NUL, NUL, NUL, 256, 512, 16384LL);
    avgpool_f<<<1024, 256>>>(hb, pool, pool + POOL_LO, 256, 8, 1, 8, 262144LL);
    cgemm<128, 0><<<dim3(16, 4, 2), 256, 65536>>>(cw + CWH_C2DN, cw + CWH_C2DN + CWLO,
        pool, pool + POOL_LO, xb, NUL, NUL, NUL, NUL, 512, 256, 2048LL);

    /* seq blocks ×4  (C=512, L=2048) */
    for (int i = 0; i < 4; i++) {
        pixelnorm_s<<<128, 32>>>(xb, xn, xs, xs + XS_LO, 512, 2048LL, 4096LL);
        cgemm<128, 0><<<dim3(16, 16, 2), 256, 65536>>>(
            wbf + WH_HG(i), wbf + WH_HG(i) + WLO, xs, xs + XS_LO,
            bufA, NUL, NUL, NUL, NUL, 2048, 512, 2048LL);
        dwconv1d_silu<<<4096, 256>>>(bufA, wp + O_DW + i * 3072, bufB, bufB + BUFB_LO);
        cgemm<128, 0><<<dim3(16, 16, 2), 256, 65536>>>(
            wbf + WH_GRU(i), wbf + WH_GRU(i) + WLO, bufB, bufB + BUFB_LO,
            hb, NUL, NUL, NUL, NUL, 2048, 1024, 2048LL);
        gru_scan<<<256, 256>>>(hb, bufA, pool, pool + POOL_LO);
        cgemm<128, 1><<<dim3(16, 4, 2), 256, 65536>>>(
            wbf + WH_OUT(i), wbf + WH_OUT(i) + WLO, pool, pool + POOL_LO,
            xb, xn, NUL, NUL, NUL, 512, 1024, 2048LL);
    }

    silu_out<<<2048, 256>>>(xb, (float*)d_out, 524288LL);
}

// round 14
// speedup vs baseline: 3.2187x; 1.0407x over previous
#include <cuda_runtime.h>
#include <cuda_bf16.h>
#include <cstdint>

#define GAIN   1.6778523489932886f   /* 1/0.596 */
#define INV058 1.3130643285972254f   /* 1/sqrt(0.7^2+0.3^2) */
#define EPSN   1e-4f

typedef unsigned long long ull;
typedef __nv_bfloat16 bf16;

/* ---------------- static device scratch (no allocations allowed) -------- */
__device__ __align__(16) float g_wpool[15230976];
__device__ __align__(16) float g_xn[33554432];
__device__ __align__(16) float g_xs[33554432];    /* bf16 planes: hi | lo   */
__device__ __align__(16) float g_bufA[67108864];
__device__ __align__(16) float g_bufB[67108864];  /* bf16 planes            */
__device__ __align__(16) float g_h[33554432];
__device__ __align__(16) float g_pool[8388608];   /* bf16 planes            */
__device__ __align__(16) float g_x[16777216];
__device__ __align__(16) bf16 g_wbf[29360128];    /* seq weights: hi | lo   */
__device__ __align__(16) bf16 g_cwbf[1048576];    /* conv weights: hi | lo  */

#define XS_LO   33554432
#define BUFB_LO 67108864
#define POOL_LO 8388608

/* fp32 weight pool offsets (depthwise weights only) */
#define O_C0WD 8192
#define O_C1WD 59264
#define O_C2WD 259712
#define O_DW   4723840

/* bf16 conv-weight hi offsets in g_cwbf; lo at +CWLO */
#define CWLO 516096
#define CWH_C0W1 0
#define CWH_C0W2 8192
#define CWH_C0DN 16384
#define CWH_C1W1 24576
#define CWH_C1W2 57344
#define CWH_C1DN 90112
#define CWH_C2W1 122880
#define CWH_C2W2 253952
#define CWH_C2DN 385024

/* bf16 seq-weight hi offsets in g_wbf; lo at +WLO */
#define WLO 14680064
#define WH_HG(i)  ((i) * 1048576)
#define WH_GRU(i) (4194304 + (i) * 2097152)
#define WH_OUT(i) (12582912 + (i) * 524288)

__device__ __forceinline__ float sigmoidf_fast(float x) {
    return __fdividef(1.f, 1.f + __expf(-x));
}
__device__ __forceinline__ float mp_siluf(float x) {
    return x * sigmoidf_fast(x) * GAIN;
}
__device__ __forceinline__ void st_split(bf16* h, bf16* l, long long i, float v) {
    bf16 hi = __float2bfloat16(v);
    h[i] = hi;
    l[i] = __float2bfloat16(v - __bfloat162float(hi));
}
__device__ __forceinline__ void st_split4(bf16* h, bf16* l, long long i,
                                          float a0, float a1, float a2, float a3) {
    union { bf16 b[4]; uint2 u; } H, L;
    H.b[0] = __float2bfloat16(a0); H.b[1] = __float2bfloat16(a1);
    H.b[2] = __float2bfloat16(a2); H.b[3] = __float2bfloat16(a3);
    L.b[0] = __float2bfloat16(a0 - __bfloat162float(H.b[0]));
    L.b[1] = __float2bfloat16(a1 - __bfloat162float(H.b[1]));
    L.b[2] = __float2bfloat16(a2 - __bfloat162float(H.b[2]));
    L.b[3] = __float2bfloat16(a3 - __bfloat162float(H.b[3]));
    *(uint2*)(h + i) = H.u;
    *(uint2*)(l + i) = L.u;
}
__device__ __forceinline__ void cpa16s(uint32_t saddr, const void* g) {
    asm volatile("cp.async.cg.shared.global [%0], [%1], 16;" :: "r"(saddr), "l"(g) : "memory");
}
__device__ __forceinline__ uint32_t smem_u32(const void* p) {
    uint32_t a;
    asm("{ .reg .u64 t; cvta.to.shared.u64 t, %1; cvt.u32.u64 %0, t; }" : "=r"(a) : "l"(p));
    return a;
}

/* ---------------- warp-MMA helpers (baseline PTX, sm_80+) --------------- */
__device__ __forceinline__ void ldm_x4(uint32_t& a0, uint32_t& a1, uint32_t& a2,
                                       uint32_t& a3, uint32_t addr) {
    asm volatile("ldmatrix.sync.aligned.m8n8.x4.shared.b16 {%0,%1,%2,%3}, [%4];"
                 : "=r"(a0), "=r"(a1), "=r"(a2), "=r"(a3) : "r"(addr));
}
__device__ __forceinline__ void ldm_x4t(uint32_t* r, uint32_t addr) {
    asm volatile("ldmatrix.sync.aligned.m8n8.x4.trans.shared.b16 {%0,%1,%2,%3}, [%4];"
                 : "=r"(r[0]), "=r"(r[1]), "=r"(r[2]), "=r"(r[3]) : "r"(addr));
}
__device__ __forceinline__ void mma16816(float* d, const uint32_t* a, uint32_t b0, uint32_t b1) {
    asm volatile("mma.sync.aligned.m16n8k16.row.col.f32.bf16.bf16.f32 "
                 "{%0,%1,%2,%3}, {%4,%5,%6,%7}, {%8,%9}, {%0,%1,%2,%3};"
                 : "+f"(d[0]), "+f"(d[1]), "+f"(d[2]), "+f"(d[3])
                 : "r"(a[0]), "r"(a[1]), "r"(a[2]), "r"(a[3]), "r"(b0), "r"(b1));
}

/* -------- fused weight normalization + bf16 split (segmented) ----------- */
struct NormSeg { const float* src; float* dstf; bf16* dsth; bf16* dstl;
                 int rowlen; int row_end; };
struct NormDescs { NormSeg s[16]; };

__global__ void norm_rows_multi(NormDescs d) {
    int blk = blockIdx.x;
    int seg = 0, row_start = 0;
#pragma unroll
    for (int i = 0; i < 16; i++) {
        if (blk >= d.s[i].row_end) { seg = i + 1; row_start = d.s[i].row_end; }
    }
    int r = blk - row_start;
    int rowlen = d.s[seg].rowlen;
    const float* s = d.s[seg].src + (long long)r * rowlen;
    float acc = 0.f;
    for (int i = threadIdx.x; i < rowlen; i += blockDim.x) { float v = s[i]; acc = fmaf(v, v, acc); }
#pragma unroll
    for (int off = 16; off; off >>= 1) acc += __shfl_down_sync(0xffffffffu, acc, off);
    __shared__ float sm[8];
    int warp = threadIdx.x >> 5, lane = threadIdx.x & 31;
    if (lane == 0) sm[warp] = acc;
    __syncthreads();
    if (threadIdx.x == 0) {
        float t = 0.f;
        int nw = blockDim.x >> 5;
        for (int i = 0; i < nw; i++) t += sm[i];
        sm[0] = rsqrtf(t + 1e-8f);
    }
    __syncthreads();
    float iv = sm[0];
    if (d.s[seg].dstf) {
        float* dst = d.s[seg].dstf + (long long)r * rowlen;
        for (int i = threadIdx.x; i < rowlen; i += blockDim.x) dst[i] = s[i] * iv;
    } else {
        bf16* h = d.s[seg].dsth + (long long)r * rowlen;
        bf16* l = d.s[seg].dstl + (long long)r * rowlen;
        for (int i = threadIdx.x; i < rowlen; i += blockDim.x) {
            float v = s[i] * iv;
            bf16 hi = __float2bfloat16(v);
            h[i] = hi;
            l[i] = __float2bfloat16(v - __bfloat162float(hi));
        }
    }
}

/* -------- proj pixel norm, 4 positions/thread, packed stores ------------ */
__global__ void proj_pixelnorm(const float* __restrict__ audio, const float* __restrict__ pw,
                               const float* __restrict__ pb,
                               bf16* __restrict__ xh, bf16* __restrict__ xl) {
    long long p = ((long long)blockIdx.x * blockDim.x + threadIdx.x) << 2;
    if (p >= 524288LL) return;
    float pm0 = 0.f, pm1 = 0.f, pm2 = 0.f;
#pragma unroll
    for (int i = 0; i < 64; i++) {
        float w = pw[i], bb = pb[i];
        pm0 = fmaf(w, w, pm0); pm1 = fmaf(w, bb, pm1); pm2 = fmaf(bb, bb, pm2);
    }
    pm0 *= (1.f / 64.f); pm1 *= (1.f / 64.f); pm2 *= (1.f / 64.f);
    float4 A = *(const float4*)(audio + p);
    float iv0 = rsqrtf(fmaf(A.x * A.x, pm0, fmaf(2.f * A.x, pm1, pm2)) + EPSN);
    float iv1 = rsqrtf(fmaf(A.y * A.y, pm0, fmaf(2.f * A.y, pm1, pm2)) + EPSN);
    float iv2 = rsqrtf(fmaf(A.z * A.z, pm0, fmaf(2.f * A.z, pm1, pm2)) + EPSN);
    float iv3 = rsqrtf(fmaf(A.w * A.w, pm0, fmaf(2.f * A.w, pm1, pm2)) + EPSN);
    long long b = p >> 18;
    long long rem = p & 262143LL;
    long long base = b * 64LL * 262144LL + rem;
#pragma unroll
    for (int c = 0; c < 64; c++) {
        float w = pw[c], bb = pb[c];
        st_split4(xh, xl, base + (long long)c * 262144LL,
                  mp_siluf(fmaf(A.x, w, bb) * iv0), mp_siluf(fmaf(A.y, w, bb) * iv1),
                  mp_siluf(fmaf(A.z, w, bb) * iv2), mp_siluf(fmaf(A.w, w, bb) * iv3));
    }
}

/* -------- pixel norm, 4 positions/thread (conv blocks) ------------------ */
template <bool SILU>
__global__ void pixelnorm4(const float* __restrict__ x, float* __restrict__ xn,
                           bf16* __restrict__ xh, bf16* __restrict__ xl,
                           int C, long long P, long long BP) {
    long long p = ((long long)blockIdx.x * blockDim.x + threadIdx.x) << 2;
    if (p >= BP) return;
    long long b = p / P, pp = p % P;
    const float* xi = x + b * (long long)C * P + pp;
    float s0 = 0.f, s1 = 0.f, s2 = 0.f, s3 = 0.f;
#pragma unroll 4
    for (int c = 0; c < C; c++) {
        float4 v = *(const float4*)(xi + (long long)c * P);
        s0 = fmaf(v.x, v.x, s0); s1 = fmaf(v.y, v.y, s1);
        s2 = fmaf(v.z, v.z, s2); s3 = fmaf(v.w, v.w, s3);
    }
    float ic = 1.f / (float)C;
    float iv0 = rsqrtf(s0 * ic + EPSN), iv1 = rsqrtf(s1 * ic + EPSN);
    float iv2 = rsqrtf(s2 * ic + EPSN), iv3 = rsqrtf(s3 * ic + EPSN);
    long long base = b * (long long)C * P + pp;
#pragma unroll 4
    for (int c = 0; c < C; c++) {
        long long o = base + (long long)c * P;
        float4 v = *(const float4*)(xi + (long long)c * P);
        float n0 = v.x * iv0, n1 = v.y * iv1, n2 = v.z * iv2, n3 = v.w * iv3;
        *(float4*)(xn + o) = make_float4(n0, n1, n2, n3);
        if (SILU) st_split4(xh, xl, o, mp_siluf(n0), mp_siluf(n1), mp_siluf(n2), mp_siluf(n3));
        else      st_split4(xh, xl, o, n0, n1, n2, n3);
    }
}

/* -------- pixel norm scalar (seq blocks, tiny) -------------------------- */
__global__ void pixelnorm_s(const float* __restrict__ x, float* __restrict__ xn,
                            bf16* __restrict__ xh, bf16* __restrict__ xl,
                            int C, long long P, long long BP) {
    long long p = (long long)blockIdx.x * blockDim.x + threadIdx.x;
    if (p >= BP) return;
    long long b = p / P, pp = p % P;
    const float* xi = x + b * (long long)C * P + pp;
    float s = 0.f;
#pragma unroll 8
    for (int c = 0; c < C; c++) { float v = xi[(long long)c * P]; s = fmaf(v, v, s); }
    float iv = rsqrtf(s / (float)C + EPSN);
    long long base = b * (long long)C * P + pp;
#pragma unroll 8
    for (int c = 0; c < C; c++) {
        float v = xi[(long long)c * P] * iv;
        long long o = base + (long long)c * P;
        xn[o] = v;
        st_split(xh, xl, o, v);
    }
}

/* -------- unified split-bf16 tensor GEMM, 3-stage pipeline -------------- */
template <int BM, int RES>
__global__ void __launch_bounds__(256, 2) cgemm(
    const bf16* __restrict__ Wh, const bf16* __restrict__ Wl,
    const bf16* __restrict__ Xh, const bf16* __restrict__ Xl,
    float* __restrict__ Y, const float* __restrict__ R,
    const float* __restrict__ AU, const float* __restrict__ PW2,
    const float* __restrict__ PB2,
    int M, int K, long long P)
{
    constexpr int WPM = BM / 32;
    constexpr int WPP = 8 / WPM;
    constexpr int PW  = 128 / WPP;
    constexpr int NT  = PW / 8;
    constexpr int ASZ = BM * 64;
    constexpr int STG = 2 * ASZ + 16384;

    extern __shared__ __align__(128) char smraw[];
    const uint32_t smb = smem_u32(smraw);
    const int tid = threadIdx.x;
    const long long p0 = (long long)blockIdx.x * 128;
    const int m0 = blockIdx.y * BM;
    const int b = blockIdx.z;
    const int ntk = K >> 5;
    const int wid = tid >> 5, lane = tid & 31;
    const int wm = wid % WPM, wp = wid / WPM;

    auto load_stage = [&](int kt, int s) {
        uint32_t base = smb + s * STG;
#pragma unroll
        for (int g = 0; g < BM / 64; g++) {
            int r = (tid >> 2) + g * 64;
            int c = tid & 3;
            uint32_t off = (uint32_t)(r * 64 + ((c ^ ((r >> 1) & 3)) << 4));
            const bf16* wh = Wh + (long long)(m0 + r) * K + kt * 32 + c * 8;
            const bf16* wl = Wl + (long long)(m0 + r) * K + kt * 32 + c * 8;
            cpa16s(base + off, wh);
            cpa16s(base + ASZ + off, wl);
        }
        {
            int r = tid >> 3;
            int cx = tid & 7;
#pragma unroll
            for (int gg = 0; gg < 2; gg++) {
                int c = cx + gg * 8;
                uint32_t off = (uint32_t)(r * 256 + ((c ^ (r & 7)) << 4));
                long long src = ((long long)b * K + kt * 32 + r) * P + p0 + c * 8;
                cpa16s(base + 2 * ASZ + off, Xh + src);
                cpa16s(base + 2 * ASZ + 8192 + off, Xl + src);
            }
        }
        asm volatile("cp.async.commit_group;" ::: "memory");
    };

    float acc[2][NT][4];
#pragma unroll
    for (int i = 0; i < 2; i++)
#pragma unroll
        for (int j = 0; j < NT; j++)
#pragma unroll
            for (int k = 0; k < 4; k++) acc[i][j][k] = 0.f;

    load_stage(0, 0);
    load_stage(1, 1);
    for (int kt = 0; kt < ntk; kt++) {
        const int s = kt % 3;
        if (kt + 1 < ntk) asm volatile("cp.async.wait_group 1;" ::: "memory");
        else              asm volatile("cp.async.wait_group 0;" ::: "memory");
        __syncthreads();
        /* prefetch stage kt+2 into the buffer consumed at kt-1 (barrier above
           guarantees all threads are done reading it) */
        if (kt + 2 < ntk) load_stage(kt + 2, (kt + 2) % 3);
        const uint32_t base = smb + s * STG;
#pragma unroll
        for (int ks = 0; ks < 2; ks++) {
            uint32_t bh[NT / 2][4], bl[NT / 2][4];
#pragma unroll
            for (int np = 0; np < NT / 2; np++) {
                int r = ks * 16 + (lane & 15);
                int chunk = wp * (PW / 8) + np * 2 + (lane >> 4);
                uint32_t ad = base + 2 * ASZ +
                              (uint32_t)(r * 256 + ((chunk ^ (r & 7)) << 4));
                ldm_x4t(bh[np], ad);
                ldm_x4t(bl[np], ad + 8192);
            }
#pragma unroll
            for (int mt = 0; mt < 2; mt++) {
                int r = wm * 32 + mt * 16 + (lane & 15);
                int chunk = ks * 2 + (lane >> 4);
                uint32_t ad = base + (uint32_t)(r * 64 + ((chunk ^ ((r >> 1) & 3)) << 4));
                uint32_t ah[4], al[4];
                ldm_x4(ah[0], ah[1], ah[2], ah[3], ad);
                ldm_x4(al[0], al[1], al[2], al[3], ad + ASZ);
#pragma unroll
                for (int np = 0; np < NT / 2; np++) {
                    mma16816(acc[mt][np * 2],     ah, bh[np][0], bh[np][1]);
                    mma16816(acc[mt][np * 2],     al, bh[np][0], bh[np][1]);
                    mma16816(acc[mt][np * 2],     ah, bl[np][0], bl[np][1]);
                    mma16816(acc[mt][np * 2 + 1], ah, bh[np][2], bh[np][3]);
                    mma16816(acc[mt][np * 2 + 1], al, bh[np][2], bh[np][3]);
                    mma16816(acc[mt][np * 2 + 1], ah, bl[np][2], bl[np][3]);
                }
            }
        }
    }

    float pm0 = 0.f, pm1 = 0.f, pm2 = 0.f;
    if (RES == 2) {
#pragma unroll
        for (int i = 0; i < 64; i++) {
            float w = PW2[i], bb = PB2[i];
            pm0 = fmaf(w, w, pm0); pm1 = fmaf(w, bb, pm1); pm2 = fmaf(bb, bb, pm2);
        }
        pm0 *= (1.f / 64.f); pm1 *= (1.f / 64.f); pm2 *= (1.f / 64.f);
    }

    const int qrow = lane >> 2;
    const int qcol = (lane & 3) << 1;
#pragma unroll
    for (int mt = 0; mt < 2; mt++) {
#pragma unroll
        for (int nt = 0; nt < NT; nt++) {
            int m = m0 + wm * 32 + mt * 16 + qrow;
            long long p = p0 + wp * PW + nt * 8 + qcol;
            long long o0 = ((long long)b * M + m) * P + p;
            long long o1 = ((long long)b * M + m + 8) * P + p;
            float2 v0 = make_float2(acc[mt][nt][0], acc[mt][nt][1]);
            float2 v1 = make_float2(acc[mt][nt][2], acc[mt][nt][3]);
            if (RES == 1) {
                const float2 r0 = *(const float2*)(R + o0);
                const float2 r1 = *(const float2*)(R + o1);
                v0.x = fmaf(0.7f, r0.x, 0.3f * v0.x) * INV058;
                v0.y = fmaf(0.7f, r0.y, 0.3f * v0.y) * INV058;
                v1.x = fmaf(0.7f, r1.x, 0.3f * v1.x) * INV058;
                v1.y = fmaf(0.7f, r1.y, 0.3f * v1.y) * INV058;
            } else if (RES == 2) {
                float A0 = AU[(long long)b * 262144LL + p];
                float A1 = AU[(long long)b * 262144LL + p + 1];
                float iv0 = rsqrtf(fmaf(A0 * A0, pm0, fmaf(2.f * A0, pm1, pm2)) + EPSN);
                float iv1 = rsqrtf(fmaf(A1 * A1, pm0, fmaf(2.f * A1, pm1, pm2)) + EPSN);
                float w0 = PW2[m], b0v = PB2[m];
                float w1 = PW2[m + 8], b1v = PB2[m + 8];
                float r00 = fmaf(A0, w0, b0v) * iv0, r01 = fmaf(A1, w0, b0v) * iv1;
                float r10 = fmaf(A0, w1, b1v) * iv0, r11 = fmaf(A1, w1, b1v) * iv1;
                v0.x = fmaf(0.7f, r00, 0.3f * v0.x) * INV058;
                v0.y = fmaf(0.7f, r01, 0.3f * v0.y) * INV058;
                v1.x = fmaf(0.7f, r10, 0.3f * v1.x) * INV058;
                v1.y = fmaf(0.7f, r11, 0.3f * v1.y) * INV058;
            }
            *(float2*)(Y + o0) = v0;
            *(float2*)(Y + o1) = v1;
        }
    }
}

/* ------- depthwise 5x3 conv2d, 8 L-elems/thread ------------------------- */
__global__ void dwconv2d_silu(const float* __restrict__ in, const float* __restrict__ w,
                              bf16* __restrict__ oh, bf16* __restrict__ ol,
                              int C, int F, long long total) {
    long long t = (long long)blockIdx.x * blockDim.x + threadIdx.x;
    if (t >= total) return;
    int l0 = (int)(t & 255) << 3;
    long long r = t >> 8;
    int f = (int)(r % F); r /= F;
    int c = (int)(r % C);
    int b = (int)(r / C);
    const float* base = in + ((long long)(b * C + c)) * F * 2048LL;
    const float* wc = w + c * 15;
    float a[8];
#pragma unroll
    for (int j = 0; j < 8; j++) a[j] = 0.f;
#pragma unroll
    for (int df = 0; df < 5; df++) {
        int ff = f + df - 2;
        if (ff < 0 || ff >= F) continue;
        const float* row = base + (long long)ff * 2048;
        float4 m0 = *(const float4*)(row + l0);
        float4 m1 = *(const float4*)(row + l0 + 4);
        float x[10];
        x[0] = (l0 > 0) ? row[l0 - 1] : 0.f;
        x[1] = m0.x; x[2] = m0.y; x[3] = m0.z; x[4] = m0.w;
        x[5] = m1.x; x[6] = m1.y; x[7] = m1.z; x[8] = m1.w;
        x[9] = (l0 + 8 < 2048) ? row[l0 + 8] : 0.f;
        float w0 = wc[df * 3 + 0], w1 = wc[df * 3 + 1], w2 = wc[df * 3 + 2];
#pragma unroll
        for (int j = 0; j < 8; j++)
            a[j] = fmaf(w0, x[j], fmaf(w1, x[j + 1], fmaf(w2, x[j + 2], a[j])));
    }
    long long o = (((long long)(b * C + c)) * F + f) * 2048LL + l0;
    st_split4(oh, ol, o,     mp_siluf(a[0]), mp_siluf(a[1]), mp_siluf(a[2]), mp_siluf(a[3]));
    st_split4(oh, ol, o + 4, mp_siluf(a[4]), mp_siluf(a[5]), mp_siluf(a[6]), mp_siluf(a[7]));
}

/* ------- freq average pool, 4 elems/thread, packed stores --------------- */
__global__ void avgpool_f(const float* __restrict__ in, bf16* __restrict__ oh,
                          bf16* __restrict__ ol,
                          int C, int F, int Fo, int s, long long total4) {
    long long t = (long long)blockIdx.x * blockDim.x + threadIdx.x;
    if (t >= total4) return;
    long long e = t << 2;
    int l = (int)(e & 2047);
    long long r = e >> 11;
    int fo = (int)(r % Fo); r /= Fo;
    int c = (int)(r % C);
    int b = (int)(r / C);
    const float* p = in + (((long long)(b * C + c)) * F + fo * s) * 2048LL + l;
    float4 sum = make_float4(0.f, 0.f, 0.f, 0.f);
    for (int j = 0; j < s; j++) {
        float4 v = *(const float4*)(p + (long long)j * 2048);
        sum.x += v.x; sum.y += v.y; sum.z += v.z; sum.w += v.w;
    }
    float is = 1.f / (float)s;
    st_split4(oh, ol, e, sum.x * is, sum.y * is, sum.z * is, sum.w * is);
}

/* ------- seq depthwise k3, 8 elems/thread ------------------------------- */
__global__ void dwconv1d_silu(const float* __restrict__ hg, const float* __restrict__ w,
                              bf16* __restrict__ oh, bf16* __restrict__ ol) {
    long long t = (long long)blockIdx.x * blockDim.x + threadIdx.x;
    if (t >= 524288LL) return;
    int l0 = (int)(t & 255) << 3;
    int c = (int)((t >> 8) & 1023);
    int b = (int)(t >> 18);
    const float* row = hg + ((long long)b * 2048 + c) * 2048LL;
    const float* wc = w + c * 3;
    float4 m0 = *(const float4*)(row + l0);
    float4 m1 = *(const float4*)(row + l0 + 4);
    float x[10];
    x[0] = (l0 > 0) ? mp_siluf(row[l0 - 1]) : 0.f;
    x[1] = mp_siluf(m0.x); x[2] = mp_siluf(m0.y);
    x[3] = mp_siluf(m0.z); x[4] = mp_siluf(m0.w);
    x[5] = mp_siluf(m1.x); x[6] = mp_siluf(m1.y);
    x[7] = mp_siluf(m1.z); x[8] = mp_siluf(m1.w);
    x[9] = (l0 + 8 < 2048) ? mp_siluf(row[l0 + 8]) : 0.f;
    float w0 = wc[0], w1 = wc[1], w2 = wc[2];
    float a[8];
#pragma unroll
    for (int j = 0; j < 8; j++)
        a[j] = fmaf(w0, x[j], fmaf(w1, x[j + 1], w2 * x[j + 2]));
    long long o = ((long long)b * 1024 + c) * 2048LL + l0;
    st_split4(oh, ol, o,     mp_siluf(a[0]), mp_siluf(a[1]), mp_siluf(a[2]), mp_siluf(a[3]));
    st_split4(oh, ol, o + 4, mp_siluf(a[4]), mp_siluf(a[5]), mp_siluf(a[6]), mp_siluf(a[7]));
}

/* --------- minGRU blocked scan (4 elems/lane) + output gate ------------- */
__global__ void gru_scan(const float* __restrict__ u, const float* __restrict__ hg,
                         bf16* __restrict__ oh, bf16* __restrict__ ol) {
    int w = (int)((blockIdx.x * blockDim.x + threadIdx.x) >> 5);
    int lane = threadIdx.x & 31;
    if (w >= 2048) return;
    int bt = w >> 10, c = w & 1023;
    const float* zrow = u + ((long long)bt * 2048 + c) * 2048LL;
    const float* crow = zrow + 1024LL * 2048LL;
    const float* grow = hg + ((long long)bt * 2048 + 1024 + c) * 2048LL;
    long long obase = ((long long)bt * 1024 + c) * 2048LL;
    float carry = 0.f;
    for (int l0 = 0; l0 < 2048; l0 += 128) {
        int le = l0 + lane * 4;
        float4 zv = *(const float4*)(zrow + le);
        float4 cv = *(const float4*)(crow + le);
        float z0 = sigmoidf_fast(zv.x), z1 = sigmoidf_fast(zv.y);
        float z2 = sigmoidf_fast(zv.z), z3 = sigmoidf_fast(zv.w);
        float a0 = 1.f - z0, b0 = z0 * cv.x;
        float a1 = 1.f - z1, b1 = z1 * cv.y;
        float a2 = 1.f - z2, b2 = z2 * cv.z;
        float a3 = 1.f - z3, b3 = z3 * cv.w;
        /* compose 4 per-lane maps left->right: h -> A*h + B */
        float A = a0, B = b0;
        A = a1 * A; B = fmaf(a1, B, b1);
        A = a2 * A; B = fmaf(a2, B, b2);
        A = a3 * A; B = fmaf(a3, B, b3);
        /* warp inclusive scan over (A,B) */
        float As = A, Bs = B;
#pragma unroll
        for (int off = 1; off < 32; off <<= 1) {
            float Ap = __shfl_up_sync(0xffffffffu, As, off);
            float Bp = __shfl_up_sync(0xffffffffu, Bs, off);
            if (lane >= off) { Bs = fmaf(As, Bp, Bs); As *= Ap; }
        }
        /* exclusive prefix for this lane */
        float Ae = __shfl_up_sync(0xffffffffu, As, 1);
        float Be = __shfl_up_sync(0xffffffffu, Bs, 1);
        if (lane == 0) { Ae = 1.f; Be = 0.f; }
        float hprev = fmaf(Ae, carry, Be);
        float h0 = fmaf(a0, hprev, b0);
        float h1 = fmaf(a1, h0, b1);
        float h2 = fmaf(a2, h1, b2);
        float h3 = fmaf(a3, h2, b3);
        carry = __shfl_sync(0xffffffffu, fmaf(As, carry, Bs), 31);
        float4 gv = *(const float4*)(grow + le);
        st_split4(oh, ol, obase + le,
                  h0 * mp_siluf(gv.x), h1 * mp_siluf(gv.y),
                  h2 * mp_siluf(gv.z), h3 * mp_siluf(gv.w));
    }
}

/* ---------------- final activation (float4) ----------------------------- */
__global__ void silu_out(const float* __restrict__ in, float* __restrict__ out, long long n4) {
    long long i = (long long)blockIdx.x * blockDim.x + threadIdx.x;
    if (i >= n4) return;
    float4 v = *(const float4*)(in + (i << 2));
    v.x = mp_siluf(v.x); v.y = mp_siluf(v.y);
    v.z = mp_siluf(v.z); v.w = mp_siluf(v.w);
    *(float4*)(out + (i << 2)) = v;
}

/* ======================================================================== */
extern "C" void kernel_launch(void* const* d_in, const int* in_sizes, int n_in,
                              void* d_out, int out_size) {
    const float* audio = (const float*)d_in[0];
    const float* pw    = (const float*)d_in[1];
    const float* pb    = (const float*)d_in[2];
    const float* c0w1  = (const float*)d_in[3];
    const float* c0wd  = (const float*)d_in[4];
    const float* c0w2  = (const float*)d_in[5];
    const float* c0dn  = (const float*)d_in[6];
    const float* c1w1  = (const float*)d_in[7];
    const float* c1wd  = (const float*)d_in[8];
    const float* c1w2  = (const float*)d_in[9];
    const float* c1dn  = (const float*)d_in[10];
    const float* c2w1  = (const float*)d_in[11];
    const float* c2wd  = (const float*)d_in[12];
    const float* c2w2  = (const float*)d_in[13];
    const float* c2dn  = (const float*)d_in[14];
    const float* hgw   = (const float*)d_in[15];
    const float* dww   = (const float*)d_in[16];
    const float* gruw  = (const float*)d_in[17];
    const float* outw  = (const float*)d_in[18];

    float *wp, *xn, *xsf, *bufA, *bufBf, *hb, *poolf, *xb;
    bf16 *wbf, *cw;
    cudaGetSymbolAddress((void**)&wp,    g_wpool);
    cudaGetSymbolAddress((void**)&xn,    g_xn);
    cudaGetSymbolAddress((void**)&xsf,   g_xs);
    cudaGetSymbolAddress((void**)&bufA,  g_bufA);
    cudaGetSymbolAddress((void**)&bufBf, g_bufB);
    cudaGetSymbolAddress((void**)&hb,    g_h);
    cudaGetSymbolAddress((void**)&poolf, g_pool);
    cudaGetSymbolAddress((void**)&xb,    g_x);
    cudaGetSymbolAddress((void**)&wbf,   g_wbf);
    cudaGetSymbolAddress((void**)&cw,    g_cwbf);

    bf16* xs   = (bf16*)xsf;
    bf16* bufB = (bf16*)bufBf;
    bf16* pool = (bf16*)poolf;
    const float* NUL = (const float*)0;

    cudaFuncSetAttribute(cgemm<128, 0>, cudaFuncAttributeMaxDynamicSharedMemorySize, 98304);
    cudaFuncSetAttribute(cgemm<128, 1>, cudaFuncAttributeMaxDynamicSharedMemorySize, 98304);
    cudaFuncSetAttribute(cgemm<64, 2>,  cudaFuncAttributeMaxDynamicSharedMemorySize, 73728);

    /* fused weight normalization + bf16 split: one launch for all 16 */
    NormDescs nd;
    {
        const float* srcs[16] = {c0w1, c0wd, c0w2, c0dn, c1w1, c1wd, c1w2, c1dn,
                                 c2w1, c2wd, c2w2, c2dn, hgw, dww, gruw, outw};
        int rows[16]   = {128, 128, 64, 128, 256, 256, 128, 256, 512, 512, 256, 512,
                          8192, 4096, 8192, 2048};
        int rowlen[16] = {64, 15, 128, 64, 128, 15, 256, 128, 256, 15, 512, 256,
                          512, 3, 1024, 1024};
        float* dstf[16] = {0, wp + O_C0WD, 0, 0, 0, wp + O_C1WD, 0, 0,
                           0, wp + O_C2WD, 0, 0, 0, wp + O_DW, 0, 0};
        int hofs[16] = {CWH_C0W1, -1, CWH_C0W2, CWH_C0DN, CWH_C1W1, -1, CWH_C1W2,
                        CWH_C1DN, CWH_C2W1, -1, CWH_C2W2, CWH_C2DN, -1, -1, -1, -1};
        int acc = 0;
        for (int i = 0; i < 16; i++) {
            acc += rows[i];
            nd.s[i].src = srcs[i];
            nd.s[i].dstf = dstf[i];
            nd.s[i].rowlen = rowlen[i];
            nd.s[i].row_end = acc;
            if (dstf[i]) { nd.s[i].dsth = 0; nd.s[i].dstl = 0; }
            else if (hofs[i] >= 0) { nd.s[i].dsth = cw + hofs[i]; nd.s[i].dstl = cw + hofs[i] + CWLO; }
        }
        nd.s[12].dsth = wbf + WH_HG(0);  nd.s[12].dstl = wbf + WH_HG(0) + WLO;
        nd.s[14].dsth = wbf + WH_GRU(0); nd.s[14].dstl = wbf + WH_GRU(0) + WLO;
        nd.s[15].dsth = wbf + WH_OUT(0); nd.s[15].dstl = wbf + WH_OUT(0) + WLO;
        norm_rows_multi<<<acc, 128>>>(nd);
    }

    /* block 0  (C 64->128->64->pool4->128, F=128, P=262144) */
    proj_pixelnorm<<<512, 256>>>(audio, pw, pb, xs, xs + XS_LO);
    cgemm<128, 0><<<dim3(2048, 1, 2), 256, 98304>>>(cw + CWH_C0W1, cw + CWH_C0W1 + CWLO,
        xs, xs + XS_LO, bufA, NUL, NUL, NUL, NUL, 128, 64, 262144LL);
    dwconv2d_silu<<<32768, 256>>>(bufA, wp + O_C0WD, bufB, bufB + BUFB_LO, 128, 128, 8388608LL);
    cgemm<64, 2><<<dim3(2048, 1, 2), 256, 73728>>>(cw + CWH_C0W2, cw + CWH_C0W2 + CWLO,
        bufB, bufB + BUFB_LO, hb, NUL, audio, pw, pb, 64, 128, 262144LL);
    avgpool_f<<<8192, 256>>>(hb, pool, pool + POOL_LO, 64, 128, 32, 4, 2097152LL);
    cgemm<128, 0><<<dim3(512, 1, 2), 256, 98304>>>(cw + CWH_C0DN, cw + CWH_C0DN + CWLO,
        pool, pool + POOL_LO, xb, NUL, NUL, NUL, NUL, 128, 64, 65536LL);

    /* block 1  (C 128->256->128->pool4->256, F=32, P=65536) */
    pixelnorm4<true><<<128, 256>>>(xb, xn, xs, xs + XS_LO, 128, 65536LL, 131072LL);
    cgemm<128, 0><<<dim3(512, 2, 2), 256, 98304>>>(cw + CWH_C1W1, cw + CWH_C1W1 + CWLO,
        xs, xs + XS_LO, bufA, NUL, NUL, NUL, NUL, 256, 128, 65536LL);
    dwconv2d_silu<<<16384, 256>>>(bufA, wp + O_C1WD, bufB, bufB + BUFB_LO, 256, 32, 4194304LL);
    cgemm<128, 1><<<dim3(512, 1, 2), 256, 98304>>>(cw + CWH_C1W2, cw + CWH_C1W2 + CWLO,
        bufB, bufB + BUFB_LO, hb, xn, NUL, NUL, NUL, 128, 256, 65536LL);
    avgpool_f<<<4096, 256>>>(hb, pool, pool + POOL_LO, 128, 32, 8, 4, 1048576LL);
    cgemm<128, 0><<<dim3(128, 2, 2), 256, 98304>>>(cw + CWH_C1DN, cw + CWH_C1DN + CWLO,
        pool, pool + POOL_LO, xb, NUL, NUL, NUL, NUL, 256, 128, 16384LL);

    /* block 2  (C 256->512->256->pool8->512, F=8, P=16384) */
    pixelnorm4<true><<<32, 256>>>(xb, xn, xs, xs + XS_LO, 256, 16384LL, 32768LL);
    cgemm<128, 0><<<dim3(128, 4, 2), 256, 98304>>>(cw + CWH_C2W1, cw + CWH_C2W1 + CWLO,
        xs, xs + XS_LO, bufA, NUL, NUL, NUL, NUL, 512, 256, 16384LL);
    dwconv2d_silu<<<8192, 256>>>(bufA, wp + O_C2WD, bufB, bufB + BUFB_LO, 512, 8, 2097152LL);
    cgemm<128, 1><<<dim3(128, 2, 2), 256, 98304>>>(cw + CWH_C2W2, cw + CWH_C2W2 + CWLO,
        bufB, bufB + BUFB_LO, hb, xn, NUL, NUL, NUL, 256, 512, 16384LL);
    avgpool_f<<<1024, 256>>>(hb, pool, pool + POOL_LO, 256, 8, 1, 8, 262144LL);
    cgemm<128, 0><<<dim3(16, 4, 2), 256, 98304>>>(cw + CWH_C2DN, cw + CWH_C2DN + CWLO,
        pool, pool + POOL_LO, xb, NUL, NUL, NUL, NUL, 512, 256, 2048LL);

    /* seq blocks ×4  (C=512, L=2048) */
    for (int i = 0; i < 4; i++) {
        pixelnorm_s<<<128, 32>>>(xb, xn, xs, xs + XS_LO, 512, 2048LL, 4096LL);
        cgemm<128, 0><<<dim3(16, 16, 2), 256, 98304>>>(
            wbf + WH_HG(i), wbf + WH_HG(i) + WLO, xs, xs + XS_LO,
            bufA, NUL, NUL, NUL, NUL, 2048, 512, 2048LL);
        dwconv1d_silu<<<2048, 256>>>(bufA, wp + O_DW + i * 3072, bufB, bufB + BUFB_LO);
        cgemm<128, 0><<<dim3(16, 16, 2), 256, 98304>>>(
            wbf + WH_GRU(i), wbf + WH_GRU(i) + WLO, bufB, bufB + BUFB_LO,
            hb, NUL, NUL, NUL, NUL, 2048, 1024, 2048LL);
        gru_scan<<<256, 256>>>(hb, bufA, pool, pool + POOL_LO);
        cgemm<128, 1><<<dim3(16, 4, 2), 256, 98304>>>(
            wbf + WH_OUT(i), wbf + WH_OUT(i) + WLO, pool, pool + POOL_LO,
            xb, xn, NUL, NUL, NUL, 512, 1024, 2048LL);
    }

    silu_out<<<2048, 256>>>(xb, (float*)d_out, 524288LL);
}

// round 15
// speedup vs baseline: 3.3875x; 1.0524x over previous
#include <cuda_runtime.h>
#include <cuda_bf16.h>
#include <cstdint>

#define GAIN   1.6778523489932886f   /* 1/0.596 */
#define INV058 1.3130643285972254f   /* 1/sqrt(0.7^2+0.3^2) */
#define EPSN   1e-4f

typedef unsigned long long ull;
typedef __nv_bfloat16 bf16;

/* ---------------- static device scratch (no allocations allowed) -------- */
__device__ __align__(16) float g_wpool[15230976];
__device__ __align__(16) float g_xn[33554432];
__device__ __align__(16) float g_xs[33554432];    /* bf16 planes: hi | lo   */
__device__ __align__(16) float g_bufA[67108864];
__device__ __align__(16) float g_bufB[67108864];  /* bf16 planes            */
__device__ __align__(16) float g_h[33554432];
__device__ __align__(16) float g_pool[8388608];   /* bf16 planes            */
__device__ __align__(16) float g_x[16777216];
__device__ __align__(16) bf16 g_wbf[29360128];    /* seq weights: hi | lo   */
__device__ __align__(16) bf16 g_cwbf[1048576];    /* conv weights: hi | lo  */

#define XS_LO   33554432
#define BUFB_LO 67108864
#define POOL_LO 8388608

/* fp32 weight pool offsets (depthwise weights only) */
#define O_C0WD 8192
#define O_C1WD 59264
#define O_C2WD 259712
#define O_DW   4723840

/* bf16 conv-weight hi offsets in g_cwbf; lo at +CWLO */
#define CWLO 516096
#define CWH_C0W1 0
#define CWH_C0W2 8192
#define CWH_C0DN 16384
#define CWH_C1W1 24576
#define CWH_C1W2 57344
#define CWH_C1DN 90112
#define CWH_C2W1 122880
#define CWH_C2W2 253952
#define CWH_C2DN 385024

/* bf16 seq-weight hi offsets in g_wbf; lo at +WLO */
#define WLO 14680064
#define WH_HG(i)  ((i) * 1048576)
#define WH_GRU(i) (4194304 + (i) * 2097152)
#define WH_OUT(i) (12582912 + (i) * 524288)

__device__ __forceinline__ float sigmoidf_fast(float x) {
    return __fdividef(1.f, 1.f + __expf(-x));
}
__device__ __forceinline__ float mp_siluf(float x) {
    return x * sigmoidf_fast(x) * GAIN;
}
__device__ __forceinline__ void st_split(bf16* h, bf16* l, long long i, float v) {
    bf16 hi = __float2bfloat16(v);
    h[i] = hi;
    l[i] = __float2bfloat16(v - __bfloat162float(hi));
}
__device__ __forceinline__ void st_split4(bf16* h, bf16* l, long long i,
                                          float a0, float a1, float a2, float a3) {
    union { bf16 b[4]; uint2 u; } H, L;
    H.b[0] = __float2bfloat16(a0); H.b[1] = __float2bfloat16(a1);
    H.b[2] = __float2bfloat16(a2); H.b[3] = __float2bfloat16(a3);
    L.b[0] = __float2bfloat16(a0 - __bfloat162float(H.b[0]));
    L.b[1] = __float2bfloat16(a1 - __bfloat162float(H.b[1]));
    L.b[2] = __float2bfloat16(a2 - __bfloat162float(H.b[2]));
    L.b[3] = __float2bfloat16(a3 - __bfloat162float(H.b[3]));
    *(uint2*)(h + i) = H.u;
    *(uint2*)(l + i) = L.u;
}
__device__ __forceinline__ void cpa16s(uint32_t saddr, const void* g) {
    asm volatile("cp.async.cg.shared.global [%0], [%1], 16;" :: "r"(saddr), "l"(g) : "memory");
}
__device__ __forceinline__ uint32_t smem_u32(const void* p) {
    uint32_t a;
    asm("{ .reg .u64 t; cvta.to.shared.u64 t, %1; cvt.u32.u64 %0, t; }" : "=r"(a) : "l"(p));
    return a;
}

/* ---------------- warp-MMA helpers (baseline PTX, sm_80+) --------------- */
__device__ __forceinline__ void ldm_x4(uint32_t& a0, uint32_t& a1, uint32_t& a2,
                                       uint32_t& a3, uint32_t addr) {
    asm volatile("ldmatrix.sync.aligned.m8n8.x4.shared.b16 {%0,%1,%2,%3}, [%4];"
                 : "=r"(a0), "=r"(a1), "=r"(a2), "=r"(a3) : "r"(addr));
}
__device__ __forceinline__ void ldm_x4t(uint32_t* r, uint32_t addr) {
    asm volatile("ldmatrix.sync.aligned.m8n8.x4.trans.shared.b16 {%0,%1,%2,%3}, [%4];"
                 : "=r"(r[0]), "=r"(r[1]), "=r"(r[2]), "=r"(r[3]) : "r"(addr));
}
__device__ __forceinline__ void mma16816(float* d, const uint32_t* a, uint32_t b0, uint32_t b1) {
    asm volatile("mma.sync.aligned.m16n8k16.row.col.f32.bf16.bf16.f32 "
                 "{%0,%1,%2,%3}, {%4,%5,%6,%7}, {%8,%9}, {%0,%1,%2,%3};"
                 : "+f"(d[0]), "+f"(d[1]), "+f"(d[2]), "+f"(d[3])
                 : "r"(a[0]), "r"(a[1]), "r"(a[2]), "r"(a[3]), "r"(b0), "r"(b1));
}

/* -------- fused weight normalization + bf16 split (segmented) ----------- */
struct NormSeg { const float* src; float* dstf; bf16* dsth; bf16* dstl;
                 int rowlen; int row_end; };
struct NormDescs { NormSeg s[16]; };

__global__ void norm_rows_multi(NormDescs d) {
    int blk = blockIdx.x;
    int seg = 0, row_start = 0;
#pragma unroll
    for (int i = 0; i < 16; i++) {
        if (blk >= d.s[i].row_end) { seg = i + 1; row_start = d.s[i].row_end; }
    }
    int r = blk - row_start;
    int rowlen = d.s[seg].rowlen;
    const float* s = d.s[seg].src + (long long)r * rowlen;
    float acc = 0.f;
    for (int i = threadIdx.x; i < rowlen; i += blockDim.x) { float v = s[i]; acc = fmaf(v, v, acc); }
#pragma unroll
    for (int off = 16; off; off >>= 1) acc += __shfl_down_sync(0xffffffffu, acc, off);
    __shared__ float sm[8];
    int warp = threadIdx.x >> 5, lane = threadIdx.x & 31;
    if (lane == 0) sm[warp] = acc;
    __syncthreads();
    if (threadIdx.x == 0) {
        float t = 0.f;
        int nw = blockDim.x >> 5;
        for (int i = 0; i < nw; i++) t += sm[i];
        sm[0] = rsqrtf(t + 1e-8f);
    }
    __syncthreads();
    float iv = sm[0];
    if (d.s[seg].dstf) {
        float* dst = d.s[seg].dstf + (long long)r * rowlen;
        for (int i = threadIdx.x; i < rowlen; i += blockDim.x) dst[i] = s[i] * iv;
    } else {
        bf16* h = d.s[seg].dsth + (long long)r * rowlen;
        bf16* l = d.s[seg].dstl + (long long)r * rowlen;
        for (int i = threadIdx.x; i < rowlen; i += blockDim.x) {
            float v = s[i] * iv;
            bf16 hi = __float2bfloat16(v);
            h[i] = hi;
            l[i] = __float2bfloat16(v - __bfloat162float(hi));
        }
    }
}

/* -------- proj pixel norm, 4 positions/thread, packed stores ------------ */
__global__ void proj_pixelnorm(const float* __restrict__ audio, const float* __restrict__ pw,
                               const float* __restrict__ pb,
                               bf16* __restrict__ xh, bf16* __restrict__ xl) {
    long long p = ((long long)blockIdx.x * blockDim.x + threadIdx.x) << 2;
    if (p >= 524288LL) return;
    float pm0 = 0.f, pm1 = 0.f, pm2 = 0.f;
#pragma unroll
    for (int i = 0; i < 64; i++) {
        float w = pw[i], bb = pb[i];
        pm0 = fmaf(w, w, pm0); pm1 = fmaf(w, bb, pm1); pm2 = fmaf(bb, bb, pm2);
    }
    pm0 *= (1.f / 64.f); pm1 *= (1.f / 64.f); pm2 *= (1.f / 64.f);
    float4 A = *(const float4*)(audio + p);
    float iv0 = rsqrtf(fmaf(A.x * A.x, pm0, fmaf(2.f * A.x, pm1, pm2)) + EPSN);
    float iv1 = rsqrtf(fmaf(A.y * A.y, pm0, fmaf(2.f * A.y, pm1, pm2)) + EPSN);
    float iv2 = rsqrtf(fmaf(A.z * A.z, pm0, fmaf(2.f * A.z, pm1, pm2)) + EPSN);
    float iv3 = rsqrtf(fmaf(A.w * A.w, pm0, fmaf(2.f * A.w, pm1, pm2)) + EPSN);
    long long b = p >> 18;
    long long rem = p & 262143LL;
    long long base = b * 64LL * 262144LL + rem;
#pragma unroll
    for (int c = 0; c < 64; c++) {
        float w = pw[c], bb = pb[c];
        st_split4(xh, xl, base + (long long)c * 262144LL,
                  mp_siluf(fmaf(A.x, w, bb) * iv0), mp_siluf(fmaf(A.y, w, bb) * iv1),
                  mp_siluf(fmaf(A.z, w, bb) * iv2), mp_siluf(fmaf(A.w, w, bb) * iv3));
    }
}

/* -------- pixel norm, 4 positions/thread (conv blocks) ------------------ */
template <bool SILU>
__global__ void pixelnorm4(const float* __restrict__ x, float* __restrict__ xn,
                           bf16* __restrict__ xh, bf16* __restrict__ xl,
                           int C, long long P, long long BP) {
    long long p = ((long long)blockIdx.x * blockDim.x + threadIdx.x) << 2;
    if (p >= BP) return;
    long long b = p / P, pp = p % P;
    const float* xi = x + b * (long long)C * P + pp;
    float s0 = 0.f, s1 = 0.f, s2 = 0.f, s3 = 0.f;
#pragma unroll 4
    for (int c = 0; c < C; c++) {
        float4 v = *(const float4*)(xi + (long long)c * P);
        s0 = fmaf(v.x, v.x, s0); s1 = fmaf(v.y, v.y, s1);
        s2 = fmaf(v.z, v.z, s2); s3 = fmaf(v.w, v.w, s3);
    }
    float ic = 1.f / (float)C;
    float iv0 = rsqrtf(s0 * ic + EPSN), iv1 = rsqrtf(s1 * ic + EPSN);
    float iv2 = rsqrtf(s2 * ic + EPSN), iv3 = rsqrtf(s3 * ic + EPSN);
    long long base = b * (long long)C * P + pp;
#pragma unroll 4
    for (int c = 0; c < C; c++) {
        long long o = base + (long long)c * P;
        float4 v = *(const float4*)(xi + (long long)c * P);
        float n0 = v.x * iv0, n1 = v.y * iv1, n2 = v.z * iv2, n3 = v.w * iv3;
        *(float4*)(xn + o) = make_float4(n0, n1, n2, n3);
        if (SILU) st_split4(xh, xl, o, mp_siluf(n0), mp_siluf(n1), mp_siluf(n2), mp_siluf(n3));
        else      st_split4(xh, xl, o, n0, n1, n2, n3);
    }
}

/* -------- pixel norm scalar (seq blocks, tiny) -------------------------- */
__global__ void pixelnorm_s(const float* __restrict__ x, float* __restrict__ xn,
                            bf16* __restrict__ xh, bf16* __restrict__ xl,
                            int C, long long P, long long BP) {
    long long p = (long long)blockIdx.x * blockDim.x + threadIdx.x;
    if (p >= BP) return;
    long long b = p / P, pp = p % P;
    const float* xi = x + b * (long long)C * P + pp;
    float s = 0.f;
#pragma unroll 8
    for (int c = 0; c < C; c++) { float v = xi[(long long)c * P]; s = fmaf(v, v, s); }
    float iv = rsqrtf(s / (float)C + EPSN);
    long long base = b * (long long)C * P + pp;
#pragma unroll 8
    for (int c = 0; c < C; c++) {
        float v = xi[(long long)c * P] * iv;
        long long o = base + (long long)c * P;
        xn[o] = v;
        st_split(xh, xl, o, v);
    }
}

/* -------- unified split-bf16 tensor GEMM, 3-stage pipeline -------------- */
/* RES: 0 none, 1 mp_add(R), 2 mp_add(recomputed proj residual),           */
/* 3 mp_add(R) + final mp_silu (writes network output)                     */
template <int BM, int RES>
__global__ void __launch_bounds__(256, 2) cgemm(
    const bf16* __restrict__ Wh, const bf16* __restrict__ Wl,
    const bf16* __restrict__ Xh, const bf16* __restrict__ Xl,
    float* __restrict__ Y, const float* __restrict__ R,
    const float* __restrict__ AU, const float* __restrict__ PW2,
    const float* __restrict__ PB2,
    int M, int K, long long P)
{
    constexpr int WPM = BM / 32;
    constexpr int WPP = 8 / WPM;
    constexpr int PW  = 128 / WPP;
    constexpr int NT  = PW / 8;
    constexpr int ASZ = BM * 64;
    constexpr int STG = 2 * ASZ + 16384;

    extern __shared__ __align__(128) char smraw[];
    const uint32_t smb = smem_u32(smraw);
    const int tid = threadIdx.x;
    const long long p0 = (long long)blockIdx.x * 128;
    const int m0 = blockIdx.y * BM;
    const int b = blockIdx.z;
    const int ntk = K >> 5;
    const int wid = tid >> 5, lane = tid & 31;
    const int wm = wid % WPM, wp = wid / WPM;

    auto load_stage = [&](int kt, int s) {
        uint32_t base = smb + s * STG;
#pragma unroll
        for (int g = 0; g < BM / 64; g++) {
            int r = (tid >> 2) + g * 64;
            int c = tid & 3;
            uint32_t off = (uint32_t)(r * 64 + ((c ^ ((r >> 1) & 3)) << 4));
            const bf16* wh = Wh + (long long)(m0 + r) * K + kt * 32 + c * 8;
            const bf16* wl = Wl + (long long)(m0 + r) * K + kt * 32 + c * 8;
            cpa16s(base + off, wh);
            cpa16s(base + ASZ + off, wl);
        }
        {
            int r = tid >> 3;
            int cx = tid & 7;
#pragma unroll
            for (int gg = 0; gg < 2; gg++) {
                int c = cx + gg * 8;
                uint32_t off = (uint32_t)(r * 256 + ((c ^ (r & 7)) << 4));
                long long src = ((long long)b * K + kt * 32 + r) * P + p0 + c * 8;
                cpa16s(base + 2 * ASZ + off, Xh + src);
                cpa16s(base + 2 * ASZ + 8192 + off, Xl + src);
            }
        }
        asm volatile("cp.async.commit_group;" ::: "memory");
    };

    float acc[2][NT][4];
#pragma unroll
    for (int i = 0; i < 2; i++)
#pragma unroll
        for (int j = 0; j < NT; j++)
#pragma unroll
            for (int k = 0; k < 4; k++) acc[i][j][k] = 0.f;

    load_stage(0, 0);
    load_stage(1, 1);
    for (int kt = 0; kt < ntk; kt++) {
        const int s = kt % 3;
        if (kt + 1 < ntk) asm volatile("cp.async.wait_group 1;" ::: "memory");
        else              asm volatile("cp.async.wait_group 0;" ::: "memory");
        __syncthreads();
        if (kt + 2 < ntk) load_stage(kt + 2, (kt + 2) % 3);
        const uint32_t base = smb + s * STG;
#pragma unroll
        for (int ks = 0; ks < 2; ks++) {
            uint32_t bh[NT / 2][4], bl[NT / 2][4];
#pragma unroll
            for (int np = 0; np < NT / 2; np++) {
                int r = ks * 16 + (lane & 15);
                int chunk = wp * (PW / 8) + np * 2 + (lane >> 4);
                uint32_t ad = base + 2 * ASZ +
                              (uint32_t)(r * 256 + ((chunk ^ (r & 7)) << 4));
                ldm_x4t(bh[np], ad);
                ldm_x4t(bl[np], ad + 8192);
            }
#pragma unroll
            for (int mt = 0; mt < 2; mt++) {
                int r = wm * 32 + mt * 16 + (lane & 15);
                int chunk = ks * 2 + (lane >> 4);
                uint32_t ad = base + (uint32_t)(r * 64 + ((chunk ^ ((r >> 1) & 3)) << 4));
                uint32_t ah[4], al[4];
                ldm_x4(ah[0], ah[1], ah[2], ah[3], ad);
                ldm_x4(al[0], al[1], al[2], al[3], ad + ASZ);
#pragma unroll
                for (int np = 0; np < NT / 2; np++) {
                    mma16816(acc[mt][np * 2],     ah, bh[np][0], bh[np][1]);
                    mma16816(acc[mt][np * 2],     al, bh[np][0], bh[np][1]);
                    mma16816(acc[mt][np * 2],     ah, bl[np][0], bl[np][1]);
                    mma16816(acc[mt][np * 2 + 1], ah, bh[np][2], bh[np][3]);
                    mma16816(acc[mt][np * 2 + 1], al, bh[np][2], bh[np][3]);
                    mma16816(acc[mt][np * 2 + 1], ah, bl[np][2], bl[np][3]);
                }
            }
        }
    }

    float pm0 = 0.f, pm1 = 0.f, pm2 = 0.f;
    if (RES == 2) {
#pragma unroll
        for (int i = 0; i < 64; i++) {
            float w = PW2[i], bb = PB2[i];
            pm0 = fmaf(w, w, pm0); pm1 = fmaf(w, bb, pm1); pm2 = fmaf(bb, bb, pm2);
        }
        pm0 *= (1.f / 64.f); pm1 *= (1.f / 64.f); pm2 *= (1.f / 64.f);
    }

    const int qrow = lane >> 2;
    const int qcol = (lane & 3) << 1;
#pragma unroll
    for (int mt = 0; mt < 2; mt++) {
#pragma unroll
        for (int nt = 0; nt < NT; nt++) {
            int m = m0 + wm * 32 + mt * 16 + qrow;
            long long p = p0 + wp * PW + nt * 8 + qcol;
            long long o0 = ((long long)b * M + m) * P + p;
            long long o1 = ((long long)b * M + m + 8) * P + p;
            float2 v0 = make_float2(acc[mt][nt][0], acc[mt][nt][1]);
            float2 v1 = make_float2(acc[mt][nt][2], acc[mt][nt][3]);
            if (RES == 1 || RES == 3) {
                const float2 r0 = *(const float2*)(R + o0);
                const float2 r1 = *(const float2*)(R + o1);
                v0.x = fmaf(0.7f, r0.x, 0.3f * v0.x) * INV058;
                v0.y = fmaf(0.7f, r0.y, 0.3f * v0.y) * INV058;
                v1.x = fmaf(0.7f, r1.x, 0.3f * v1.x) * INV058;
                v1.y = fmaf(0.7f, r1.y, 0.3f * v1.y) * INV058;
            } else if (RES == 2) {
                float A0 = AU[(long long)b * 262144LL + p];
                float A1 = AU[(long long)b * 262144LL + p + 1];
                float iv0 = rsqrtf(fmaf(A0 * A0, pm0, fmaf(2.f * A0, pm1, pm2)) + EPSN);
                float iv1 = rsqrtf(fmaf(A1 * A1, pm0, fmaf(2.f * A1, pm1, pm2)) + EPSN);
                float w0 = PW2[m], b0v = PB2[m];
                float w1 = PW2[m + 8], b1v = PB2[m + 8];
                float r00 = fmaf(A0, w0, b0v) * iv0, r01 = fmaf(A1, w0, b0v) * iv1;
                float r10 = fmaf(A0, w1, b1v) * iv0, r11 = fmaf(A1, w1, b1v) * iv1;
                v0.x = fmaf(0.7f, r00, 0.3f * v0.x) * INV058;
                v0.y = fmaf(0.7f, r01, 0.3f * v0.y) * INV058;
                v1.x = fmaf(0.7f, r10, 0.3f * v1.x) * INV058;
                v1.y = fmaf(0.7f, r11, 0.3f * v1.y) * INV058;
            }
            if (RES == 3) {
                v0.x = mp_siluf(v0.x); v0.y = mp_siluf(v0.y);
                v1.x = mp_siluf(v1.x); v1.y = mp_siluf(v1.y);
            }
            *(float2*)(Y + o0) = v0;
            *(float2*)(Y + o1) = v1;
        }
    }
}

/* ------- depthwise 5x3 conv2d, 4 f-rows x 8 L-elems per thread ---------- */
__global__ void dwconv2d_silu(const float* __restrict__ in, const float* __restrict__ w,
                              bf16* __restrict__ oh, bf16* __restrict__ ol,
                              int C, int F, long long total) {
    long long t = (long long)blockIdx.x * blockDim.x + threadIdx.x;
    if (t >= total) return;
    int l0 = (int)(t & 255) << 3;
    long long r = t >> 8;
    int Fq = F >> 2;
    int f0 = ((int)(r % Fq)) << 2; r /= Fq;
    int c = (int)(r % C);
    int b = (int)(r / C);
    const float* base = in + ((long long)(b * C + c)) * F * 2048LL;
    float wreg[15];
#pragma unroll
    for (int i = 0; i < 15; i++) wreg[i] = w[c * 15 + i];
    float a[4][8];
#pragma unroll
    for (int fo = 0; fo < 4; fo++)
#pragma unroll
        for (int j = 0; j < 8; j++) a[fo][j] = 0.f;
#pragma unroll
    for (int fi = 0; fi < 8; fi++) {
        int fr = f0 + fi - 2;
        if (fr < 0 || fr >= F) continue;
        const float* row = base + (long long)fr * 2048;
        float4 m0 = *(const float4*)(row + l0);
        float4 m1 = *(const float4*)(row + l0 + 4);
        float x[10];
        x[0] = (l0 > 0) ? row[l0 - 1] : 0.f;
        x[1] = m0.x; x[2] = m0.y; x[3] = m0.z; x[4] = m0.w;
        x[5] = m1.x; x[6] = m1.y; x[7] = m1.z; x[8] = m1.w;
        x[9] = (l0 + 8 < 2048) ? row[l0 + 8] : 0.f;
#pragma unroll
        for (int fo = 0; fo < 4; fo++) {
            int df = fi - fo;
            if (df < 0 || df > 4) continue;   /* compile-time pruned */
            float w0 = wreg[df * 3 + 0], w1 = wreg[df * 3 + 1], w2 = wreg[df * 3 + 2];
#pragma unroll
            for (int j = 0; j < 8; j++)
                a[fo][j] = fmaf(w0, x[j], fmaf(w1, x[j + 1], fmaf(w2, x[j + 2], a[fo][j])));
        }
    }
#pragma unroll
    for (int fo = 0; fo < 4; fo++) {
        long long o = (((long long)(b * C + c)) * F + f0 + fo) * 2048LL + l0;
        st_split4(oh, ol, o,     mp_siluf(a[fo][0]), mp_siluf(a[fo][1]),
                                 mp_siluf(a[fo][2]), mp_siluf(a[fo][3]));
        st_split4(oh, ol, o + 4, mp_siluf(a[fo][4]), mp_siluf(a[fo][5]),
                                 mp_siluf(a[fo][6]), mp_siluf(a[fo][7]));
    }
}

/* ------- freq average pool, 4 elems/thread, packed stores --------------- */
__global__ void avgpool_f(const float* __restrict__ in, bf16* __restrict__ oh,
                          bf16* __restrict__ ol,
                          int C, int F, int Fo, int s, long long total4) {
    long long t = (long long)blockIdx.x * blockDim.x + threadIdx.x;
    if (t >= total4) return;
    long long e = t << 2;
    int l = (int)(e & 2047);
    long long r = e >> 11;
    int fo = (int)(r % Fo); r /= Fo;
    int c = (int)(r % C);
    int b = (int)(r / C);
    const float* p = in + (((long long)(b * C + c)) * F + fo * s) * 2048LL + l;
    float4 sum = make_float4(0.f, 0.f, 0.f, 0.f);
    for (int j = 0; j < s; j++) {
        float4 v = *(const float4*)(p + (long long)j * 2048);
        sum.x += v.x; sum.y += v.y; sum.z += v.z; sum.w += v.w;
    }
    float is = 1.f / (float)s;
    st_split4(oh, ol, e, sum.x * is, sum.y * is, sum.z * is, sum.w * is);
}

/* ------- seq depthwise k3, 8 elems/thread ------------------------------- */
__global__ void dwconv1d_silu(const float* __restrict__ hg, const float* __restrict__ w,
                              bf16* __restrict__ oh, bf16* __restrict__ ol) {
    long long t = (long long)blockIdx.x * blockDim.x + threadIdx.x;
    if (t >= 524288LL) return;
    int l0 = (int)(t & 255) << 3;
    int c = (int)((t >> 8) & 1023);
    int b = (int)(t >> 18);
    const float* row = hg + ((long long)b * 2048 + c) * 2048LL;
    const float* wc = w + c * 3;
    float4 m0 = *(const float4*)(row + l0);
    float4 m1 = *(const float4*)(row + l0 + 4);
    float x[10];
    x[0] = (l0 > 0) ? mp_siluf(row[l0 - 1]) : 0.f;
    x[1] = mp_siluf(m0.x); x[2] = mp_siluf(m0.y);
    x[3] = mp_siluf(m0.z); x[4] = mp_siluf(m0.w);
    x[5] = mp_siluf(m1.x); x[6] = mp_siluf(m1.y);
    x[7] = mp_siluf(m1.z); x[8] = mp_siluf(m1.w);
    x[9] = (l0 + 8 < 2048) ? mp_siluf(row[l0 + 8]) : 0.f;
    float w0 = wc[0], w1 = wc[1], w2 = wc[2];
    float a[8];
#pragma unroll
    for (int j = 0; j < 8; j++)
        a[j] = fmaf(w0, x[j], fmaf(w1, x[j + 1], w2 * x[j + 2]));
    long long o = ((long long)b * 1024 + c) * 2048LL + l0;
    st_split4(oh, ol, o,     mp_siluf(a[0]), mp_siluf(a[1]), mp_siluf(a[2]), mp_siluf(a[3]));
    st_split4(oh, ol, o + 4, mp_siluf(a[4]), mp_siluf(a[5]), mp_siluf(a[6]), mp_siluf(a[7]));
}

/* --------- minGRU blocked scan (4 elems/lane) + output gate ------------- */
__global__ void gru_scan(const float* __restrict__ u, const float* __restrict__ hg,
                         bf16* __restrict__ oh, bf16* __restrict__ ol) {
    int w = (int)((blockIdx.x * blockDim.x + threadIdx.x) >> 5);
    int lane = threadIdx.x & 31;
    if (w >= 2048) return;
    int bt = w >> 10, c = w & 1023;
    const float* zrow = u + ((long long)bt * 2048 + c) * 2048LL;
    const float* crow = zrow + 1024LL * 2048LL;
    const float* grow = hg + ((long long)bt * 2048 + 1024 + c) * 2048LL;
    long long obase = ((long long)bt * 1024 + c) * 2048LL;
    float carry = 0.f;
    for (int l0 = 0; l0 < 2048; l0 += 128) {
        int le = l0 + lane * 4;
        float4 zv = *(const float4*)(zrow + le);
        float4 cv = *(const float4*)(crow + le);
        float z0 = sigmoidf_fast(zv.x), z1 = sigmoidf_fast(zv.y);
        float z2 = sigmoidf_fast(zv.z), z3 = sigmoidf_fast(zv.w);
        float a0 = 1.f - z0, b0 = z0 * cv.x;
        float a1 = 1.f - z1, b1 = z1 * cv.y;
        float a2 = 1.f - z2, b2 = z2 * cv.z;
        float a3 = 1.f - z3, b3 = z3 * cv.w;
        float A = a0, B = b0;
        A = a1 * A; B = fmaf(a1, B, b1);
        A = a2 * A; B = fmaf(a2, B, b2);
        A = a3 * A; B = fmaf(a3, B, b3);
        float As = A, Bs = B;
#pragma unroll
        for (int off = 1; off < 32; off <<= 1) {
            float Ap = __shfl_up_sync(0xffffffffu, As, off);
            float Bp = __shfl_up_sync(0xffffffffu, Bs, off);
            if (lane >= off) { Bs = fmaf(As, Bp, Bs); As *= Ap; }
        }
        float Ae = __shfl_up_sync(0xffffffffu, As, 1);
        float Be = __shfl_up_sync(0xffffffffu, Bs, 1);
        if (lane == 0) { Ae = 1.f; Be = 0.f; }
        float hprev = fmaf(Ae, carry, Be);
        float h0 = fmaf(a0, hprev, b0);
        float h1 = fmaf(a1, h0, b1);
        float h2 = fmaf(a2, h1, b2);
        float h3 = fmaf(a3, h2, b3);
        carry = __shfl_sync(0xffffffffu, fmaf(As, carry, Bs), 31);
        float4 gv = *(const float4*)(grow + le);
        st_split4(oh, ol, obase + le,
                  h0 * mp_siluf(gv.x), h1 * mp_siluf(gv.y),
                  h2 * mp_siluf(gv.z), h3 * mp_siluf(gv.w));
    }
}

/* ======================================================================== */
extern "C" void kernel_launch(void* const* d_in, const int* in_sizes, int n_in,
                              void* d_out, int out_size) {
    const float* audio = (const float*)d_in[0];
    const float* pw    = (const float*)d_in[1];
    const float* pb    = (const float*)d_in[2];
    const float* c0w1  = (const float*)d_in[3];
    const float* c0wd  = (const float*)d_in[4];
    const float* c0w2  = (const float*)d_in[5];
    const float* c0dn  = (const float*)d_in[6];
    const float* c1w1  = (const float*)d_in[7];
    const float* c1wd  = (const float*)d_in[8];
    const float* c1w2  = (const float*)d_in[9];
    const float* c1dn  = (const float*)d_in[10];
    const float* c2w1  = (const float*)d_in[11];
    const float* c2wd  = (const float*)d_in[12];
    const float* c2w2  = (const float*)d_in[13];
    const float* c2dn  = (const float*)d_in[14];
    const float* hgw   = (const float*)d_in[15];
    const float* dww   = (const float*)d_in[16];
    const float* gruw  = (const float*)d_in[17];
    const float* outw  = (const float*)d_in[18];

    float *wp, *xn, *xsf, *bufA, *bufBf, *hb, *poolf, *xb;
    bf16 *wbf, *cw;
    cudaGetSymbolAddress((void**)&wp,    g_wpool);
    cudaGetSymbolAddress((void**)&xn,    g_xn);
    cudaGetSymbolAddress((void**)&xsf,   g_xs);
    cudaGetSymbolAddress((void**)&bufA,  g_bufA);
    cudaGetSymbolAddress((void**)&bufBf, g_bufB);
    cudaGetSymbolAddress((void**)&hb,    g_h);
    cudaGetSymbolAddress((void**)&poolf, g_pool);
    cudaGetSymbolAddress((void**)&xb,    g_x);
    cudaGetSymbolAddress((void**)&wbf,   g_wbf);
    cudaGetSymbolAddress((void**)&cw,    g_cwbf);

    bf16* xs   = (bf16*)xsf;
    bf16* bufB = (bf16*)bufBf;
    bf16* pool = (bf16*)poolf;
    const float* NUL = (const float*)0;

    cudaFuncSetAttribute(cgemm<128, 0>, cudaFuncAttributeMaxDynamicSharedMemorySize, 98304);
    cudaFuncSetAttribute(cgemm<128, 1>, cudaFuncAttributeMaxDynamicSharedMemorySize, 98304);
    cudaFuncSetAttribute(cgemm<128, 3>, cudaFuncAttributeMaxDynamicSharedMemorySize, 98304);
    cudaFuncSetAttribute(cgemm<64, 2>,  cudaFuncAttributeMaxDynamicSharedMemorySize, 73728);

    /* fused weight normalization + bf16 split: one launch for all 16 */
    NormDescs nd;
    {
        const float* srcs[16] = {c0w1, c0wd, c0w2, c0dn, c1w1, c1wd, c1w2, c1dn,
                                 c2w1, c2wd, c2w2, c2dn, hgw, dww, gruw, outw};
        int rows[16]   = {128, 128, 64, 128, 256, 256, 128, 256, 512, 512, 256, 512,
                          8192, 4096, 8192, 2048};
        int rowlen[16] = {64, 15, 128, 64, 128, 15, 256, 128, 256, 15, 512, 256,
                          512, 3, 1024, 1024};
        float* dstf[16] = {0, wp + O_C0WD, 0, 0, 0, wp + O_C1WD, 0, 0,
                           0, wp + O_C2WD, 0, 0, 0, wp + O_DW, 0, 0};
        int hofs[16] = {CWH_C0W1, -1, CWH_C0W2, CWH_C0DN, CWH_C1W1, -1, CWH_C1W2,
                        CWH_C1DN, CWH_C2W1, -1, CWH_C2W2, CWH_C2DN, -1, -1, -1, -1};
        int acc = 0;
        for (int i = 0; i < 16; i++) {
            acc += rows[i];
            nd.s[i].src = srcs[i];
            nd.s[i].dstf = dstf[i];
            nd.s[i].rowlen = rowlen[i];
            nd.s[i].row_end = acc;
            if (dstf[i]) { nd.s[i].dsth = 0; nd.s[i].dstl = 0; }
            else if (hofs[i] >= 0) { nd.s[i].dsth = cw + hofs[i]; nd.s[i].dstl = cw + hofs[i] + CWLO; }
        }
        nd.s[12].dsth = wbf + WH_HG(0);  nd.s[12].dstl = wbf + WH_HG(0) + WLO;
        nd.s[14].dsth = wbf + WH_GRU(0); nd.s[14].dstl = wbf + WH_GRU(0) + WLO;
        nd.s[15].dsth = wbf + WH_OUT(0); nd.s[15].dstl = wbf + WH_OUT(0) + WLO;
        norm_rows_multi<<<acc, 128>>>(nd);
    }

    /* block 0  (C 64->128->64->pool4->128, F=128, P=262144) */
    proj_pixelnorm<<<512, 256>>>(audio, pw, pb, xs, xs + XS_LO);
    cgemm<128, 0><<<dim3(2048, 1, 2), 256, 98304>>>(cw + CWH_C0W1, cw + CWH_C0W1 + CWLO,
        xs, xs + XS_LO, bufA, NUL, NUL, NUL, NUL, 128, 64, 262144LL);
    dwconv2d_silu<<<8192, 256>>>(bufA, wp + O_C0WD, bufB, bufB + BUFB_LO, 128, 128, 2097152LL);
    cgemm<64, 2><<<dim3(2048, 1, 2), 256, 73728>>>(cw + CWH_C0W2, cw + CWH_C0W2 + CWLO,
        bufB, bufB + BUFB_LO, hb, NUL, audio, pw, pb, 64, 128, 262144LL);
    avgpool_f<<<8192, 256>>>(hb, pool, pool + POOL_LO, 64, 128, 32, 4, 2097152LL);
    cgemm<128, 0><<<dim3(512, 1, 2), 256, 98304>>>(cw + CWH_C0DN, cw + CWH_C0DN + CWLO,
        pool, pool + POOL_LO, xb, NUL, NUL, NUL, NUL, 128, 64, 65536LL);

    /* block 1  (C 128->256->128->pool4->256, F=32, P=65536) */
    pixelnorm4<true><<<128, 256>>>(xb, xn, xs, xs + XS_LO, 128, 65536LL, 131072LL);
    cgemm<128, 0><<<dim3(512, 2, 2), 256, 98304>>>(cw + CWH_C1W1, cw + CWH_C1W1 + CWLO,
        xs, xs + XS_LO, bufA, NUL, NUL, NUL, NUL, 256, 128, 65536LL);
    dwconv2d_silu<<<4096, 256>>>(bufA, wp + O_C1WD, bufB, bufB + BUFB_LO, 256, 32, 1048576LL);
    cgemm<128, 1><<<dim3(512, 1, 2), 256, 98304>>>(cw + CWH_C1W2, cw + CWH_C1W2 + CWLO,
        bufB, bufB + BUFB_LO, hb, xn, NUL, NUL, NUL, 128, 256, 65536LL);
    avgpool_f<<<4096, 256>>>(hb, pool, pool + POOL_LO, 128, 32, 8, 4, 1048576LL);
    cgemm<128, 0><<<dim3(128, 2, 2), 256, 98304>>>(cw + CWH_C1DN, cw + CWH_C1DN + CWLO,
        pool, pool + POOL_LO, xb, NUL, NUL, NUL, NUL, 256, 128, 16384LL);

    /* block 2  (C 256->512->256->pool8->512, F=8, P=16384) */
    pixelnorm4<true><<<32, 256>>>(xb, xn, xs, xs + XS_LO, 256, 16384LL, 32768LL);
    cgemm<128, 0><<<dim3(128, 4, 2), 256, 98304>>>(cw + CWH_C2W1, cw + CWH_C2W1 + CWLO,
        xs, xs + XS_LO, bufA, NUL, NUL, NUL, NUL, 512, 256, 16384LL);
    dwconv2d_silu<<<2048, 256>>>(bufA, wp + O_C2WD, bufB, bufB + BUFB_LO, 512, 8, 524288LL);
    cgemm<128, 1><<<dim3(128, 2, 2), 256, 98304>>>(cw + CWH_C2W2, cw + CWH_C2W2 + CWLO,
        bufB, bufB + BUFB_LO, hb, xn, NUL, NUL, NUL, 256, 512, 16384LL);
    avgpool_f<<<1024, 256>>>(hb, pool, pool + POOL_LO, 256, 8, 1, 8, 262144LL);
    cgemm<128, 0><<<dim3(16, 4, 2), 256, 98304>>>(cw + CWH_C2DN, cw + CWH_C2DN + CWLO,
        pool, pool + POOL_LO, xb, NUL, NUL, NUL, NUL, 512, 256, 2048LL);

    /* seq blocks ×4  (C=512, L=2048); last out-GEMM fuses final silu */
    for (int i = 0; i < 4; i++) {
        pixelnorm_s<<<128, 32>>>(xb, xn, xs, xs + XS_LO, 512, 2048LL, 4096LL);
        cgemm<128, 0><<<dim3(16, 16, 2), 256, 98304>>>(
            wbf + WH_HG(i), wbf + WH_HG(i) + WLO, xs, xs + XS_LO,
            bufA, NUL, NUL, NUL, NUL, 2048, 512, 2048LL);
        dwconv1d_silu<<<2048, 256>>>(bufA, wp + O_DW + i * 3072, bufB, bufB + BUFB_LO);
        cgemm<128, 0><<<dim3(16, 16, 2), 256, 98304>>>(
            wbf + WH_GRU(i), wbf + WH_GRU(i) + WLO, bufB, bufB + BUFB_LO,
            hb, NUL, NUL, NUL, NUL, 2048, 1024, 2048LL);
        gru_scan<<<256, 256>>>(hb, bufA, pool, pool + POOL_LO);
        if (i < 3) {
            cgemm<128, 1><<<dim3(16, 4, 2), 256, 98304>>>(
                wbf + WH_OUT(i), wbf + WH_OUT(i) + WLO, pool, pool + POOL_LO,
                xb, xn, NUL, NUL, NUL, 512, 1024, 2048LL);
        } else {
            cgemm<128, 3><<<dim3(16, 4, 2), 256, 98304>>>(
                wbf + WH_OUT(i), wbf + WH_OUT(i) + WLO, pool, pool + POOL_LO,
                (float*)d_out, xn, NUL, NUL, NUL, 512, 1024, 2048LL);
        }
    }
}